// round 3
// baseline (speedup 1.0000x reference)
#include <cuda_runtime.h>
#include <cuda_fp16.h>
#include <math.h>

#define BB 32
#define NN 512
#define NNODE (BB*NN)      // 16384
#define FF 6
#define WW 128
#define KG 100
#define KP 3
#define NEDGE (NNODE*KP)   // 49152
#define DIM2 1536

// ---------------- scratch (device globals; no allocation) ----------------
__device__ int    g_nbr100[NNODE*KG];
__device__ int    g_nbr3[NNODE*KP];
__device__ float  g_t1[NNODE*18];
__device__ float  g_hmA[NNODE*384];
__device__ float  g_hmB[NNODE*384];
__device__ float  g_Y[NNODE*384];
__device__ float  g_Z[(size_t)NEDGE*256];
__device__ float  g_M[(size_t)NEDGE*128];
__device__ float  g_gram[(size_t)BB*NN*NN];
__device__ float  g_nrm[NNODE];
__device__ __half g_h16a[NNODE*128];
__device__ __half g_h16b[NNODE*128];
__device__ float  g_z1[BB*DIM2];
__device__ float  g_z2[BB*DIM2];

// ---------------- kNN (k=100): block-per-row bitonic sort of 512 (d, idx) ----------------
__device__ __forceinline__ void cmpswap(float& ka, int& va, float& kb, int& vb, int ddd) {
    bool gt = (ka > kb) || (ka == kb && va > vb);
    if (gt == (ddd != 0)) {
        float tk = ka; ka = kb; kb = tk;
        int   tv = va; va = vb; vb = tv;
    }
}

__global__ void knn_kernel(const float* __restrict__ x, int K, int* __restrict__ out) {
    __shared__ float key[512];
    __shared__ int   val[512];
    int node = blockIdx.x;
    int b = node >> 9;
    int i = node & 511;
    int tid = threadIdx.x;  // 256

    float xi[FF];
    const float* xr = x + (size_t)node * FF;
    float sqi = 0.f;
#pragma unroll
    for (int d = 0; d < FF; d++) { xi[d] = xr[d]; sqi += xi[d]*xi[d]; }
    for (int j = tid; j < 512; j += 256) {
        const float* xj = x + (size_t)(b*512 + j) * FF;
        float dot = 0.f, sqj = 0.f;
#pragma unroll
        for (int d = 0; d < FF; d++) { float v = xj[d]; dot += xi[d]*v; sqj += v*v; }
        float dd = sqi + sqj - 2.f*dot;
        if (j == i) dd = 1e10f;
        key[j] = dd; val[j] = j;
    }
    __syncthreads();

    for (int size = 2; size < 512; size <<= 1) {
        int ddd = ((tid & (size >> 1)) == 0) ? 1 : 0;
        for (int stride = size >> 1; stride > 0; stride >>= 1) {
            int pos = 2*tid - (tid & (stride - 1));
            cmpswap(key[pos], val[pos], key[pos+stride], val[pos+stride], ddd);
            __syncthreads();
        }
    }
    for (int stride = 256; stride > 0; stride >>= 1) {
        int pos = 2*tid - (tid & (stride - 1));
        cmpswap(key[pos], val[pos], key[pos+stride], val[pos+stride], 1);
        __syncthreads();
    }
    for (int t = tid; t < K; t += 256)
        out[(size_t)node*K + t] = b*512 + val[t];
}

// ---------------- top-3 from gram (+ precomputed norms): 3-round argmin ----------------
__global__ void top3_kernel(const float* __restrict__ gram, const float* __restrict__ nrm,
                            int* __restrict__ out3) {
    __shared__ unsigned long long keys[512];
    __shared__ unsigned long long red[256];
    int node = blockIdx.x;
    int b = node >> 9, i = node & 511;
    int tid = threadIdx.x;  // 256
    const float* g = gram + (size_t)b*512*512 + (size_t)i*512;
    const float* nb = nrm + b*512;
    float ni = nb[i];
    for (int j = tid; j < 512; j += 256) {
        float d = ni + nb[j] - 2.f*g[j];
        if (j == i) d = 1e10f;
        unsigned int bits = __float_as_uint(d);
        bits = (bits & 0x80000000u) ? ~bits : (bits | 0x80000000u);
        keys[j] = ((unsigned long long)bits << 32) | (unsigned)j;
    }
    __syncthreads();
#pragma unroll
    for (int r = 0; r < 3; r++) {
        unsigned long long m = min(keys[tid], keys[tid+256]);
        red[tid] = m; __syncthreads();
        for (int o = 128; o > 0; o >>= 1) {
            if (tid < o) red[tid] = min(red[tid], red[tid+o]);
            __syncthreads();
        }
        unsigned long long best = red[0];
        int j = (int)(best & 0xffffffffu);
        if (tid == 0) {
            out3[node*3 + r] = b*512 + j;
            keys[j] = 0xFFFFFFFFFFFFFFFFull;
        }
        __syncthreads();
    }
}

// ---------------- TAG1: fused per-graph 2-hop mean of x (dim 6) ----------------
__global__ void tag1_aggr(const float* __restrict__ x, const int* __restrict__ nbr,
                          float* __restrict__ t1) {
    __shared__ float xs[6][512];
    __shared__ float m1[6][512];
    int b = blockIdx.x;
    int tid = threadIdx.x;  // 512
    const float* xr = x + (size_t)(b*512 + tid)*6;
#pragma unroll
    for (int d = 0; d < 6; d++) xs[d][tid] = xr[d];
    __syncthreads();

    const int* nb = nbr + (size_t)(b*512 + tid)*KG;
    float acc[6] = {};
#pragma unroll 4
    for (int k = 0; k < KG; k++) {
        int j = nb[k] & 511;
#pragma unroll
        for (int d = 0; d < 6; d++) acc[d] += xs[d][j];
    }
    float* tr = t1 + (size_t)(b*512 + tid)*18;
#pragma unroll
    for (int d = 0; d < 6; d++) {
        float v = acc[d] * 0.01f;
        m1[d][tid] = v;
        tr[d] = xs[d][tid];
        tr[6 + d] = v;
    }
    __syncthreads();
    float acc2[6] = {};
#pragma unroll 4
    for (int k = 0; k < KG; k++) {
        int j = nb[k] & 511;
#pragma unroll
        for (int d = 0; d < 6; d++) acc2[d] += m1[d][j];
    }
#pragma unroll
    for (int d = 0; d < 6; d++) tr[12 + d] = acc2[d] * 0.01f;
}

// ---------------- smem-staged fp16 aggregation (dim 128) ----------------
#define SMEM_AGG (512*128*2 + 32*100*4)
__global__ void aggr_smem(const __half* __restrict__ src16,
                          const int* __restrict__ nbr,
                          float* __restrict__ dst, int ldd,
                          __half* __restrict__ dst2, int wantHalf,
                          float scale) {
    extern __shared__ char sm[];
    __half* tile  = (__half*)sm;                 // [512][128]
    int*    idxbf = (int*)(sm + 512*128*2);      // [32][100]
    int bg = blockIdx.y, part = blockIdx.x;
    int tid = threadIdx.x;                        // 1024
    const uint4* gsrc = (const uint4*)(src16 + (size_t)bg*512*128);
    uint4* stile = (uint4*)tile;
#pragma unroll
    for (int t = 0; t < 8; t++) stile[tid + 1024*t] = gsrc[tid + 1024*t];
    __syncthreads();

    int warp = tid >> 5, lane = tid & 31;
    int* myidx = idxbf + warp*100;
#pragma unroll
    for (int nl = 0; nl < 4; nl++) {
        int nodeLocal = part*128 + warp*4 + nl;
        int node = bg*512 + nodeLocal;
        const int* nb = nbr + (size_t)node*KG;
        myidx[lane]      = nb[lane]      & 511;
        myidx[lane + 32] = nb[lane + 32] & 511;
        myidx[lane + 64] = nb[lane + 64] & 511;
        if (lane < 4) myidx[lane + 96] = nb[lane + 96] & 511;
        __syncwarp();
        float4 acc = {0.f, 0.f, 0.f, 0.f};
#pragma unroll 4
        for (int k = 0; k < KG; k++) {
            int j = myidx[k];
            const __half2* row = (const __half2*)tile + (size_t)j*64 + lane*2;
            float2 f0 = __half22float2(row[0]);
            float2 f1 = __half22float2(row[1]);
            acc.x += f0.x; acc.y += f0.y; acc.z += f1.x; acc.w += f1.y;
        }
        __syncwarp();
        acc.x *= scale; acc.y *= scale; acc.z *= scale; acc.w *= scale;
        *(float4*)(dst + (size_t)node*ldd + lane*4) = acc;
        if (wantHalf) {
            __half2* o = (__half2*)(dst2 + (size_t)node*128 + lane*4);
            o[0] = __floats2half2_rn(acc.x, acc.y);
            o[1] = __floats2half2_rn(acc.z, acc.w);
        }
    }
}

// ---------------- fused GEMM: C = act(A[M,K] @ W[K,128] + bias) ----------------
__global__ void gemm_bias_lrelu(const float* __restrict__ A, int lda,
                                const float* __restrict__ W,
                                const float* __restrict__ bias,
                                float* __restrict__ C, int ldc,
                                int K, int act, __half* __restrict__ C16) {
    __shared__ float As[16][136];
    __shared__ float Ws[16][128];
    int m0 = blockIdx.x * 128;
    int tid = threadIdx.x;
    int tr = tid >> 4, tc = tid & 15;
    float acc[8][8] = {};

    for (int k0 = 0; k0 < K; k0 += 16) {
#pragma unroll
        for (int i = 0; i < 8; i++) {
            int idx = tid + 256*i;
            int r = idx >> 4, c = idx & 15;
            float v = 0.f;
            if (k0 + c < K) v = A[(size_t)(m0 + r)*lda + k0 + c];
            As[c][r] = v;
        }
#pragma unroll
        for (int i = 0; i < 8; i++) {
            int idx = tid + 256*i;
            int kk = idx >> 7, n = idx & 127;
            float v = 0.f;
            if (k0 + kk < K) v = W[(size_t)(k0+kk)*128 + n];
            Ws[kk][n] = v;
        }
        __syncthreads();
#pragma unroll
        for (int k = 0; k < 16; k++) {
            float a[8], bv[8];
            *(float4*)&a[0]  = *(const float4*)&As[k][tr*8];
            *(float4*)&a[4]  = *(const float4*)&As[k][tr*8+4];
            *(float4*)&bv[0] = *(const float4*)&Ws[k][tc*8];
            *(float4*)&bv[4] = *(const float4*)&Ws[k][tc*8+4];
#pragma unroll
            for (int u = 0; u < 8; u++)
#pragma unroll
                for (int v = 0; v < 8; v++)
                    acc[u][v] = fmaf(a[u], bv[v], acc[u][v]);
        }
        __syncthreads();
    }
#pragma unroll
    for (int u = 0; u < 8; u++) {
        int r = m0 + tr*8 + u;
#pragma unroll
        for (int v = 0; v < 8; v++) {
            int c = tc*8 + v;
            float val = acc[u][v];
            if (bias) val += bias[c];
            if (act) val = val > 0.f ? val : 0.01f*val;
            C[(size_t)r*ldc + c] = val;
            if (C16) C16[(size_t)r*128 + c] = __float2half_rn(val);
        }
    }
}

// ---------------- symmetric Gram: G = Y Y^T per graph, 128x128 tiles, lower triangle ----------------
// grid (10 tiles, 32 graphs), 256 threads, 8x8 per thread. Mirrors off-diagonal tiles,
// emits nrm[i] = G[i][i] from diagonal tiles.
__global__ void gram_kernel(const float* __restrict__ Y, int ld,
                            float* __restrict__ G, float* __restrict__ nrm) {
    const int TI[10] = {0,1,1,2,2,2,3,3,3,3};
    const int TJ[10] = {0,0,1,0,1,2,0,1,2,3};
    __shared__ float As[16][136];
    __shared__ float Bs[16][136];
    int b  = blockIdx.y;
    int ti = TI[blockIdx.x], tj = TJ[blockIdx.x];
    int i0 = ti*128, j0 = tj*128;
    const float* Yb = Y + (size_t)b * 512 * ld;
    int tid = threadIdx.x;
    int tr = tid >> 4, tc = tid & 15;
    float acc[8][8] = {};

    for (int k0 = 0; k0 < 128; k0 += 16) {
#pragma unroll
        for (int i = 0; i < 8; i++) {
            int idx = tid + 256*i;
            int r = idx >> 4, c = idx & 15;
            As[c][r] = Yb[(size_t)(i0 + r)*ld + k0 + c];
            Bs[c][r] = Yb[(size_t)(j0 + r)*ld + k0 + c];
        }
        __syncthreads();
#pragma unroll
        for (int k = 0; k < 16; k++) {
            float a[8], bv[8];
            *(float4*)&a[0]  = *(const float4*)&As[k][tr*8];
            *(float4*)&a[4]  = *(const float4*)&As[k][tr*8+4];
            *(float4*)&bv[0] = *(const float4*)&Bs[k][tc*8];
            *(float4*)&bv[4] = *(const float4*)&Bs[k][tc*8+4];
#pragma unroll
            for (int u = 0; u < 8; u++)
#pragma unroll
                for (int v = 0; v < 8; v++)
                    acc[u][v] = fmaf(a[u], bv[v], acc[u][v]);
        }
        __syncthreads();
    }

    float* Gb = G + (size_t)b*512*512;
    // direct tile (coalesced)
#pragma unroll
    for (int u = 0; u < 8; u++) {
        int r = i0 + tr*8 + u;
        float4 lo = {acc[u][0], acc[u][1], acc[u][2], acc[u][3]};
        float4 hi = {acc[u][4], acc[u][5], acc[u][6], acc[u][7]};
        float* row = Gb + (size_t)r*512 + j0 + tc*8;
        *(float4*)row       = lo;
        *(float4*)(row + 4) = hi;
    }
    if (ti != tj) {
        // mirror tile: per-thread 32B row segments
#pragma unroll
        for (int v = 0; v < 8; v++) {
            int r = j0 + tc*8 + v;
            float4 lo = {acc[0][v], acc[1][v], acc[2][v], acc[3][v]};
            float4 hi = {acc[4][v], acc[5][v], acc[6][v], acc[7][v]};
            float* row = Gb + (size_t)r*512 + i0 + tr*8;
            *(float4*)row       = lo;
            *(float4*)(row + 4) = hi;
        }
    } else if (tr == tc) {
        // diagonal: norms
#pragma unroll
        for (int u = 0; u < 8; u++)
            nrm[b*512 + i0 + tr*8 + u] = acc[u][u];
    }
}

// ---------------- EdgeConv1: U/V from x (K=6 each) ----------------
__global__ void uv6_kernel(const float* __restrict__ x, const float* __restrict__ W12,
                           float* __restrict__ U, float* __restrict__ V) {
    __shared__ float Ws[12][128];
    int tid = threadIdx.x;   // 256
    for (int t = tid; t < 12*128; t += 256) Ws[t >> 7][t & 127] = W12[t];
    __syncthreads();
    int node = blockIdx.x*2 + (tid >> 7);
    int c = tid & 127;
    const float* xr = x + (size_t)node*6;
    float au = 0.f, av = 0.f;
#pragma unroll
    for (int d = 0; d < 6; d++) {
        float xv = xr[d];
        au = fmaf(xv, Ws[d][c], au);
        av = fmaf(xv, Ws[6+d][c], av);
    }
    U[(size_t)node*128 + c] = au;
    V[(size_t)node*128 + c] = av;
}

// h_e = lrelu(U[i] + V[j] - V[i] + b), 3 edges per node
__global__ void edge_hidden(const float* __restrict__ U, const float* __restrict__ V,
                            const int* __restrict__ nbr, int nstride,
                            const float* __restrict__ b, float* __restrict__ H) {
    int n = blockIdx.x; int c = threadIdx.x;   // 128
    float base = U[(size_t)n*128 + c] - V[(size_t)n*128 + c] + b[c];
#pragma unroll
    for (int k = 0; k < 3; k++) {
        int j = nbr[(size_t)n*nstride + k];
        float h = base + V[(size_t)j*128 + c];
        H[(size_t)(n*3 + k)*128 + c] = h > 0.f ? h : 0.01f*h;
    }
}

// Y_out[n] = max_k lrelu(U[n] + V[j_k] - V[n] + b)
__global__ void edge_fused_max(const float* __restrict__ U, const float* __restrict__ V,
                               const int* __restrict__ nbr, int nstride,
                               const float* __restrict__ b, float* __restrict__ Yout) {
    int n = blockIdx.x; int c = threadIdx.x;   // 128
    float base = U[(size_t)n*128 + c] - V[(size_t)n*128 + c] + b[c];
    float m = -1e30f;
#pragma unroll
    for (int k = 0; k < 3; k++) {
        int j = nbr[(size_t)n*nstride + k];
        float h = base + V[(size_t)j*128 + c];
        h = h > 0.f ? h : 0.01f*h;
        m = fmaxf(m, h);
    }
    Yout[(size_t)n*384 + c] = m;
}

__global__ void maxpool3(const float* __restrict__ M, float* __restrict__ Yc) {
    int n = blockIdx.x; int c = threadIdx.x;   // 128
    float v0 = M[(size_t)(n*3+0)*128 + c];
    float v1 = M[(size_t)(n*3+1)*128 + c];
    float v2 = M[(size_t)(n*3+2)*128 + c];
    Yc[(size_t)n*384 + c] = fmaxf(v0, fmaxf(v1, v2));
}

// ---------------- graph pooling: grid (32, 4), 256 thr = 32 ch x 8 strips ----------------
__global__ void pool_mean_max(const float* __restrict__ src, int ld,
                              float* __restrict__ z, int offm, int offx) {
    __shared__ float ss[8][32];
    __shared__ float sx[8][32];
    int b = blockIdx.x;
    int lane = threadIdx.x & 31;
    int s = threadIdx.x >> 5;                    // strip 0..7
    int c = blockIdx.y*32 + lane;
    const float* p = src + (size_t)b*512*ld + c;
    float sum = 0.f, mx = -1e30f;
    int n0 = s*64;
#pragma unroll 4
    for (int n = n0; n < n0 + 64; n++) {
        float v = p[(size_t)n*ld];
        sum += v; mx = fmaxf(mx, v);
    }
    ss[s][lane] = sum; sx[s][lane] = mx;
    __syncthreads();
    if (s == 0) {
#pragma unroll
        for (int t = 1; t < 8; t++) {
            sum += ss[t][lane];
            mx = fmaxf(mx, sx[t][lane]);
        }
        z[b*DIM2 + offm + c] = sum * (1.f/512.f);
        z[b*DIM2 + offx + c] = mx;
    }
}

// ---------------- head ----------------
__global__ void bn_kernel(const float* __restrict__ zin, const float* __restrict__ gamma,
                          const float* __restrict__ beta, float* __restrict__ zout) {
    int c = blockIdx.x*blockDim.x + threadIdx.x;
    if (c >= DIM2) return;
    float s = 0.f;
    for (int r = 0; r < 32; r++) s += zin[r*DIM2 + c];
    float mu = s * (1.f/32.f);
    float v = 0.f;
    for (int r = 0; r < 32; r++) { float d = zin[r*DIM2+c] - mu; v += d*d; }
    float inv = rsqrtf(v*(1.f/32.f) + 1e-5f);
    float ga = gamma[c], be = beta[c];
    for (int r = 0; r < 32; r++)
        zout[r*DIM2+c] = (zin[r*DIM2+c] - mu)*inv*ga + be;
}

__global__ void lin_layer(const float* __restrict__ A, const float* __restrict__ W,
                          const float* __restrict__ bias, float* __restrict__ C) {
    extern __shared__ float As[];               // 32 x 1537
    int tid = threadIdx.x;                       // 512
    for (int idx = tid; idx < 32*1536; idx += 512) {
        int r = idx / 1536; int k = idx - r*1536;
        As[r*1537 + k] = A[idx];
    }
    __syncthreads();
    int c = blockIdx.x*16 + (tid & 15);
    int r = tid >> 4;                            // 0..31
    float acc = 0.f;
#pragma unroll 8
    for (int k = 0; k < 1536; k++)
        acc = fmaf(As[r*1537 + k], W[(size_t)k*1536 + c], acc);
    float v = acc + bias[c];
    v = v > 0.f ? v : 0.01f*v;
    C[r*DIM2 + c] = v;
}

__global__ void out_kernel(const float* __restrict__ z, const float* __restrict__ W,
                           const float* __restrict__ b, float* __restrict__ out) {
    __shared__ float red[256];
    int row = blockIdx.x; int tid = threadIdx.x;
    float s = 0.f;
    for (int k = tid; k < DIM2; k += 256) s += z[row*DIM2 + k] * W[k];
    red[tid] = s; __syncthreads();
    for (int o = 128; o > 0; o >>= 1) { if (tid < o) red[tid] += red[tid+o]; __syncthreads(); }
    if (tid == 0) out[row] = red[0] + b[0];
}

// ---------------- host orchestration ----------------
extern "C" void kernel_launch(void* const* d_in, const int* in_sizes, int n_in,
                              void* d_out, int out_size) {
    const float* x       = (const float*)d_in[0];
    const float* tag1_W  = (const float*)d_in[2];
    const float* tag1_b  = (const float*)d_in[3];
    const float* tag_W   = (const float*)d_in[4];
    const float* tag_b   = (const float*)d_in[5];
    const float* p1_W1   = (const float*)d_in[6];
    const float* p1_b1   = (const float*)d_in[7];
    const float* p1_W2   = (const float*)d_in[8];
    const float* p1_b2   = (const float*)d_in[9];
    const float* pf_W    = (const float*)d_in[10];
    const float* pf_b    = (const float*)d_in[11];
    const float* bn_g    = (const float*)d_in[12];
    const float* bn_b    = (const float*)d_in[13];
    const float* lin_W   = (const float*)d_in[14];
    const float* lin_b   = (const float*)d_in[15];
    const float* out_W   = (const float*)d_in[16];
    const float* out_b   = (const float*)d_in[17];
    float* out = (float*)d_out;

    int *nbr100, *nbr3;
    float *t1, *hmA, *hmB, *Y, *Z, *M, *gram, *nrm, *z1, *z2;
    __half *h16a, *h16b;
    cudaGetSymbolAddress((void**)&nbr100, g_nbr100);
    cudaGetSymbolAddress((void**)&nbr3,   g_nbr3);
    cudaGetSymbolAddress((void**)&t1,     g_t1);
    cudaGetSymbolAddress((void**)&hmA,    g_hmA);
    cudaGetSymbolAddress((void**)&hmB,    g_hmB);
    cudaGetSymbolAddress((void**)&Y,      g_Y);
    cudaGetSymbolAddress((void**)&Z,      g_Z);
    cudaGetSymbolAddress((void**)&M,      g_M);
    cudaGetSymbolAddress((void**)&gram,   g_gram);
    cudaGetSymbolAddress((void**)&nrm,    g_nrm);
    cudaGetSymbolAddress((void**)&h16a,   g_h16a);
    cudaGetSymbolAddress((void**)&h16b,   g_h16b);
    cudaGetSymbolAddress((void**)&z1,     g_z1);
    cudaGetSymbolAddress((void**)&z2,     g_z2);

    cudaFuncSetAttribute(aggr_smem, cudaFuncAttributeMaxDynamicSharedMemorySize, SMEM_AGG);
    size_t shmem_lin = 32*1537*sizeof(float);
    cudaFuncSetAttribute(lin_layer, cudaFuncAttributeMaxDynamicSharedMemorySize, (int)shmem_lin);

    const float invKG = 1.f/(float)KG;
    dim3 gAgg(4, 32);
    dim3 gPool(32, 4);
    dim3 gGram(10, 32);

    // ===== graph kNN (k=100, sorted ascending; top3 = EdgeConv1 nbrs) =====
    knn_kernel<<<NNODE, 256>>>(x, KG, nbr100);

    // ===== TAG layer 1 (F=6 -> 128) =====
    tag1_aggr<<<32, 512>>>(x, nbr100, t1);
    gemm_bias_lrelu<<<NNODE/128, 256>>>(t1, 18, tag1_W, tag1_b, hmA, 384, 18, 1, h16a);
    pool_mean_max<<<gPool, 256>>>(hmA, 384, z1, 0, 128);

    // ===== TAG layer 2 (128 -> 128) =====
    aggr_smem<<<gAgg, 1024, SMEM_AGG>>>(h16a, nbr100, hmA + 128, 384, h16b, 1, invKG);
    aggr_smem<<<gAgg, 1024, SMEM_AGG>>>(h16b, nbr100, hmA + 256, 384, nullptr, 0, invKG);
    gemm_bias_lrelu<<<NNODE/128, 256>>>(hmA, 384, tag_W, tag_b, hmB, 384, 384, 1, h16a);
    pool_mean_max<<<gPool, 256>>>(hmB, 384, z1, 256, 384);

    // ===== TAG layer 3 (128 -> 128) =====
    aggr_smem<<<gAgg, 1024, SMEM_AGG>>>(h16a, nbr100, hmB + 128, 384, h16b, 1, invKG);
    aggr_smem<<<gAgg, 1024, SMEM_AGG>>>(h16b, nbr100, hmB + 256, 384, nullptr, 0, invKG);
    gemm_bias_lrelu<<<NNODE/128, 256>>>(hmB, 384, tag_W + 3*128*128, tag_b + 128, hmA, 384, 384, 1, nullptr);
    pool_mean_max<<<gPool, 256>>>(hmA, 384, z1, 512, 640);

    // ===== EdgeConv 1 (on x, k=3, 2-layer MLP; layer1 linearized) =====
    {
        float* U = M;
        float* V = M + (size_t)NNODE*128;
        uv6_kernel<<<NNODE/2, 256>>>(x, p1_W1, U, V);
        edge_hidden<<<NNODE, 128>>>(U, V, nbr100, KG, p1_b1, Z);
    }
    gemm_bias_lrelu<<<NEDGE/128, 256>>>(Z, 128, p1_W2, p1_b2, M, 128, 128, 1, nullptr);
    maxpool3<<<NNODE, 128>>>(M, Y);

    // ===== EdgeConv 2 (kNN on y1, linearized) =====
    gram_kernel<<<gGram, 256>>>(Y, 384, gram, nrm);
    top3_kernel<<<NNODE, 256>>>(gram, nrm, nbr3);
    {
        float* U = Z;
        float* V = Z + (size_t)NNODE*128;
        gemm_bias_lrelu<<<NNODE/128, 256>>>(Y, 384, pf_W,            nullptr, U, 128, 128, 0, nullptr);
        gemm_bias_lrelu<<<NNODE/128, 256>>>(Y, 384, pf_W + 128*128,  nullptr, V, 128, 128, 0, nullptr);
        edge_fused_max<<<NNODE, 128>>>(U, V, nbr3, KP, pf_b, Y + 128);
    }

    // ===== EdgeConv 3 (kNN on y2, linearized) =====
    gram_kernel<<<gGram, 256>>>(Y + 128, 384, gram, nrm);
    top3_kernel<<<NNODE, 256>>>(gram, nrm, nbr3);
    {
        float* U = Z;
        float* V = Z + (size_t)NNODE*128;
        gemm_bias_lrelu<<<NNODE/128, 256>>>(Y + 128, 384, pf_W + 256*128,           nullptr, U, 128, 128, 0, nullptr);
        gemm_bias_lrelu<<<NNODE/128, 256>>>(Y + 128, 384, pf_W + 256*128 + 128*128, nullptr, V, 128, 128, 0, nullptr);
        edge_fused_max<<<NNODE, 128>>>(U, V, nbr3, KP, pf_b + 128, Y + 256);
    }

    // ===== point-branch pooling =====
    pool_mean_max<<<gPool, 256>>>(Y,       384, z1, 768,        768 + 384);
    pool_mean_max<<<gPool, 256>>>(Y + 128, 384, z1, 768 + 128,  768 + 512);
    pool_mean_max<<<gPool, 256>>>(Y + 256, 384, z1, 768 + 256,  768 + 640);

    // ===== head =====
    bn_kernel<<<12, 128>>>(z1, bn_g, bn_b, z2);

    const float* src = z2; float* dst = z1;
    for (int g = 0; g < 5; g++) {
        lin_layer<<<96, 512, shmem_lin>>>(src, lin_W + (size_t)g*1536*1536, lin_b + g*1536, dst);
        const float* tmp = dst; dst = (float*)src; src = tmp;
    }
    out_kernel<<<32, 256>>>(z1, out_W, out_b, out);
}

// round 4
// speedup vs baseline: 1.0940x; 1.0940x over previous
#include <cuda_runtime.h>
#include <cuda_fp16.h>
#include <math.h>

#define BB 32
#define NN 512
#define NNODE (BB*NN)      // 16384
#define FF 6
#define WW 128
#define KG 100
#define KP 3
#define NEDGE (NNODE*KP)   // 49152
#define DIM2 1536

// ---------------- scratch (device globals; no allocation) ----------------
__device__ int    g_nbr100[NNODE*KG];
__device__ int    g_nbr3[NNODE*KP];
__device__ float  g_t1[NNODE*18];
__device__ float  g_hmA[NNODE*384];
__device__ float  g_hmB[NNODE*384];
__device__ float  g_Y[NNODE*384];
__device__ float  g_Z[(size_t)NEDGE*256];
__device__ float  g_M[(size_t)NEDGE*128];
__device__ float  g_gram[(size_t)BB*NN*NN];
__device__ float  g_nrm[NNODE];
__device__ __half g_h16a[NNODE*128];
__device__ __half g_h16b[NNODE*128];
__device__ float  g_z1[BB*DIM2];
__device__ float  g_z2[BB*DIM2];

// ---------------- kNN (k=100): block-per-row bitonic sort of 512 (d, idx) ----------------
__device__ __forceinline__ void cmpswap(float& ka, int& va, float& kb, int& vb, int ddd) {
    bool gt = (ka > kb) || (ka == kb && va > vb);
    if (gt == (ddd != 0)) {
        float tk = ka; ka = kb; kb = tk;
        int   tv = va; va = vb; vb = tv;
    }
}

__global__ void knn_kernel(const float* __restrict__ x, int K, int* __restrict__ out) {
    __shared__ float key[512];
    __shared__ int   val[512];
    int node = blockIdx.x;
    int b = node >> 9;
    int i = node & 511;
    int tid = threadIdx.x;  // 256

    float xi[FF];
    const float* xr = x + (size_t)node * FF;
    float sqi = 0.f;
#pragma unroll
    for (int d = 0; d < FF; d++) { xi[d] = xr[d]; sqi += xi[d]*xi[d]; }
    for (int j = tid; j < 512; j += 256) {
        const float* xj = x + (size_t)(b*512 + j) * FF;
        float dot = 0.f, sqj = 0.f;
#pragma unroll
        for (int d = 0; d < FF; d++) { float v = xj[d]; dot += xi[d]*v; sqj += v*v; }
        float dd = sqi + sqj - 2.f*dot;
        if (j == i) dd = 1e10f;
        key[j] = dd; val[j] = j;
    }
    __syncthreads();

    for (int size = 2; size < 512; size <<= 1) {
        int ddd = ((tid & (size >> 1)) == 0) ? 1 : 0;
        for (int stride = size >> 1; stride > 0; stride >>= 1) {
            int pos = 2*tid - (tid & (stride - 1));
            cmpswap(key[pos], val[pos], key[pos+stride], val[pos+stride], ddd);
            __syncthreads();
        }
    }
    for (int stride = 256; stride > 0; stride >>= 1) {
        int pos = 2*tid - (tid & (stride - 1));
        cmpswap(key[pos], val[pos], key[pos+stride], val[pos+stride], 1);
        __syncthreads();
    }
    for (int t = tid; t < K; t += 256)
        out[(size_t)node*K + t] = b*512 + val[t];
}

// ---------------- top-3 from gram (+ precomputed norms): 3-round argmin ----------------
__global__ void top3_kernel(const float* __restrict__ gram, const float* __restrict__ nrm,
                            int* __restrict__ out3) {
    __shared__ unsigned long long keys[512];
    __shared__ unsigned long long red[256];
    int node = blockIdx.x;
    int b = node >> 9, i = node & 511;
    int tid = threadIdx.x;  // 256
    const float* g = gram + (size_t)b*512*512 + (size_t)i*512;
    const float* nb = nrm + b*512;
    float ni = nb[i];
    for (int j = tid; j < 512; j += 256) {
        float d = ni + nb[j] - 2.f*g[j];
        if (j == i) d = 1e10f;
        unsigned int bits = __float_as_uint(d);
        bits = (bits & 0x80000000u) ? ~bits : (bits | 0x80000000u);
        keys[j] = ((unsigned long long)bits << 32) | (unsigned)j;
    }
    __syncthreads();
#pragma unroll
    for (int r = 0; r < 3; r++) {
        unsigned long long m = min(keys[tid], keys[tid+256]);
        red[tid] = m; __syncthreads();
        for (int o = 128; o > 0; o >>= 1) {
            if (tid < o) red[tid] = min(red[tid], red[tid+o]);
            __syncthreads();
        }
        unsigned long long best = red[0];
        int j = (int)(best & 0xffffffffu);
        if (tid == 0) {
            out3[node*3 + r] = b*512 + j;
            keys[j] = 0xFFFFFFFFFFFFFFFFull;
        }
        __syncthreads();
    }
}

// ---------------- TAG1: fused per-graph 2-hop mean of x (dim 6) ----------------
__global__ void tag1_aggr(const float* __restrict__ x, const int* __restrict__ nbr,
                          float* __restrict__ t1) {
    __shared__ float xs[6][512];
    __shared__ float m1[6][512];
    int b = blockIdx.x;
    int tid = threadIdx.x;  // 512
    const float* xr = x + (size_t)(b*512 + tid)*6;
#pragma unroll
    for (int d = 0; d < 6; d++) xs[d][tid] = xr[d];
    __syncthreads();

    const int* nb = nbr + (size_t)(b*512 + tid)*KG;
    float acc[6] = {};
#pragma unroll 4
    for (int k = 0; k < KG; k++) {
        int j = nb[k] & 511;
#pragma unroll
        for (int d = 0; d < 6; d++) acc[d] += xs[d][j];
    }
    float* tr = t1 + (size_t)(b*512 + tid)*18;
#pragma unroll
    for (int d = 0; d < 6; d++) {
        float v = acc[d] * 0.01f;
        m1[d][tid] = v;
        tr[d] = xs[d][tid];
        tr[6 + d] = v;
    }
    __syncthreads();
    float acc2[6] = {};
#pragma unroll 4
    for (int k = 0; k < KG; k++) {
        int j = nb[k] & 511;
#pragma unroll
        for (int d = 0; d < 6; d++) acc2[d] += m1[d][j];
    }
#pragma unroll
    for (int d = 0; d < 6; d++) tr[12 + d] = acc2[d] * 0.01f;
}

// ---------------- smem-staged fp16 aggregation (dim 128) ----------------
#define SMEM_AGG (512*128*2 + 32*100*4)
__global__ void aggr_smem(const __half* __restrict__ src16,
                          const int* __restrict__ nbr,
                          float* __restrict__ dst, int ldd,
                          __half* __restrict__ dst2, int wantHalf,
                          float scale) {
    extern __shared__ char sm[];
    __half* tile  = (__half*)sm;                 // [512][128]
    int*    idxbf = (int*)(sm + 512*128*2);      // [32][100]
    int bg = blockIdx.y, part = blockIdx.x;
    int tid = threadIdx.x;                        // 1024
    const uint4* gsrc = (const uint4*)(src16 + (size_t)bg*512*128);
    uint4* stile = (uint4*)tile;
#pragma unroll
    for (int t = 0; t < 8; t++) stile[tid + 1024*t] = gsrc[tid + 1024*t];
    __syncthreads();

    int warp = tid >> 5, lane = tid & 31;
    int* myidx = idxbf + warp*100;
#pragma unroll
    for (int nl = 0; nl < 4; nl++) {
        int nodeLocal = part*128 + warp*4 + nl;
        int node = bg*512 + nodeLocal;
        const int* nb = nbr + (size_t)node*KG;
        myidx[lane]      = nb[lane]      & 511;
        myidx[lane + 32] = nb[lane + 32] & 511;
        myidx[lane + 64] = nb[lane + 64] & 511;
        if (lane < 4) myidx[lane + 96] = nb[lane + 96] & 511;
        __syncwarp();
        float4 acc = {0.f, 0.f, 0.f, 0.f};
#pragma unroll 4
        for (int k = 0; k < KG; k++) {
            int j = myidx[k];
            const __half2* row = (const __half2*)tile + (size_t)j*64 + lane*2;
            float2 f0 = __half22float2(row[0]);
            float2 f1 = __half22float2(row[1]);
            acc.x += f0.x; acc.y += f0.y; acc.z += f1.x; acc.w += f1.y;
        }
        __syncwarp();
        acc.x *= scale; acc.y *= scale; acc.z *= scale; acc.w *= scale;
        *(float4*)(dst + (size_t)node*ldd + lane*4) = acc;
        if (wantHalf) {
            __half2* o = (__half2*)(dst2 + (size_t)node*128 + lane*4);
            o[0] = __floats2half2_rn(acc.x, acc.y);
            o[1] = __floats2half2_rn(acc.z, acc.w);
        }
    }
}

// ---------------- fused GEMM: C = act(A[M,K] @ W[K,128] + bias) ----------------
__global__ void gemm_bias_lrelu(const float* __restrict__ A, int lda,
                                const float* __restrict__ W,
                                const float* __restrict__ bias,
                                float* __restrict__ C, int ldc,
                                int K, int act, __half* __restrict__ C16) {
    __shared__ float As[16][136];
    __shared__ float Ws[16][128];
    int m0 = blockIdx.x * 128;
    int tid = threadIdx.x;
    int tr = tid >> 4, tc = tid & 15;
    float acc[8][8] = {};

    for (int k0 = 0; k0 < K; k0 += 16) {
#pragma unroll
        for (int i = 0; i < 8; i++) {
            int idx = tid + 256*i;
            int r = idx >> 4, c = idx & 15;
            float v = 0.f;
            if (k0 + c < K) v = A[(size_t)(m0 + r)*lda + k0 + c];
            As[c][r] = v;
        }
#pragma unroll
        for (int i = 0; i < 8; i++) {
            int idx = tid + 256*i;
            int kk = idx >> 7, n = idx & 127;
            float v = 0.f;
            if (k0 + kk < K) v = W[(size_t)(k0+kk)*128 + n];
            Ws[kk][n] = v;
        }
        __syncthreads();
#pragma unroll
        for (int k = 0; k < 16; k++) {
            float a[8], bv[8];
            *(float4*)&a[0]  = *(const float4*)&As[k][tr*8];
            *(float4*)&a[4]  = *(const float4*)&As[k][tr*8+4];
            *(float4*)&bv[0] = *(const float4*)&Ws[k][tc*8];
            *(float4*)&bv[4] = *(const float4*)&Ws[k][tc*8+4];
#pragma unroll
            for (int u = 0; u < 8; u++)
#pragma unroll
                for (int v = 0; v < 8; v++)
                    acc[u][v] = fmaf(a[u], bv[v], acc[u][v]);
        }
        __syncthreads();
    }
#pragma unroll
    for (int u = 0; u < 8; u++) {
        int r = m0 + tr*8 + u;
#pragma unroll
        for (int v = 0; v < 8; v++) {
            int c = tc*8 + v;
            float val = acc[u][v];
            if (bias) val += bias[c];
            if (act) val = val > 0.f ? val : 0.01f*val;
            C[(size_t)r*ldc + c] = val;
            if (C16) C16[(size_t)r*128 + c] = __float2half_rn(val);
        }
    }
}

// ---------------- per-graph Gram matrix G = Y Y^T (512x512, K=128), 64x64 tiles ----------------
// grid (8, 8, 32); diagonal blocks also emit nrm[i] = G[i][i]
__global__ void gram_kernel(const float* __restrict__ Y, int ld,
                            float* __restrict__ G, float* __restrict__ nrm) {
    __shared__ float Ai[16][68];
    __shared__ float Aj[16][68];
    int b  = blockIdx.z;
    int i0 = blockIdx.y * 64, j0 = blockIdx.x * 64;
    const float* Yb = Y + (size_t)b * 512 * ld;
    int tid = threadIdx.x;
    int ty = tid >> 4, tx = tid & 15;
    float acc[4][4] = {};

    for (int k0 = 0; k0 < 128; k0 += 16) {
#pragma unroll
        for (int t = 0; t < 4; t++) {
            int idx = tid + 256*t;
            int r = idx >> 4, c = idx & 15;
            Ai[c][r] = Yb[(size_t)(i0 + r)*ld + k0 + c];
            Aj[c][r] = Yb[(size_t)(j0 + r)*ld + k0 + c];
        }
        __syncthreads();
#pragma unroll
        for (int k = 0; k < 16; k++) {
            float a[4], bv[4];
            *(float4*)&a[0]  = *(const float4*)&Ai[k][ty*4];
            *(float4*)&bv[0] = *(const float4*)&Aj[k][tx*4];
#pragma unroll
            for (int u = 0; u < 4; u++)
#pragma unroll
                for (int v = 0; v < 4; v++)
                    acc[u][v] = fmaf(a[u], bv[v], acc[u][v]);
        }
        __syncthreads();
    }
    float* Gb = G + (size_t)b*512*512;
#pragma unroll
    for (int u = 0; u < 4; u++)
#pragma unroll
        for (int v = 0; v < 4; v++)
            Gb[(size_t)(i0+ty*4+u)*512 + (j0+tx*4+v)] = acc[u][v];

    if (i0 == j0 && ty == tx) {
#pragma unroll
        for (int u = 0; u < 4; u++)
            nrm[b*512 + i0 + ty*4 + u] = acc[u][u];
    }
}

// ---------------- EdgeConv1: U/V from x (K=6 each) ----------------
__global__ void uv6_kernel(const float* __restrict__ x, const float* __restrict__ W12,
                           float* __restrict__ U, float* __restrict__ V) {
    __shared__ float Ws[12][128];
    int tid = threadIdx.x;   // 256
    for (int t = tid; t < 12*128; t += 256) Ws[t >> 7][t & 127] = W12[t];
    __syncthreads();
    int node = blockIdx.x*2 + (tid >> 7);
    int c = tid & 127;
    const float* xr = x + (size_t)node*6;
    float au = 0.f, av = 0.f;
#pragma unroll
    for (int d = 0; d < 6; d++) {
        float xv = xr[d];
        au = fmaf(xv, Ws[d][c], au);
        av = fmaf(xv, Ws[6+d][c], av);
    }
    U[(size_t)node*128 + c] = au;
    V[(size_t)node*128 + c] = av;
}

// h_e = lrelu(U[i] + V[j] - V[i] + b), 3 edges per node
__global__ void edge_hidden(const float* __restrict__ U, const float* __restrict__ V,
                            const int* __restrict__ nbr, int nstride,
                            const float* __restrict__ b, float* __restrict__ H) {
    int n = blockIdx.x; int c = threadIdx.x;   // 128
    float base = U[(size_t)n*128 + c] - V[(size_t)n*128 + c] + b[c];
#pragma unroll
    for (int k = 0; k < 3; k++) {
        int j = nbr[(size_t)n*nstride + k];
        float h = base + V[(size_t)j*128 + c];
        H[(size_t)(n*3 + k)*128 + c] = h > 0.f ? h : 0.01f*h;
    }
}

// Y_out[n] = max_k lrelu(U[n] + V[j_k] - V[n] + b)
__global__ void edge_fused_max(const float* __restrict__ U, const float* __restrict__ V,
                               const int* __restrict__ nbr, int nstride,
                               const float* __restrict__ b, float* __restrict__ Yout) {
    int n = blockIdx.x; int c = threadIdx.x;   // 128
    float base = U[(size_t)n*128 + c] - V[(size_t)n*128 + c] + b[c];
    float m = -1e30f;
#pragma unroll
    for (int k = 0; k < 3; k++) {
        int j = nbr[(size_t)n*nstride + k];
        float h = base + V[(size_t)j*128 + c];
        h = h > 0.f ? h : 0.01f*h;
        m = fmaxf(m, h);
    }
    Yout[(size_t)n*384 + c] = m;
}

__global__ void maxpool3(const float* __restrict__ M, float* __restrict__ Yc) {
    int n = blockIdx.x; int c = threadIdx.x;   // 128
    float v0 = M[(size_t)(n*3+0)*128 + c];
    float v1 = M[(size_t)(n*3+1)*128 + c];
    float v2 = M[(size_t)(n*3+2)*128 + c];
    Yc[(size_t)n*384 + c] = fmaxf(v0, fmaxf(v1, v2));
}

// ---------------- graph pooling: grid (32, 4), 256 thr = 32 ch x 8 strips ----------------
__global__ void pool_mean_max(const float* __restrict__ src, int ld,
                              float* __restrict__ z, int offm, int offx) {
    __shared__ float ss[8][32];
    __shared__ float sx[8][32];
    int b = blockIdx.x;
    int lane = threadIdx.x & 31;
    int s = threadIdx.x >> 5;                    // strip 0..7
    int c = blockIdx.y*32 + lane;
    const float* p = src + (size_t)b*512*ld + c;
    float sum = 0.f, mx = -1e30f;
    int n0 = s*64;
#pragma unroll 4
    for (int n = n0; n < n0 + 64; n++) {
        float v = p[(size_t)n*ld];
        sum += v; mx = fmaxf(mx, v);
    }
    ss[s][lane] = sum; sx[s][lane] = mx;
    __syncthreads();
    if (s == 0) {
#pragma unroll
        for (int t = 1; t < 8; t++) {
            sum += ss[t][lane];
            mx = fmaxf(mx, sx[t][lane]);
        }
        z[b*DIM2 + offm + c] = sum * (1.f/512.f);
        z[b*DIM2 + offx + c] = mx;
    }
}

// ---------------- head ----------------
__global__ void bn_kernel(const float* __restrict__ zin, const float* __restrict__ gamma,
                          const float* __restrict__ beta, float* __restrict__ zout) {
    int c = blockIdx.x*blockDim.x + threadIdx.x;
    if (c >= DIM2) return;
    float s = 0.f;
    for (int r = 0; r < 32; r++) s += zin[r*DIM2 + c];
    float mu = s * (1.f/32.f);
    float v = 0.f;
    for (int r = 0; r < 32; r++) { float d = zin[r*DIM2+c] - mu; v += d*d; }
    float inv = rsqrtf(v*(1.f/32.f) + 1e-5f);
    float ga = gamma[c], be = beta[c];
    for (int r = 0; r < 32; r++)
        zout[r*DIM2+c] = (zin[r*DIM2+c] - mu)*inv*ga + be;
}

// 4 channels per thread, float4 W loads; grid 24, block 512
__global__ void lin_layer(const float* __restrict__ A, const float* __restrict__ W,
                          const float* __restrict__ bias, float* __restrict__ C) {
    extern __shared__ float As[];               // 32 x 1537
    int tid = threadIdx.x;                       // 512
    for (int idx = tid; idx < 32*1536; idx += 512) {
        int r = idx / 1536; int k = idx - r*1536;
        As[r*1537 + k] = A[idx];
    }
    __syncthreads();
    int cg = blockIdx.x*16 + (tid & 15);         // channel group (4 ch)
    int r  = tid >> 4;                           // 0..31
    int c0 = cg*4;
    float a0 = 0.f, a1 = 0.f, a2 = 0.f, a3 = 0.f;
    const float* As_r = As + r*1537;
#pragma unroll 4
    for (int k = 0; k < 1536; k++) {
        float a = As_r[k];
        float4 w = *(const float4*)&W[(size_t)k*1536 + c0];
        a0 = fmaf(a, w.x, a0);
        a1 = fmaf(a, w.y, a1);
        a2 = fmaf(a, w.z, a2);
        a3 = fmaf(a, w.w, a3);
    }
    float4 bv = *(const float4*)&bias[c0];
    a0 += bv.x; a1 += bv.y; a2 += bv.z; a3 += bv.w;
    a0 = a0 > 0.f ? a0 : 0.01f*a0;
    a1 = a1 > 0.f ? a1 : 0.01f*a1;
    a2 = a2 > 0.f ? a2 : 0.01f*a2;
    a3 = a3 > 0.f ? a3 : 0.01f*a3;
    *(float4*)&C[r*DIM2 + c0] = make_float4(a0, a1, a2, a3);
}

__global__ void out_kernel(const float* __restrict__ z, const float* __restrict__ W,
                           const float* __restrict__ b, float* __restrict__ out) {
    __shared__ float red[256];
    int row = blockIdx.x; int tid = threadIdx.x;
    float s = 0.f;
    for (int k = tid; k < DIM2; k += 256) s += z[row*DIM2 + k] * W[k];
    red[tid] = s; __syncthreads();
    for (int o = 128; o > 0; o >>= 1) { if (tid < o) red[tid] += red[tid+o]; __syncthreads(); }
    if (tid == 0) out[row] = red[0] + b[0];
}

// ---------------- host orchestration ----------------
extern "C" void kernel_launch(void* const* d_in, const int* in_sizes, int n_in,
                              void* d_out, int out_size) {
    const float* x       = (const float*)d_in[0];
    const float* tag1_W  = (const float*)d_in[2];
    const float* tag1_b  = (const float*)d_in[3];
    const float* tag_W   = (const float*)d_in[4];
    const float* tag_b   = (const float*)d_in[5];
    const float* p1_W1   = (const float*)d_in[6];
    const float* p1_b1   = (const float*)d_in[7];
    const float* p1_W2   = (const float*)d_in[8];
    const float* p1_b2   = (const float*)d_in[9];
    const float* pf_W    = (const float*)d_in[10];
    const float* pf_b    = (const float*)d_in[11];
    const float* bn_g    = (const float*)d_in[12];
    const float* bn_b    = (const float*)d_in[13];
    const float* lin_W   = (const float*)d_in[14];
    const float* lin_b   = (const float*)d_in[15];
    const float* out_W   = (const float*)d_in[16];
    const float* out_b   = (const float*)d_in[17];
    float* out = (float*)d_out;

    int *nbr100, *nbr3;
    float *t1, *hmA, *hmB, *Y, *Z, *M, *gram, *nrm, *z1, *z2;
    __half *h16a, *h16b;
    cudaGetSymbolAddress((void**)&nbr100, g_nbr100);
    cudaGetSymbolAddress((void**)&nbr3,   g_nbr3);
    cudaGetSymbolAddress((void**)&t1,     g_t1);
    cudaGetSymbolAddress((void**)&hmA,    g_hmA);
    cudaGetSymbolAddress((void**)&hmB,    g_hmB);
    cudaGetSymbolAddress((void**)&Y,      g_Y);
    cudaGetSymbolAddress((void**)&Z,      g_Z);
    cudaGetSymbolAddress((void**)&M,      g_M);
    cudaGetSymbolAddress((void**)&gram,   g_gram);
    cudaGetSymbolAddress((void**)&nrm,    g_nrm);
    cudaGetSymbolAddress((void**)&h16a,   g_h16a);
    cudaGetSymbolAddress((void**)&h16b,   g_h16b);
    cudaGetSymbolAddress((void**)&z1,     g_z1);
    cudaGetSymbolAddress((void**)&z2,     g_z2);

    cudaFuncSetAttribute(aggr_smem, cudaFuncAttributeMaxDynamicSharedMemorySize, SMEM_AGG);
    size_t shmem_lin = 32*1537*sizeof(float);
    cudaFuncSetAttribute(lin_layer, cudaFuncAttributeMaxDynamicSharedMemorySize, (int)shmem_lin);

    const float invKG = 1.f/(float)KG;
    dim3 gAgg(4, 32);
    dim3 gPool(32, 4);
    dim3 gGram(8, 8, 32);

    // ===== graph kNN (k=100, sorted ascending; top3 = EdgeConv1 nbrs) =====
    knn_kernel<<<NNODE, 256>>>(x, KG, nbr100);

    // ===== TAG layer 1 (F=6 -> 128) =====
    tag1_aggr<<<32, 512>>>(x, nbr100, t1);
    gemm_bias_lrelu<<<NNODE/128, 256>>>(t1, 18, tag1_W, tag1_b, hmA, 384, 18, 1, h16a);
    pool_mean_max<<<gPool, 256>>>(hmA, 384, z1, 0, 128);

    // ===== TAG layer 2 (128 -> 128) =====
    aggr_smem<<<gAgg, 1024, SMEM_AGG>>>(h16a, nbr100, hmA + 128, 384, h16b, 1, invKG);
    aggr_smem<<<gAgg, 1024, SMEM_AGG>>>(h16b, nbr100, hmA + 256, 384, nullptr, 0, invKG);
    gemm_bias_lrelu<<<NNODE/128, 256>>>(hmA, 384, tag_W, tag_b, hmB, 384, 384, 1, h16a);
    pool_mean_max<<<gPool, 256>>>(hmB, 384, z1, 256, 384);

    // ===== TAG layer 3 (128 -> 128) =====
    aggr_smem<<<gAgg, 1024, SMEM_AGG>>>(h16a, nbr100, hmB + 128, 384, h16b, 1, invKG);
    aggr_smem<<<gAgg, 1024, SMEM_AGG>>>(h16b, nbr100, hmB + 256, 384, nullptr, 0, invKG);
    gemm_bias_lrelu<<<NNODE/128, 256>>>(hmB, 384, tag_W + 3*128*128, tag_b + 128, hmA, 384, 384, 1, nullptr);
    pool_mean_max<<<gPool, 256>>>(hmA, 384, z1, 512, 640);

    // ===== EdgeConv 1 (on x, k=3, 2-layer MLP; layer1 linearized) =====
    {
        float* U = M;
        float* V = M + (size_t)NNODE*128;
        uv6_kernel<<<NNODE/2, 256>>>(x, p1_W1, U, V);
        edge_hidden<<<NNODE, 128>>>(U, V, nbr100, KG, p1_b1, Z);
    }
    gemm_bias_lrelu<<<NEDGE/128, 256>>>(Z, 128, p1_W2, p1_b2, M, 128, 128, 1, nullptr);
    maxpool3<<<NNODE, 128>>>(M, Y);

    // ===== EdgeConv 2 (kNN on y1, linearized) =====
    gram_kernel<<<gGram, 256>>>(Y, 384, gram, nrm);
    top3_kernel<<<NNODE, 256>>>(gram, nrm, nbr3);
    {
        float* U = Z;
        float* V = Z + (size_t)NNODE*128;
        gemm_bias_lrelu<<<NNODE/128, 256>>>(Y, 384, pf_W,            nullptr, U, 128, 128, 0, nullptr);
        gemm_bias_lrelu<<<NNODE/128, 256>>>(Y, 384, pf_W + 128*128,  nullptr, V, 128, 128, 0, nullptr);
        edge_fused_max<<<NNODE, 128>>>(U, V, nbr3, KP, pf_b, Y + 128);
    }

    // ===== EdgeConv 3 (kNN on y2, linearized) =====
    gram_kernel<<<gGram, 256>>>(Y + 128, 384, gram, nrm);
    top3_kernel<<<NNODE, 256>>>(gram, nrm, nbr3);
    {
        float* U = Z;
        float* V = Z + (size_t)NNODE*128;
        gemm_bias_lrelu<<<NNODE/128, 256>>>(Y + 128, 384, pf_W + 256*128,           nullptr, U, 128, 128, 0, nullptr);
        gemm_bias_lrelu<<<NNODE/128, 256>>>(Y + 128, 384, pf_W + 256*128 + 128*128, nullptr, V, 128, 128, 0, nullptr);
        edge_fused_max<<<NNODE, 128>>>(U, V, nbr3, KP, pf_b + 128, Y + 256);
    }

    // ===== point-branch pooling =====
    pool_mean_max<<<gPool, 256>>>(Y,       384, z1, 768,        768 + 384);
    pool_mean_max<<<gPool, 256>>>(Y + 128, 384, z1, 768 + 128,  768 + 512);
    pool_mean_max<<<gPool, 256>>>(Y + 256, 384, z1, 768 + 256,  768 + 640);

    // ===== head =====
    bn_kernel<<<12, 128>>>(z1, bn_g, bn_b, z2);

    const float* src = z2; float* dst = z1;
    for (int g = 0; g < 5; g++) {
        lin_layer<<<24, 512, shmem_lin>>>(src, lin_W + (size_t)g*1536*1536, lin_b + g*1536, dst);
        const float* tmp = dst; dst = (float*)src; src = tmp;
    }
    out_kernel<<<32, 256>>>(z1, out_W, out_b, out);
}

// round 5
// speedup vs baseline: 1.3960x; 1.2760x over previous
#include <cuda_runtime.h>
#include <cuda_fp16.h>
#include <math.h>

#define BB 32
#define NN 512
#define NNODE (BB*NN)      // 16384
#define FF 6
#define WW 128
#define KG 100
#define KP 3
#define NEDGE (NNODE*KP)   // 49152
#define DIM2 1536

// ---------------- scratch (device globals; no allocation) ----------------
__device__ int    g_nbr100[NNODE*KG];
__device__ int    g_nbr3[NNODE*KP];
__device__ float  g_t1[NNODE*18];
__device__ float  g_hmA[NNODE*384];
__device__ float  g_hmB[NNODE*384];
__device__ float  g_Y[NNODE*384];
__device__ float  g_Z[(size_t)NEDGE*256];
__device__ float  g_M[(size_t)NEDGE*128];
__device__ float  g_gram[(size_t)BB*NN*NN];
__device__ float  g_nrm[NNODE];
__device__ __half g_h16a[NNODE*128];
__device__ __half g_h16b[NNODE*128];
__device__ float  g_z1[BB*DIM2];
__device__ float  g_z2[BB*DIM2];

// ---------------- kNN (k=100): block-per-row bitonic sort of 512 (d, idx) ----------------
__device__ __forceinline__ void cmpswap(float& ka, int& va, float& kb, int& vb, int ddd) {
    bool gt = (ka > kb) || (ka == kb && va > vb);
    if (gt == (ddd != 0)) {
        float tk = ka; ka = kb; kb = tk;
        int   tv = va; va = vb; vb = tv;
    }
}

__global__ void knn_kernel(const float* __restrict__ x, int K, int* __restrict__ out) {
    __shared__ float key[512];
    __shared__ int   val[512];
    int node = blockIdx.x;
    int b = node >> 9;
    int i = node & 511;
    int tid = threadIdx.x;  // 256

    float xi[FF];
    const float* xr = x + (size_t)node * FF;
    float sqi = 0.f;
#pragma unroll
    for (int d = 0; d < FF; d++) { xi[d] = xr[d]; sqi += xi[d]*xi[d]; }
    for (int j = tid; j < 512; j += 256) {
        const float* xj = x + (size_t)(b*512 + j) * FF;
        float dot = 0.f, sqj = 0.f;
#pragma unroll
        for (int d = 0; d < FF; d++) { float v = xj[d]; dot += xi[d]*v; sqj += v*v; }
        float dd = sqi + sqj - 2.f*dot;
        if (j == i) dd = 1e10f;
        key[j] = dd; val[j] = j;
    }
    __syncthreads();

    for (int size = 2; size < 512; size <<= 1) {
        int ddd = ((tid & (size >> 1)) == 0) ? 1 : 0;
        for (int stride = size >> 1; stride > 0; stride >>= 1) {
            int pos = 2*tid - (tid & (stride - 1));
            cmpswap(key[pos], val[pos], key[pos+stride], val[pos+stride], ddd);
            __syncthreads();
        }
    }
    for (int stride = 256; stride > 0; stride >>= 1) {
        int pos = 2*tid - (tid & (stride - 1));
        cmpswap(key[pos], val[pos], key[pos+stride], val[pos+stride], 1);
        __syncthreads();
    }
    for (int t = tid; t < K; t += 256)
        out[(size_t)node*K + t] = b*512 + val[t];
}

// ---------------- top-3 from gram (+ precomputed norms): 3-round argmin ----------------
__global__ void top3_kernel(const float* __restrict__ gram, const float* __restrict__ nrm,
                            int* __restrict__ out3) {
    __shared__ unsigned long long keys[512];
    __shared__ unsigned long long red[256];
    int node = blockIdx.x;
    int b = node >> 9, i = node & 511;
    int tid = threadIdx.x;  // 256
    const float* g = gram + (size_t)b*512*512 + (size_t)i*512;
    const float* nb = nrm + b*512;
    float ni = nb[i];
    for (int j = tid; j < 512; j += 256) {
        float d = ni + nb[j] - 2.f*g[j];
        if (j == i) d = 1e10f;
        unsigned int bits = __float_as_uint(d);
        bits = (bits & 0x80000000u) ? ~bits : (bits | 0x80000000u);
        keys[j] = ((unsigned long long)bits << 32) | (unsigned)j;
    }
    __syncthreads();
#pragma unroll
    for (int r = 0; r < 3; r++) {
        unsigned long long m = min(keys[tid], keys[tid+256]);
        red[tid] = m; __syncthreads();
        for (int o = 128; o > 0; o >>= 1) {
            if (tid < o) red[tid] = min(red[tid], red[tid+o]);
            __syncthreads();
        }
        unsigned long long best = red[0];
        int j = (int)(best & 0xffffffffu);
        if (tid == 0) {
            out3[node*3 + r] = b*512 + j;
            keys[j] = 0xFFFFFFFFFFFFFFFFull;
        }
        __syncthreads();
    }
}

// ---------------- TAG1: fused per-graph 2-hop mean of x (dim 6) ----------------
__global__ void tag1_aggr(const float* __restrict__ x, const int* __restrict__ nbr,
                          float* __restrict__ t1) {
    __shared__ float xs[6][512];
    __shared__ float m1[6][512];
    int b = blockIdx.x;
    int tid = threadIdx.x;  // 512
    const float* xr = x + (size_t)(b*512 + tid)*6;
#pragma unroll
    for (int d = 0; d < 6; d++) xs[d][tid] = xr[d];
    __syncthreads();

    const int* nb = nbr + (size_t)(b*512 + tid)*KG;
    float acc[6] = {};
#pragma unroll 4
    for (int k = 0; k < KG; k++) {
        int j = nb[k] & 511;
#pragma unroll
        for (int d = 0; d < 6; d++) acc[d] += xs[d][j];
    }
    float* tr = t1 + (size_t)(b*512 + tid)*18;
#pragma unroll
    for (int d = 0; d < 6; d++) {
        float v = acc[d] * 0.01f;
        m1[d][tid] = v;
        tr[d] = xs[d][tid];
        tr[6 + d] = v;
    }
    __syncthreads();
    float acc2[6] = {};
#pragma unroll 4
    for (int k = 0; k < KG; k++) {
        int j = nb[k] & 511;
#pragma unroll
        for (int d = 0; d < 6; d++) acc2[d] += m1[d][j];
    }
#pragma unroll
    for (int d = 0; d < 6; d++) tr[12 + d] = acc2[d] * 0.01f;
}

// ---------------- smem-staged fp16 aggregation (dim 128) ----------------
#define SMEM_AGG (512*128*2 + 32*100*4)
__global__ void aggr_smem(const __half* __restrict__ src16,
                          const int* __restrict__ nbr,
                          float* __restrict__ dst, int ldd,
                          __half* __restrict__ dst2, int wantHalf,
                          float scale) {
    extern __shared__ char sm[];
    __half* tile  = (__half*)sm;                 // [512][128]
    int*    idxbf = (int*)(sm + 512*128*2);      // [32][100]
    int bg = blockIdx.y, part = blockIdx.x;
    int tid = threadIdx.x;                        // 1024
    const uint4* gsrc = (const uint4*)(src16 + (size_t)bg*512*128);
    uint4* stile = (uint4*)tile;
#pragma unroll
    for (int t = 0; t < 8; t++) stile[tid + 1024*t] = gsrc[tid + 1024*t];
    __syncthreads();

    int warp = tid >> 5, lane = tid & 31;
    int* myidx = idxbf + warp*100;
#pragma unroll
    for (int nl = 0; nl < 4; nl++) {
        int nodeLocal = part*128 + warp*4 + nl;
        int node = bg*512 + nodeLocal;
        const int* nb = nbr + (size_t)node*KG;
        myidx[lane]      = nb[lane]      & 511;
        myidx[lane + 32] = nb[lane + 32] & 511;
        myidx[lane + 64] = nb[lane + 64] & 511;
        if (lane < 4) myidx[lane + 96] = nb[lane + 96] & 511;
        __syncwarp();
        float4 acc = {0.f, 0.f, 0.f, 0.f};
#pragma unroll 4
        for (int k = 0; k < KG; k++) {
            int j = myidx[k];
            const __half2* row = (const __half2*)tile + (size_t)j*64 + lane*2;
            float2 f0 = __half22float2(row[0]);
            float2 f1 = __half22float2(row[1]);
            acc.x += f0.x; acc.y += f0.y; acc.z += f1.x; acc.w += f1.y;
        }
        __syncwarp();
        acc.x *= scale; acc.y *= scale; acc.z *= scale; acc.w *= scale;
        *(float4*)(dst + (size_t)node*ldd + lane*4) = acc;
        if (wantHalf) {
            __half2* o = (__half2*)(dst2 + (size_t)node*128 + lane*4);
            o[0] = __floats2half2_rn(acc.x, acc.y);
            o[1] = __floats2half2_rn(acc.z, acc.w);
        }
    }
}

// ---------------- fused GEMM: C = act(A[M,K] @ W[K,128] + bias) ----------------
__global__ void gemm_bias_lrelu(const float* __restrict__ A, int lda,
                                const float* __restrict__ W,
                                const float* __restrict__ bias,
                                float* __restrict__ C, int ldc,
                                int K, int act, __half* __restrict__ C16) {
    __shared__ float As[16][136];
    __shared__ float Ws[16][128];
    int m0 = blockIdx.x * 128;
    int tid = threadIdx.x;
    int tr = tid >> 4, tc = tid & 15;
    float acc[8][8] = {};

    for (int k0 = 0; k0 < K; k0 += 16) {
#pragma unroll
        for (int i = 0; i < 8; i++) {
            int idx = tid + 256*i;
            int r = idx >> 4, c = idx & 15;
            float v = 0.f;
            if (k0 + c < K) v = A[(size_t)(m0 + r)*lda + k0 + c];
            As[c][r] = v;
        }
#pragma unroll
        for (int i = 0; i < 8; i++) {
            int idx = tid + 256*i;
            int kk = idx >> 7, n = idx & 127;
            float v = 0.f;
            if (k0 + kk < K) v = W[(size_t)(k0+kk)*128 + n];
            Ws[kk][n] = v;
        }
        __syncthreads();
#pragma unroll
        for (int k = 0; k < 16; k++) {
            float a[8], bv[8];
            *(float4*)&a[0]  = *(const float4*)&As[k][tr*8];
            *(float4*)&a[4]  = *(const float4*)&As[k][tr*8+4];
            *(float4*)&bv[0] = *(const float4*)&Ws[k][tc*8];
            *(float4*)&bv[4] = *(const float4*)&Ws[k][tc*8+4];
#pragma unroll
            for (int u = 0; u < 8; u++)
#pragma unroll
                for (int v = 0; v < 8; v++)
                    acc[u][v] = fmaf(a[u], bv[v], acc[u][v]);
        }
        __syncthreads();
    }
#pragma unroll
    for (int u = 0; u < 8; u++) {
        int r = m0 + tr*8 + u;
#pragma unroll
        for (int v = 0; v < 8; v++) {
            int c = tc*8 + v;
            float val = acc[u][v];
            if (bias) val += bias[c];
            if (act) val = val > 0.f ? val : 0.01f*val;
            C[(size_t)r*ldc + c] = val;
            if (C16) C16[(size_t)r*128 + c] = __float2half_rn(val);
        }
    }
}

// ---------------- per-graph Gram: 128x64 tiles, 8x4 per thread ----------------
// grid (8, 4, 32): 8 j-tiles x 4 i-tiles x 32 graphs, 256 threads.
// Emits nrm[i] = G[i][i] from tiles containing the diagonal.
__global__ void gram_kernel(const float* __restrict__ Y, int ld,
                            float* __restrict__ G, float* __restrict__ nrm) {
    __shared__ float As[16][136];   // [k][i-row]
    __shared__ float Bs[16][72];    // [k][j-row]
    int b  = blockIdx.z;
    int i0 = blockIdx.y * 128, j0 = blockIdx.x * 64;
    const float* Yb = Y + (size_t)b * 512 * ld;
    int tid = threadIdx.x;
    int tr = tid >> 4, tc = tid & 15;   // tr 0..15 (8 rows each), tc 0..15 (4 cols each)
    float acc[8][4] = {};

    for (int k0 = 0; k0 < 128; k0 += 16) {
#pragma unroll
        for (int t = 0; t < 8; t++) {   // 128x16 A tile
            int idx = tid + 256*t;
            int r = idx >> 4, c = idx & 15;
            As[c][r] = Yb[(size_t)(i0 + r)*ld + k0 + c];
        }
#pragma unroll
        for (int t = 0; t < 4; t++) {   // 64x16 B tile
            int idx = tid + 256*t;
            int r = idx >> 4, c = idx & 15;
            Bs[c][r] = Yb[(size_t)(j0 + r)*ld + k0 + c];
        }
        __syncthreads();
#pragma unroll
        for (int k = 0; k < 16; k++) {
            float a[8], bv[4];
            *(float4*)&a[0]  = *(const float4*)&As[k][tr*8];
            *(float4*)&a[4]  = *(const float4*)&As[k][tr*8+4];
            *(float4*)&bv[0] = *(const float4*)&Bs[k][tc*4];
#pragma unroll
            for (int u = 0; u < 8; u++)
#pragma unroll
                for (int v = 0; v < 4; v++)
                    acc[u][v] = fmaf(a[u], bv[v], acc[u][v]);
        }
        __syncthreads();
    }
    float* Gb = G + (size_t)b*512*512;
#pragma unroll
    for (int u = 0; u < 8; u++) {
        int r = i0 + tr*8 + u;
        *(float4*)(Gb + (size_t)r*512 + j0 + tc*4) =
            make_float4(acc[u][0], acc[u][1], acc[u][2], acc[u][3]);
    }
    // diagonal -> norms
#pragma unroll
    for (int u = 0; u < 8; u++) {
        int r = i0 + tr*8 + u;
        int dc = r - (j0 + tc*4);
        if (dc >= 0 && dc < 4)
            nrm[b*512 + r] = acc[u][dc];
    }
}

// ---------------- EdgeConv1: U/V from x (K=6 each) ----------------
__global__ void uv6_kernel(const float* __restrict__ x, const float* __restrict__ W12,
                           float* __restrict__ U, float* __restrict__ V) {
    __shared__ float Ws[12][128];
    int tid = threadIdx.x;   // 256
    for (int t = tid; t < 12*128; t += 256) Ws[t >> 7][t & 127] = W12[t];
    __syncthreads();
    int node = blockIdx.x*2 + (tid >> 7);
    int c = tid & 127;
    const float* xr = x + (size_t)node*6;
    float au = 0.f, av = 0.f;
#pragma unroll
    for (int d = 0; d < 6; d++) {
        float xv = xr[d];
        au = fmaf(xv, Ws[d][c], au);
        av = fmaf(xv, Ws[6+d][c], av);
    }
    U[(size_t)node*128 + c] = au;
    V[(size_t)node*128 + c] = av;
}

// h_e = lrelu(U[i] + V[j] - V[i] + b), 3 edges per node
__global__ void edge_hidden(const float* __restrict__ U, const float* __restrict__ V,
                            const int* __restrict__ nbr, int nstride,
                            const float* __restrict__ b, float* __restrict__ H) {
    int n = blockIdx.x; int c = threadIdx.x;   // 128
    float base = U[(size_t)n*128 + c] - V[(size_t)n*128 + c] + b[c];
#pragma unroll
    for (int k = 0; k < 3; k++) {
        int j = nbr[(size_t)n*nstride + k];
        float h = base + V[(size_t)j*128 + c];
        H[(size_t)(n*3 + k)*128 + c] = h > 0.f ? h : 0.01f*h;
    }
}

// Y_out[n] = max_k lrelu(U[n] + V[j_k] - V[n] + b)
__global__ void edge_fused_max(const float* __restrict__ U, const float* __restrict__ V,
                               const int* __restrict__ nbr, int nstride,
                               const float* __restrict__ b, float* __restrict__ Yout) {
    int n = blockIdx.x; int c = threadIdx.x;   // 128
    float base = U[(size_t)n*128 + c] - V[(size_t)n*128 + c] + b[c];
    float m = -1e30f;
#pragma unroll
    for (int k = 0; k < 3; k++) {
        int j = nbr[(size_t)n*nstride + k];
        float h = base + V[(size_t)j*128 + c];
        h = h > 0.f ? h : 0.01f*h;
        m = fmaxf(m, h);
    }
    Yout[(size_t)n*384 + c] = m;
}

__global__ void maxpool3(const float* __restrict__ M, float* __restrict__ Yc) {
    int n = blockIdx.x; int c = threadIdx.x;   // 128
    float v0 = M[(size_t)(n*3+0)*128 + c];
    float v1 = M[(size_t)(n*3+1)*128 + c];
    float v2 = M[(size_t)(n*3+2)*128 + c];
    Yc[(size_t)n*384 + c] = fmaxf(v0, fmaxf(v1, v2));
}

// ---------------- graph pooling: grid (32, 4), 256 thr = 32 ch x 8 strips ----------------
__global__ void pool_mean_max(const float* __restrict__ src, int ld,
                              float* __restrict__ z, int offm, int offx) {
    __shared__ float ss[8][32];
    __shared__ float sx[8][32];
    int b = blockIdx.x;
    int lane = threadIdx.x & 31;
    int s = threadIdx.x >> 5;                    // strip 0..7
    int c = blockIdx.y*32 + lane;
    const float* p = src + (size_t)b*512*ld + c;
    float sum = 0.f, mx = -1e30f;
    int n0 = s*64;
#pragma unroll 4
    for (int n = n0; n < n0 + 64; n++) {
        float v = p[(size_t)n*ld];
        sum += v; mx = fmaxf(mx, v);
    }
    ss[s][lane] = sum; sx[s][lane] = mx;
    __syncthreads();
    if (s == 0) {
#pragma unroll
        for (int t = 1; t < 8; t++) {
            sum += ss[t][lane];
            mx = fmaxf(mx, sx[t][lane]);
        }
        z[b*DIM2 + offm + c] = sum * (1.f/512.f);
        z[b*DIM2 + offx + c] = mx;
    }
}

// ---------------- head ----------------
__global__ void bn_kernel(const float* __restrict__ zin, const float* __restrict__ gamma,
                          const float* __restrict__ beta, float* __restrict__ zout) {
    int c = blockIdx.x*blockDim.x + threadIdx.x;
    if (c >= DIM2) return;
    float s = 0.f;
    for (int r = 0; r < 32; r++) s += zin[r*DIM2 + c];
    float mu = s * (1.f/32.f);
    float v = 0.f;
    for (int r = 0; r < 32; r++) { float d = zin[r*DIM2+c] - mu; v += d*d; }
    float inv = rsqrtf(v*(1.f/32.f) + 1e-5f);
    float ga = gamma[c], be = beta[c];
    for (int r = 0; r < 32; r++)
        zout[r*DIM2+c] = (zin[r*DIM2+c] - mu)*inv*ga + be;
}

// round-2 version: grid 96, block 512, dyn smem 32x1537
__global__ void lin_layer(const float* __restrict__ A, const float* __restrict__ W,
                          const float* __restrict__ bias, float* __restrict__ C) {
    extern __shared__ float As[];               // 32 x 1537
    int tid = threadIdx.x;                       // 512
    for (int idx = tid; idx < 32*1536; idx += 512) {
        int r = idx / 1536; int k = idx - r*1536;
        As[r*1537 + k] = A[idx];
    }
    __syncthreads();
    int c = blockIdx.x*16 + (tid & 15);
    int r = tid >> 4;                            // 0..31
    float acc = 0.f;
#pragma unroll 8
    for (int k = 0; k < 1536; k++)
        acc = fmaf(As[r*1537 + k], W[(size_t)k*1536 + c], acc);
    float v = acc + bias[c];
    v = v > 0.f ? v : 0.01f*v;
    C[r*DIM2 + c] = v;
}

__global__ void out_kernel(const float* __restrict__ z, const float* __restrict__ W,
                           const float* __restrict__ b, float* __restrict__ out) {
    __shared__ float red[256];
    int row = blockIdx.x; int tid = threadIdx.x;
    float s = 0.f;
    for (int k = tid; k < DIM2; k += 256) s += z[row*DIM2 + k] * W[k];
    red[tid] = s; __syncthreads();
    for (int o = 128; o > 0; o >>= 1) { if (tid < o) red[tid] += red[tid+o]; __syncthreads(); }
    if (tid == 0) out[row] = red[0] + b[0];
}

// ---------------- host orchestration ----------------
extern "C" void kernel_launch(void* const* d_in, const int* in_sizes, int n_in,
                              void* d_out, int out_size) {
    const float* x       = (const float*)d_in[0];
    const float* tag1_W  = (const float*)d_in[2];
    const float* tag1_b  = (const float*)d_in[3];
    const float* tag_W   = (const float*)d_in[4];
    const float* tag_b   = (const float*)d_in[5];
    const float* p1_W1   = (const float*)d_in[6];
    const float* p1_b1   = (const float*)d_in[7];
    const float* p1_W2   = (const float*)d_in[8];
    const float* p1_b2   = (const float*)d_in[9];
    const float* pf_W    = (const float*)d_in[10];
    const float* pf_b    = (const float*)d_in[11];
    const float* bn_g    = (const float*)d_in[12];
    const float* bn_b    = (const float*)d_in[13];
    const float* lin_W   = (const float*)d_in[14];
    const float* lin_b   = (const float*)d_in[15];
    const float* out_W   = (const float*)d_in[16];
    const float* out_b   = (const float*)d_in[17];
    float* out = (float*)d_out;

    int *nbr100, *nbr3;
    float *t1, *hmA, *hmB, *Y, *Z, *M, *gram, *nrm, *z1, *z2;
    __half *h16a, *h16b;
    cudaGetSymbolAddress((void**)&nbr100, g_nbr100);
    cudaGetSymbolAddress((void**)&nbr3,   g_nbr3);
    cudaGetSymbolAddress((void**)&t1,     g_t1);
    cudaGetSymbolAddress((void**)&hmA,    g_hmA);
    cudaGetSymbolAddress((void**)&hmB,    g_hmB);
    cudaGetSymbolAddress((void**)&Y,      g_Y);
    cudaGetSymbolAddress((void**)&Z,      g_Z);
    cudaGetSymbolAddress((void**)&M,      g_M);
    cudaGetSymbolAddress((void**)&gram,   g_gram);
    cudaGetSymbolAddress((void**)&nrm,    g_nrm);
    cudaGetSymbolAddress((void**)&h16a,   g_h16a);
    cudaGetSymbolAddress((void**)&h16b,   g_h16b);
    cudaGetSymbolAddress((void**)&z1,     g_z1);
    cudaGetSymbolAddress((void**)&z2,     g_z2);

    cudaFuncSetAttribute(aggr_smem, cudaFuncAttributeMaxDynamicSharedMemorySize, SMEM_AGG);
    size_t shmem_lin = 32*1537*sizeof(float);
    cudaFuncSetAttribute(lin_layer, cudaFuncAttributeMaxDynamicSharedMemorySize, (int)shmem_lin);

    const float invKG = 1.f/(float)KG;
    dim3 gAgg(4, 32);
    dim3 gPool(32, 4);
    dim3 gGram(8, 4, 32);

    // ===== graph kNN (k=100, sorted ascending; top3 = EdgeConv1 nbrs) =====
    knn_kernel<<<NNODE, 256>>>(x, KG, nbr100);

    // ===== TAG layer 1 (F=6 -> 128) =====
    tag1_aggr<<<32, 512>>>(x, nbr100, t1);
    gemm_bias_lrelu<<<NNODE/128, 256>>>(t1, 18, tag1_W, tag1_b, hmA, 384, 18, 1, h16a);
    pool_mean_max<<<gPool, 256>>>(hmA, 384, z1, 0, 128);

    // ===== TAG layer 2 (128 -> 128) =====
    aggr_smem<<<gAgg, 1024, SMEM_AGG>>>(h16a, nbr100, hmA + 128, 384, h16b, 1, invKG);
    aggr_smem<<<gAgg, 1024, SMEM_AGG>>>(h16b, nbr100, hmA + 256, 384, nullptr, 0, invKG);
    gemm_bias_lrelu<<<NNODE/128, 256>>>(hmA, 384, tag_W, tag_b, hmB, 384, 384, 1, h16a);
    pool_mean_max<<<gPool, 256>>>(hmB, 384, z1, 256, 384);

    // ===== TAG layer 3 (128 -> 128) =====
    aggr_smem<<<gAgg, 1024, SMEM_AGG>>>(h16a, nbr100, hmB + 128, 384, h16b, 1, invKG);
    aggr_smem<<<gAgg, 1024, SMEM_AGG>>>(h16b, nbr100, hmB + 256, 384, nullptr, 0, invKG);
    gemm_bias_lrelu<<<NNODE/128, 256>>>(hmB, 384, tag_W + 3*128*128, tag_b + 128, hmA, 384, 384, 1, nullptr);
    pool_mean_max<<<gPool, 256>>>(hmA, 384, z1, 512, 640);

    // ===== EdgeConv 1 (on x, k=3, 2-layer MLP; layer1 linearized) =====
    {
        float* U = M;
        float* V = M + (size_t)NNODE*128;
        uv6_kernel<<<NNODE/2, 256>>>(x, p1_W1, U, V);
        edge_hidden<<<NNODE, 128>>>(U, V, nbr100, KG, p1_b1, Z);
    }
    gemm_bias_lrelu<<<NEDGE/128, 256>>>(Z, 128, p1_W2, p1_b2, M, 128, 128, 1, nullptr);
    maxpool3<<<NNODE, 128>>>(M, Y);

    // ===== EdgeConv 2 (kNN on y1, linearized) =====
    gram_kernel<<<gGram, 256>>>(Y, 384, gram, nrm);
    top3_kernel<<<NNODE, 256>>>(gram, nrm, nbr3);
    {
        float* U = Z;
        float* V = Z + (size_t)NNODE*128;
        gemm_bias_lrelu<<<NNODE/128, 256>>>(Y, 384, pf_W,            nullptr, U, 128, 128, 0, nullptr);
        gemm_bias_lrelu<<<NNODE/128, 256>>>(Y, 384, pf_W + 128*128,  nullptr, V, 128, 128, 0, nullptr);
        edge_fused_max<<<NNODE, 128>>>(U, V, nbr3, KP, pf_b, Y + 128);
    }

    // ===== EdgeConv 3 (kNN on y2, linearized) =====
    gram_kernel<<<gGram, 256>>>(Y + 128, 384, gram, nrm);
    top3_kernel<<<NNODE, 256>>>(gram, nrm, nbr3);
    {
        float* U = Z;
        float* V = Z + (size_t)NNODE*128;
        gemm_bias_lrelu<<<NNODE/128, 256>>>(Y + 128, 384, pf_W + 256*128,           nullptr, U, 128, 128, 0, nullptr);
        gemm_bias_lrelu<<<NNODE/128, 256>>>(Y + 128, 384, pf_W + 256*128 + 128*128, nullptr, V, 128, 128, 0, nullptr);
        edge_fused_max<<<NNODE, 128>>>(U, V, nbr3, KP, pf_b + 128, Y + 256);
    }

    // ===== point-branch pooling =====
    pool_mean_max<<<gPool, 256>>>(Y,       384, z1, 768,        768 + 384);
    pool_mean_max<<<gPool, 256>>>(Y + 128, 384, z1, 768 + 128,  768 + 512);
    pool_mean_max<<<gPool, 256>>>(Y + 256, 384, z1, 768 + 256,  768 + 640);

    // ===== head =====
    bn_kernel<<<12, 128>>>(z1, bn_g, bn_b, z2);

    const float* src = z2; float* dst = z1;
    for (int g = 0; g < 5; g++) {
        lin_layer<<<96, 512, shmem_lin>>>(src, lin_W + (size_t)g*1536*1536, lin_b + g*1536, dst);
        const float* tmp = dst; dst = (float*)src; src = tmp;
    }
    out_kernel<<<32, 256>>>(z1, out_W, out_b, out);
}

// round 6
// speedup vs baseline: 1.6740x; 1.1991x over previous
#include <cuda_runtime.h>
#include <cuda_fp16.h>
#include <math.h>

#define BB 32
#define NN 512
#define NNODE (BB*NN)      // 16384
#define FF 6
#define WW 128
#define KG 100
#define KP 3
#define NEDGE (NNODE*KP)   // 49152
#define DIM2 1536

typedef unsigned long long ull;

// ---------------- scratch (device globals; no allocation) ----------------
__device__ int    g_nbr100[NNODE*KG];
__device__ int    g_nbr3[NNODE*KP];
__device__ float  g_t1[NNODE*18];
__device__ float  g_hmA[NNODE*384];
__device__ float  g_hmB[NNODE*384];
__device__ float  g_Y[NNODE*384];
__device__ float  g_Z[(size_t)NEDGE*256];
__device__ float  g_M[(size_t)NEDGE*128];
__device__ float  g_gram[(size_t)BB*NN*NN];
__device__ float  g_nrm[NNODE];
__device__ __half g_h16a[NNODE*128];
__device__ __half g_h16b[NNODE*128];
__device__ float  g_z1[BB*DIM2];
__device__ float  g_z2[BB*DIM2];

// ---------------- kNN (k=100): packed 64-bit-key bitonic sort of 512 ----------------
__global__ void knn_kernel(const float* __restrict__ x, int K, int* __restrict__ out) {
    __shared__ ull key[512];
    int node = blockIdx.x;
    int b = node >> 9;
    int i = node & 511;
    int tid = threadIdx.x;  // 256

    float xi[FF];
    const float* xr = x + (size_t)node * FF;
    float sqi = 0.f;
#pragma unroll
    for (int d = 0; d < FF; d++) { xi[d] = xr[d]; sqi += xi[d]*xi[d]; }
    for (int j = tid; j < 512; j += 256) {
        const float* xj = x + (size_t)(b*512 + j) * FF;
        float dot = 0.f, sqj = 0.f;
#pragma unroll
        for (int d = 0; d < FF; d++) { float v = xj[d]; dot += xi[d]*v; sqj += v*v; }
        float dd = sqi + sqj - 2.f*dot;
        if (j == i) dd = 1e10f;
        unsigned int bits = __float_as_uint(dd);
        bits = (bits & 0x80000000u) ? ~bits : (bits | 0x80000000u);
        key[j] = ((ull)bits << 32) | (unsigned)j;
    }
    __syncthreads();

    for (int size = 2; size < 512; size <<= 1) {
        int up = ((tid & (size >> 1)) == 0);
        for (int stride = size >> 1; stride > 0; stride >>= 1) {
            int pos = 2*tid - (tid & (stride - 1));
            ull a = key[pos], c = key[pos + stride];
            ull lo = a < c ? a : c;
            ull hi = a < c ? c : a;
            key[pos]          = up ? lo : hi;
            key[pos + stride] = up ? hi : lo;
            __syncthreads();
        }
    }
    for (int stride = 256; stride > 0; stride >>= 1) {
        int pos = 2*tid - (tid & (stride - 1));
        ull a = key[pos], c = key[pos + stride];
        key[pos]          = a < c ? a : c;
        key[pos + stride] = a < c ? c : a;
        __syncthreads();
    }
    for (int t = tid; t < K; t += 256)
        out[(size_t)node*K + t] = b*512 + (int)(key[t] & 0xffffffffu);
}

// ---------------- top-3 from gram (+ precomputed norms): 3-round argmin ----------------
__global__ void top3_kernel(const float* __restrict__ gram, const float* __restrict__ nrm,
                            int* __restrict__ out3) {
    __shared__ ull keys[512];
    __shared__ ull red[256];
    int node = blockIdx.x;
    int b = node >> 9, i = node & 511;
    int tid = threadIdx.x;  // 256
    const float* g = gram + (size_t)b*512*512 + (size_t)i*512;
    const float* nb = nrm + b*512;
    float ni = nb[i];
    for (int j = tid; j < 512; j += 256) {
        float d = ni + nb[j] - 2.f*g[j];
        if (j == i) d = 1e10f;
        unsigned int bits = __float_as_uint(d);
        bits = (bits & 0x80000000u) ? ~bits : (bits | 0x80000000u);
        keys[j] = ((ull)bits << 32) | (unsigned)j;
    }
    __syncthreads();
#pragma unroll
    for (int r = 0; r < 3; r++) {
        ull m = min(keys[tid], keys[tid+256]);
        red[tid] = m; __syncthreads();
        for (int o = 128; o > 0; o >>= 1) {
            if (tid < o) red[tid] = min(red[tid], red[tid+o]);
            __syncthreads();
        }
        ull best = red[0];
        int j = (int)(best & 0xffffffffu);
        if (tid == 0) {
            out3[node*3 + r] = b*512 + j;
            keys[j] = 0xFFFFFFFFFFFFFFFFull;
        }
        __syncthreads();
    }
}

// ---------------- TAG1: fused per-graph 2-hop mean of x (dim 6) ----------------
__global__ void tag1_aggr(const float* __restrict__ x, const int* __restrict__ nbr,
                          float* __restrict__ t1) {
    __shared__ float xs[6][512];
    __shared__ float m1[6][512];
    int b = blockIdx.x;
    int tid = threadIdx.x;  // 512
    const float* xr = x + (size_t)(b*512 + tid)*6;
#pragma unroll
    for (int d = 0; d < 6; d++) xs[d][tid] = xr[d];
    __syncthreads();

    const int* nb = nbr + (size_t)(b*512 + tid)*KG;
    float acc[6] = {};
#pragma unroll 4
    for (int k = 0; k < KG; k++) {
        int j = nb[k] & 511;
#pragma unroll
        for (int d = 0; d < 6; d++) acc[d] += xs[d][j];
    }
    float* tr = t1 + (size_t)(b*512 + tid)*18;
#pragma unroll
    for (int d = 0; d < 6; d++) {
        float v = acc[d] * 0.01f;
        m1[d][tid] = v;
        tr[d] = xs[d][tid];
        tr[6 + d] = v;
    }
    __syncthreads();
    float acc2[6] = {};
#pragma unroll 4
    for (int k = 0; k < KG; k++) {
        int j = nb[k] & 511;
#pragma unroll
        for (int d = 0; d < 6; d++) acc2[d] += m1[d][j];
    }
#pragma unroll
    for (int d = 0; d < 6; d++) tr[12 + d] = acc2[d] * 0.01f;
}

// ---------------- smem-staged fp16 aggregation (dim 128) ----------------
#define SMEM_AGG (512*128*2 + 32*100*4)
__global__ void aggr_smem(const __half* __restrict__ src16,
                          const int* __restrict__ nbr,
                          float* __restrict__ dst, int ldd,
                          __half* __restrict__ dst2, int wantHalf,
                          float scale) {
    extern __shared__ char sm[];
    __half* tile  = (__half*)sm;                 // [512][128]
    int*    idxbf = (int*)(sm + 512*128*2);      // [32][100]
    int bg = blockIdx.y, part = blockIdx.x;
    int tid = threadIdx.x;                        // 1024
    const uint4* gsrc = (const uint4*)(src16 + (size_t)bg*512*128);
    uint4* stile = (uint4*)tile;
#pragma unroll
    for (int t = 0; t < 8; t++) stile[tid + 1024*t] = gsrc[tid + 1024*t];
    __syncthreads();

    int warp = tid >> 5, lane = tid & 31;
    int* myidx = idxbf + warp*100;
#pragma unroll
    for (int nl = 0; nl < 4; nl++) {
        int nodeLocal = part*128 + warp*4 + nl;
        int node = bg*512 + nodeLocal;
        const int* nb = nbr + (size_t)node*KG;
        myidx[lane]      = nb[lane]      & 511;
        myidx[lane + 32] = nb[lane + 32] & 511;
        myidx[lane + 64] = nb[lane + 64] & 511;
        if (lane < 4) myidx[lane + 96] = nb[lane + 96] & 511;
        __syncwarp();
        float4 acc = {0.f, 0.f, 0.f, 0.f};
#pragma unroll 4
        for (int k = 0; k < KG; k++) {
            int j = myidx[k];
            const __half2* row = (const __half2*)tile + (size_t)j*64 + lane*2;
            float2 f0 = __half22float2(row[0]);
            float2 f1 = __half22float2(row[1]);
            acc.x += f0.x; acc.y += f0.y; acc.z += f1.x; acc.w += f1.y;
        }
        __syncwarp();
        acc.x *= scale; acc.y *= scale; acc.z *= scale; acc.w *= scale;
        *(float4*)(dst + (size_t)node*ldd + lane*4) = acc;
        if (wantHalf) {
            __half2* o = (__half2*)(dst2 + (size_t)node*128 + lane*4);
            o[0] = __floats2half2_rn(acc.x, acc.y);
            o[1] = __floats2half2_rn(acc.z, acc.w);
        }
    }
}

// ---------------- fused GEMM: C = act(A[M,K] @ W[K,128] + bias) ----------------
__global__ void gemm_bias_lrelu(const float* __restrict__ A, int lda,
                                const float* __restrict__ W,
                                const float* __restrict__ bias,
                                float* __restrict__ C, int ldc,
                                int K, int act, __half* __restrict__ C16) {
    __shared__ float As[16][136];
    __shared__ float Ws[16][128];
    int m0 = blockIdx.x * 128;
    int tid = threadIdx.x;
    int tr = tid >> 4, tc = tid & 15;
    float acc[8][8] = {};

    for (int k0 = 0; k0 < K; k0 += 16) {
#pragma unroll
        for (int i = 0; i < 8; i++) {
            int idx = tid + 256*i;
            int r = idx >> 4, c = idx & 15;
            float v = 0.f;
            if (k0 + c < K) v = A[(size_t)(m0 + r)*lda + k0 + c];
            As[c][r] = v;
        }
#pragma unroll
        for (int i = 0; i < 8; i++) {
            int idx = tid + 256*i;
            int kk = idx >> 7, n = idx & 127;
            float v = 0.f;
            if (k0 + kk < K) v = W[(size_t)(k0+kk)*128 + n];
            Ws[kk][n] = v;
        }
        __syncthreads();
#pragma unroll
        for (int k = 0; k < 16; k++) {
            float a[8], bv[8];
            *(float4*)&a[0]  = *(const float4*)&As[k][tr*8];
            *(float4*)&a[4]  = *(const float4*)&As[k][tr*8+4];
            *(float4*)&bv[0] = *(const float4*)&Ws[k][tc*8];
            *(float4*)&bv[4] = *(const float4*)&Ws[k][tc*8+4];
#pragma unroll
            for (int u = 0; u < 8; u++)
#pragma unroll
                for (int v = 0; v < 8; v++)
                    acc[u][v] = fmaf(a[u], bv[v], acc[u][v]);
        }
        __syncthreads();
    }
#pragma unroll
    for (int u = 0; u < 8; u++) {
        int r = m0 + tr*8 + u;
#pragma unroll
        for (int v = 0; v < 8; v++) {
            int c = tc*8 + v;
            float val = acc[u][v];
            if (bias) val += bias[c];
            if (act) val = val > 0.f ? val : 0.01f*val;
            C[(size_t)r*ldc + c] = val;
            if (C16) C16[(size_t)r*128 + c] = __float2half_rn(val);
        }
    }
}

// ---------------- per-graph Gram: 128x64 tiles, 8x4 per thread ----------------
__global__ void gram_kernel(const float* __restrict__ Y, int ld,
                            float* __restrict__ G, float* __restrict__ nrm) {
    __shared__ float As[16][136];
    __shared__ float Bs[16][72];
    int b  = blockIdx.z;
    int i0 = blockIdx.y * 128, j0 = blockIdx.x * 64;
    const float* Yb = Y + (size_t)b * 512 * ld;
    int tid = threadIdx.x;
    int tr = tid >> 4, tc = tid & 15;
    float acc[8][4] = {};

    for (int k0 = 0; k0 < 128; k0 += 16) {
#pragma unroll
        for (int t = 0; t < 8; t++) {
            int idx = tid + 256*t;
            int r = idx >> 4, c = idx & 15;
            As[c][r] = Yb[(size_t)(i0 + r)*ld + k0 + c];
        }
#pragma unroll
        for (int t = 0; t < 4; t++) {
            int idx = tid + 256*t;
            int r = idx >> 4, c = idx & 15;
            Bs[c][r] = Yb[(size_t)(j0 + r)*ld + k0 + c];
        }
        __syncthreads();
#pragma unroll
        for (int k = 0; k < 16; k++) {
            float a[8], bv[4];
            *(float4*)&a[0]  = *(const float4*)&As[k][tr*8];
            *(float4*)&a[4]  = *(const float4*)&As[k][tr*8+4];
            *(float4*)&bv[0] = *(const float4*)&Bs[k][tc*4];
#pragma unroll
            for (int u = 0; u < 8; u++)
#pragma unroll
                for (int v = 0; v < 4; v++)
                    acc[u][v] = fmaf(a[u], bv[v], acc[u][v]);
        }
        __syncthreads();
    }
    float* Gb = G + (size_t)b*512*512;
#pragma unroll
    for (int u = 0; u < 8; u++) {
        int r = i0 + tr*8 + u;
        *(float4*)(Gb + (size_t)r*512 + j0 + tc*4) =
            make_float4(acc[u][0], acc[u][1], acc[u][2], acc[u][3]);
    }
#pragma unroll
    for (int u = 0; u < 8; u++) {
        int r = i0 + tr*8 + u;
        int dc = r - (j0 + tc*4);
        if (dc >= 0 && dc < 4)
            nrm[b*512 + r] = acc[u][dc];
    }
}

// ---------------- EdgeConv1: U/V from x (K=6 each) ----------------
__global__ void uv6_kernel(const float* __restrict__ x, const float* __restrict__ W12,
                           float* __restrict__ U, float* __restrict__ V) {
    __shared__ float Ws[12][128];
    int tid = threadIdx.x;   // 256
    for (int t = tid; t < 12*128; t += 256) Ws[t >> 7][t & 127] = W12[t];
    __syncthreads();
    int node = blockIdx.x*2 + (tid >> 7);
    int c = tid & 127;
    const float* xr = x + (size_t)node*6;
    float au = 0.f, av = 0.f;
#pragma unroll
    for (int d = 0; d < 6; d++) {
        float xv = xr[d];
        au = fmaf(xv, Ws[d][c], au);
        av = fmaf(xv, Ws[6+d][c], av);
    }
    U[(size_t)node*128 + c] = au;
    V[(size_t)node*128 + c] = av;
}

// h_e = lrelu(U[i] + V[j] - V[i] + b), 3 edges per node
__global__ void edge_hidden(const float* __restrict__ U, const float* __restrict__ V,
                            const int* __restrict__ nbr, int nstride,
                            const float* __restrict__ b, float* __restrict__ H) {
    int n = blockIdx.x; int c = threadIdx.x;   // 128
    float base = U[(size_t)n*128 + c] - V[(size_t)n*128 + c] + b[c];
#pragma unroll
    for (int k = 0; k < 3; k++) {
        int j = nbr[(size_t)n*nstride + k];
        float h = base + V[(size_t)j*128 + c];
        H[(size_t)(n*3 + k)*128 + c] = h > 0.f ? h : 0.01f*h;
    }
}

// Y_out[n] = max_k lrelu(U[n] + V[j_k] - V[n] + b)
__global__ void edge_fused_max(const float* __restrict__ U, const float* __restrict__ V,
                               const int* __restrict__ nbr, int nstride,
                               const float* __restrict__ b, float* __restrict__ Yout) {
    int n = blockIdx.x; int c = threadIdx.x;   // 128
    float base = U[(size_t)n*128 + c] - V[(size_t)n*128 + c] + b[c];
    float m = -1e30f;
#pragma unroll
    for (int k = 0; k < 3; k++) {
        int j = nbr[(size_t)n*nstride + k];
        float h = base + V[(size_t)j*128 + c];
        h = h > 0.f ? h : 0.01f*h;
        m = fmaxf(m, h);
    }
    Yout[(size_t)n*384 + c] = m;
}

__global__ void maxpool3(const float* __restrict__ M, float* __restrict__ Yc) {
    int n = blockIdx.x; int c = threadIdx.x;   // 128
    float v0 = M[(size_t)(n*3+0)*128 + c];
    float v1 = M[(size_t)(n*3+1)*128 + c];
    float v2 = M[(size_t)(n*3+2)*128 + c];
    Yc[(size_t)n*384 + c] = fmaxf(v0, fmaxf(v1, v2));
}

// ---------------- graph pooling: 4 independent accumulators (MLP ~16) ----------------
__global__ void pool_mean_max(const float* __restrict__ src, int ld,
                              float* __restrict__ z, int offm, int offx) {
    __shared__ float ss[8][32];
    __shared__ float sx[8][32];
    int b = blockIdx.x;
    int lane = threadIdx.x & 31;
    int s = threadIdx.x >> 5;                    // strip 0..7
    int c = blockIdx.y*32 + lane;
    const float* p = src + (size_t)b*512*ld + c + (size_t)(s*64)*ld;
    float s0 = 0.f, s1 = 0.f, s2 = 0.f, s3 = 0.f;
    float x0 = -1e30f, x1 = -1e30f, x2 = -1e30f, x3 = -1e30f;
#pragma unroll
    for (int n = 0; n < 64; n += 4) {
        float v0 = p[(size_t)(n+0)*ld];
        float v1 = p[(size_t)(n+1)*ld];
        float v2 = p[(size_t)(n+2)*ld];
        float v3 = p[(size_t)(n+3)*ld];
        s0 += v0; s1 += v1; s2 += v2; s3 += v3;
        x0 = fmaxf(x0, v0); x1 = fmaxf(x1, v1);
        x2 = fmaxf(x2, v2); x3 = fmaxf(x3, v3);
    }
    float sum = (s0 + s1) + (s2 + s3);
    float mx = fmaxf(fmaxf(x0, x1), fmaxf(x2, x3));
    ss[s][lane] = sum; sx[s][lane] = mx;
    __syncthreads();
    if (s == 0) {
#pragma unroll
        for (int t = 1; t < 8; t++) {
            sum += ss[t][lane];
            mx = fmaxf(mx, sx[t][lane]);
        }
        z[b*DIM2 + offm + c] = sum * (1.f/512.f);
        z[b*DIM2 + offx + c] = mx;
    }
}

// ---------------- head: lin layer with optional fused BatchNorm ----------------
// grid 96, block 512, dyn smem 32 x 1537
__global__ void lin_layer(const float* __restrict__ A, const float* __restrict__ W,
                          const float* __restrict__ bias, float* __restrict__ C,
                          const float* __restrict__ gamma, const float* __restrict__ beta,
                          int doBN) {
    extern __shared__ float As[];               // 32 x 1537
    int tid = threadIdx.x;                       // 512
    for (int idx = tid; idx < 32*1536; idx += 512) {
        int r = idx / 1536; int k = idx - r*1536;
        As[r*1537 + k] = A[idx];
    }
    __syncthreads();
    if (doBN) {
        for (int ch = tid; ch < 1536; ch += 512) {
            float sm = 0.f;
#pragma unroll 8
            for (int r = 0; r < 32; r++) sm += As[r*1537 + ch];
            float mu = sm * (1.f/32.f);
            float vr = 0.f;
#pragma unroll 8
            for (int r = 0; r < 32; r++) { float d = As[r*1537 + ch] - mu; vr += d*d; }
            float inv = rsqrtf(vr*(1.f/32.f) + 1e-5f) * gamma[ch];
            float be = beta[ch];
#pragma unroll 8
            for (int r = 0; r < 32; r++)
                As[r*1537 + ch] = (As[r*1537 + ch] - mu)*inv + be;
        }
        __syncthreads();
    }
    int c = blockIdx.x*16 + (tid & 15);
    int r = tid >> 4;                            // 0..31
    const float* As_r = As + r*1537;
    float a0 = 0.f, a1 = 0.f, a2 = 0.f, a3 = 0.f;
#pragma unroll 8
    for (int k = 0; k < 1536; k += 4) {
        a0 = fmaf(As_r[k+0], W[(size_t)(k+0)*1536 + c], a0);
        a1 = fmaf(As_r[k+1], W[(size_t)(k+1)*1536 + c], a1);
        a2 = fmaf(As_r[k+2], W[(size_t)(k+2)*1536 + c], a2);
        a3 = fmaf(As_r[k+3], W[(size_t)(k+3)*1536 + c], a3);
    }
    float v = (a0 + a1) + (a2 + a3) + bias[c];
    v = v > 0.f ? v : 0.01f*v;
    C[r*DIM2 + c] = v;
}

__global__ void out_kernel(const float* __restrict__ z, const float* __restrict__ W,
                           const float* __restrict__ b, float* __restrict__ out) {
    __shared__ float red[256];
    int row = blockIdx.x; int tid = threadIdx.x;
    float s = 0.f;
    for (int k = tid; k < DIM2; k += 256) s += z[row*DIM2 + k] * W[k];
    red[tid] = s; __syncthreads();
    for (int o = 128; o > 0; o >>= 1) { if (tid < o) red[tid] += red[tid+o]; __syncthreads(); }
    if (tid == 0) out[row] = red[0] + b[0];
}

// ---------------- host orchestration ----------------
extern "C" void kernel_launch(void* const* d_in, const int* in_sizes, int n_in,
                              void* d_out, int out_size) {
    const float* x       = (const float*)d_in[0];
    const float* tag1_W  = (const float*)d_in[2];
    const float* tag1_b  = (const float*)d_in[3];
    const float* tag_W   = (const float*)d_in[4];
    const float* tag_b   = (const float*)d_in[5];
    const float* p1_W1   = (const float*)d_in[6];
    const float* p1_b1   = (const float*)d_in[7];
    const float* p1_W2   = (const float*)d_in[8];
    const float* p1_b2   = (const float*)d_in[9];
    const float* pf_W    = (const float*)d_in[10];
    const float* pf_b    = (const float*)d_in[11];
    const float* bn_g    = (const float*)d_in[12];
    const float* bn_b    = (const float*)d_in[13];
    const float* lin_W   = (const float*)d_in[14];
    const float* lin_b   = (const float*)d_in[15];
    const float* out_W   = (const float*)d_in[16];
    const float* out_b   = (const float*)d_in[17];
    float* out = (float*)d_out;

    int *nbr100, *nbr3;
    float *t1, *hmA, *hmB, *Y, *Z, *M, *gram, *nrm, *z1, *z2;
    __half *h16a, *h16b;
    cudaGetSymbolAddress((void**)&nbr100, g_nbr100);
    cudaGetSymbolAddress((void**)&nbr3,   g_nbr3);
    cudaGetSymbolAddress((void**)&t1,     g_t1);
    cudaGetSymbolAddress((void**)&hmA,    g_hmA);
    cudaGetSymbolAddress((void**)&hmB,    g_hmB);
    cudaGetSymbolAddress((void**)&Y,      g_Y);
    cudaGetSymbolAddress((void**)&Z,      g_Z);
    cudaGetSymbolAddress((void**)&M,      g_M);
    cudaGetSymbolAddress((void**)&gram,   g_gram);
    cudaGetSymbolAddress((void**)&nrm,    g_nrm);
    cudaGetSymbolAddress((void**)&h16a,   g_h16a);
    cudaGetSymbolAddress((void**)&h16b,   g_h16b);
    cudaGetSymbolAddress((void**)&z1,     g_z1);
    cudaGetSymbolAddress((void**)&z2,     g_z2);

    cudaFuncSetAttribute(aggr_smem, cudaFuncAttributeMaxDynamicSharedMemorySize, SMEM_AGG);
    size_t shmem_lin = 32*1537*sizeof(float);
    cudaFuncSetAttribute(lin_layer, cudaFuncAttributeMaxDynamicSharedMemorySize, (int)shmem_lin);

    const float invKG = 1.f/(float)KG;
    dim3 gAgg(4, 32);
    dim3 gPool(32, 4);
    dim3 gGram(8, 4, 32);

    // ===== graph kNN (k=100, sorted ascending; top3 = EdgeConv1 nbrs) =====
    knn_kernel<<<NNODE, 256>>>(x, KG, nbr100);                                   // #1

    // ===== TAG layer 1 (F=6 -> 128) =====
    tag1_aggr<<<32, 512>>>(x, nbr100, t1);                                       // #2
    gemm_bias_lrelu<<<NNODE/128, 256>>>(t1, 18, tag1_W, tag1_b, hmA, 384, 18, 1, h16a); // #3

    // ===== TAG layer 2 aggregation first (ncu slot #4 = aggr_smem) =====
    aggr_smem<<<gAgg, 1024, SMEM_AGG>>>(h16a, nbr100, hmA + 128, 384, h16b, 1, invKG); // #4
    aggr_smem<<<gAgg, 1024, SMEM_AGG>>>(h16b, nbr100, hmA + 256, 384, nullptr, 0, invKG); // #5
    pool_mean_max<<<gPool, 256>>>(hmA, 384, z1, 0, 128);   // TAG1 pool (cols 0:128 intact)
    gemm_bias_lrelu<<<NNODE/128, 256>>>(hmA, 384, tag_W, tag_b, hmB, 384, 384, 1, h16a);
    pool_mean_max<<<gPool, 256>>>(hmB, 384, z1, 256, 384);

    // ===== TAG layer 3 (128 -> 128) =====
    aggr_smem<<<gAgg, 1024, SMEM_AGG>>>(h16a, nbr100, hmB + 128, 384, h16b, 1, invKG);
    aggr_smem<<<gAgg, 1024, SMEM_AGG>>>(h16b, nbr100, hmB + 256, 384, nullptr, 0, invKG);
    gemm_bias_lrelu<<<NNODE/128, 256>>>(hmB, 384, tag_W + 3*128*128, tag_b + 128, hmA, 384, 384, 1, nullptr);
    pool_mean_max<<<gPool, 256>>>(hmA, 384, z1, 512, 640);

    // ===== EdgeConv 1 (on x, k=3, 2-layer MLP; layer1 linearized) =====
    {
        float* U = M;
        float* V = M + (size_t)NNODE*128;
        uv6_kernel<<<NNODE/2, 256>>>(x, p1_W1, U, V);
        edge_hidden<<<NNODE, 128>>>(U, V, nbr100, KG, p1_b1, Z);
    }
    gemm_bias_lrelu<<<NEDGE/128, 256>>>(Z, 128, p1_W2, p1_b2, M, 128, 128, 1, nullptr);
    maxpool3<<<NNODE, 128>>>(M, Y);

    // ===== EdgeConv 2 (kNN on y1, linearized) =====
    gram_kernel<<<gGram, 256>>>(Y, 384, gram, nrm);
    top3_kernel<<<NNODE, 256>>>(gram, nrm, nbr3);
    {
        float* U = Z;
        float* V = Z + (size_t)NNODE*128;
        gemm_bias_lrelu<<<NNODE/128, 256>>>(Y, 384, pf_W,            nullptr, U, 128, 128, 0, nullptr);
        gemm_bias_lrelu<<<NNODE/128, 256>>>(Y, 384, pf_W + 128*128,  nullptr, V, 128, 128, 0, nullptr);
        edge_fused_max<<<NNODE, 128>>>(U, V, nbr3, KP, pf_b, Y + 128);
    }

    // ===== EdgeConv 3 (kNN on y2, linearized) =====
    gram_kernel<<<gGram, 256>>>(Y + 128, 384, gram, nrm);
    top3_kernel<<<NNODE, 256>>>(gram, nrm, nbr3);
    {
        float* U = Z;
        float* V = Z + (size_t)NNODE*128;
        gemm_bias_lrelu<<<NNODE/128, 256>>>(Y + 128, 384, pf_W + 256*128,           nullptr, U, 128, 128, 0, nullptr);
        gemm_bias_lrelu<<<NNODE/128, 256>>>(Y + 128, 384, pf_W + 256*128 + 128*128, nullptr, V, 128, 128, 0, nullptr);
        edge_fused_max<<<NNODE, 128>>>(U, V, nbr3, KP, pf_b + 128, Y + 256);
    }

    // ===== point-branch pooling =====
    pool_mean_max<<<gPool, 256>>>(Y,       384, z1, 768,        768 + 384);
    pool_mean_max<<<gPool, 256>>>(Y + 128, 384, z1, 768 + 128,  768 + 512);
    pool_mean_max<<<gPool, 256>>>(Y + 256, 384, z1, 768 + 256,  768 + 640);

    // ===== head: BN fused into first lin layer =====
    const float* src = z1; float* dst = z2;
    for (int g = 0; g < 5; g++) {
        lin_layer<<<96, 512, shmem_lin>>>(src, lin_W + (size_t)g*1536*1536, lin_b + g*1536,
                                          dst, bn_g, bn_b, g == 0 ? 1 : 0);
        const float* tmp = dst; dst = (float*)src; src = tmp;
    }
    // 5 layers: z1->z2->z1->z2->z1->z2, final in z2
    out_kernel<<<32, 256>>>(z2, out_W, out_b, out);
}

// round 7
// speedup vs baseline: 1.7285x; 1.0325x over previous
#include <cuda_runtime.h>
#include <cuda_fp16.h>
#include <math.h>

#define BB 32
#define NN 512
#define NNODE (BB*NN)      // 16384
#define FF 6
#define WW 128
#define KG 100
#define KP 3
#define NEDGE (NNODE*KP)   // 49152
#define DIM2 1536

typedef unsigned long long ull;

// ---------------- scratch (device globals; no allocation) ----------------
__device__ int    g_nbr100[NNODE*KG];
__device__ int    g_nbr3[NNODE*KP];
__device__ float  g_t1[NNODE*18];
__device__ float  g_hmA[NNODE*384];
__device__ float  g_hmB[NNODE*384];
__device__ float  g_Y[NNODE*384];
__device__ float  g_Z[(size_t)NEDGE*256];
__device__ float  g_M[(size_t)NEDGE*128];
__device__ float  g_gram[(size_t)BB*NN*NN];
__device__ float  g_nrm[NNODE];
__device__ __half g_h16a[NNODE*128];
__device__ __half g_h16b[NNODE*128];
__device__ float  g_z1[BB*DIM2];
__device__ float  g_z2[BB*DIM2];

// ---------------- kNN (k=100): packed 64-bit-key bitonic sort of 512 ----------------
__global__ void knn_kernel(const float* __restrict__ x, int K, int* __restrict__ out) {
    __shared__ ull key[512];
    int node = blockIdx.x;
    int b = node >> 9;
    int i = node & 511;
    int tid = threadIdx.x;  // 256

    float xi[FF];
    const float* xr = x + (size_t)node * FF;
    float sqi = 0.f;
#pragma unroll
    for (int d = 0; d < FF; d++) { xi[d] = xr[d]; sqi += xi[d]*xi[d]; }
    for (int j = tid; j < 512; j += 256) {
        const float* xj = x + (size_t)(b*512 + j) * FF;
        float dot = 0.f, sqj = 0.f;
#pragma unroll
        for (int d = 0; d < FF; d++) { float v = xj[d]; dot += xi[d]*v; sqj += v*v; }
        float dd = sqi + sqj - 2.f*dot;
        if (j == i) dd = 1e10f;
        unsigned int bits = __float_as_uint(dd);
        bits = (bits & 0x80000000u) ? ~bits : (bits | 0x80000000u);
        key[j] = ((ull)bits << 32) | (unsigned)j;
    }
    __syncthreads();

    for (int size = 2; size < 512; size <<= 1) {
        int up = ((tid & (size >> 1)) == 0);
        for (int stride = size >> 1; stride > 0; stride >>= 1) {
            int pos = 2*tid - (tid & (stride - 1));
            ull a = key[pos], c = key[pos + stride];
            ull lo = a < c ? a : c;
            ull hi = a < c ? c : a;
            key[pos]          = up ? lo : hi;
            key[pos + stride] = up ? hi : lo;
            __syncthreads();
        }
    }
    for (int stride = 256; stride > 0; stride >>= 1) {
        int pos = 2*tid - (tid & (stride - 1));
        ull a = key[pos], c = key[pos + stride];
        key[pos]          = a < c ? a : c;
        key[pos + stride] = a < c ? c : a;
        __syncthreads();
    }
    for (int t = tid; t < K; t += 256)
        out[(size_t)node*K + t] = b*512 + (int)(key[t] & 0xffffffffu);
}

// ---------------- top-3 from gram: shfl-based 3-round argmin ----------------
__global__ void top3_kernel(const float* __restrict__ gram, const float* __restrict__ nrm,
                            int* __restrict__ out3) {
    __shared__ ull keys[512];
    __shared__ ull wmin[8];
    int node = blockIdx.x;
    int b = node >> 9, i = node & 511;
    int tid = threadIdx.x;  // 256
    int warp = tid >> 5, lane = tid & 31;
    const float* g = gram + (size_t)b*512*512 + (size_t)i*512;
    const float* nb = nrm + b*512;
    float ni = nb[i];
#pragma unroll
    for (int t = 0; t < 2; t++) {
        int j = tid + 256*t;
        float d = ni + nb[j] - 2.f*g[j];
        if (j == i) d = 1e10f;
        unsigned int bits = __float_as_uint(d);
        bits = (bits & 0x80000000u) ? ~bits : (bits | 0x80000000u);
        keys[j] = ((ull)bits << 32) | (unsigned)j;
    }
    __syncthreads();
#pragma unroll
    for (int r = 0; r < 3; r++) {
        ull m = min(keys[tid], keys[tid+256]);
#pragma unroll
        for (int o = 16; o > 0; o >>= 1)
            m = min(m, __shfl_down_sync(0xffffffffu, m, o));
        if (lane == 0) wmin[warp] = m;
        __syncthreads();
        if (tid == 0) {
            ull best = wmin[0];
#pragma unroll
            for (int w = 1; w < 8; w++) best = min(best, wmin[w]);
            int j = (int)(best & 0xffffffffu);
            out3[node*3 + r] = b*512 + j;
            keys[j] = 0xFFFFFFFFFFFFFFFFull;
        }
        __syncthreads();
    }
}

// ---------------- TAG1: fused per-graph 2-hop mean (dim 6), warp-per-node ----------------
__global__ void tag1_aggr(const float* __restrict__ x, const int* __restrict__ nbr,
                          float* __restrict__ t1) {
    __shared__ float xs[6][512];
    __shared__ float m1[6][512];
    __shared__ float m2[6][512];
    int b = blockIdx.x;
    int tid = threadIdx.x;  // 512
    int warp = tid >> 5, lane = tid & 31;
    const float* xr = x + (size_t)(b*512 + tid)*6;
#pragma unroll
    for (int d = 0; d < 6; d++) xs[d][tid] = xr[d];
    __syncthreads();

    // hop 1: each warp processes 32 nodes, lanes split the 100 neighbors
    for (int nl = 0; nl < 32; nl++) {
        int node = warp*32 + nl;
        const int* nbp = nbr + (size_t)(b*512 + node)*KG;
        float a0=0,a1=0,a2=0,a3=0,a4=0,a5=0;
        for (int k = lane; k < KG; k += 32) {
            int j = nbp[k] & 511;
            a0 += xs[0][j]; a1 += xs[1][j]; a2 += xs[2][j];
            a3 += xs[3][j]; a4 += xs[4][j]; a5 += xs[5][j];
        }
#pragma unroll
        for (int o = 16; o > 0; o >>= 1) {
            a0 += __shfl_down_sync(0xffffffffu, a0, o);
            a1 += __shfl_down_sync(0xffffffffu, a1, o);
            a2 += __shfl_down_sync(0xffffffffu, a2, o);
            a3 += __shfl_down_sync(0xffffffffu, a3, o);
            a4 += __shfl_down_sync(0xffffffffu, a4, o);
            a5 += __shfl_down_sync(0xffffffffu, a5, o);
        }
        if (lane == 0) {
            m1[0][node] = a0*0.01f; m1[1][node] = a1*0.01f; m1[2][node] = a2*0.01f;
            m1[3][node] = a3*0.01f; m1[4][node] = a4*0.01f; m1[5][node] = a5*0.01f;
        }
    }
    __syncthreads();
    // hop 2
    for (int nl = 0; nl < 32; nl++) {
        int node = warp*32 + nl;
        const int* nbp = nbr + (size_t)(b*512 + node)*KG;
        float a0=0,a1=0,a2=0,a3=0,a4=0,a5=0;
        for (int k = lane; k < KG; k += 32) {
            int j = nbp[k] & 511;
            a0 += m1[0][j]; a1 += m1[1][j]; a2 += m1[2][j];
            a3 += m1[3][j]; a4 += m1[4][j]; a5 += m1[5][j];
        }
#pragma unroll
        for (int o = 16; o > 0; o >>= 1) {
            a0 += __shfl_down_sync(0xffffffffu, a0, o);
            a1 += __shfl_down_sync(0xffffffffu, a1, o);
            a2 += __shfl_down_sync(0xffffffffu, a2, o);
            a3 += __shfl_down_sync(0xffffffffu, a3, o);
            a4 += __shfl_down_sync(0xffffffffu, a4, o);
            a5 += __shfl_down_sync(0xffffffffu, a5, o);
        }
        if (lane == 0) {
            m2[0][node] = a0*0.01f; m2[1][node] = a1*0.01f; m2[2][node] = a2*0.01f;
            m2[3][node] = a3*0.01f; m2[4][node] = a4*0.01f; m2[5][node] = a5*0.01f;
        }
    }
    __syncthreads();
    float* tr = t1 + (size_t)(b*512 + tid)*18;
#pragma unroll
    for (int d = 0; d < 6; d++) {
        tr[d]      = xs[d][tid];
        tr[6 + d]  = m1[d][tid];
        tr[12 + d] = m2[d][tid];
    }
}

// ---------------- smem-staged fp16 aggregation (dim 128) ----------------
#define SMEM_AGG (512*128*2 + 32*100*4)
__global__ void aggr_smem(const __half* __restrict__ src16,
                          const int* __restrict__ nbr,
                          float* __restrict__ dst, int ldd,
                          __half* __restrict__ dst2, int wantHalf,
                          float scale) {
    extern __shared__ char sm[];
    __half* tile  = (__half*)sm;                 // [512][128]
    int*    idxbf = (int*)(sm + 512*128*2);      // [32][100]
    int bg = blockIdx.y, part = blockIdx.x;
    int tid = threadIdx.x;                        // 1024
    const uint4* gsrc = (const uint4*)(src16 + (size_t)bg*512*128);
    uint4* stile = (uint4*)tile;
#pragma unroll
    for (int t = 0; t < 8; t++) stile[tid + 1024*t] = gsrc[tid + 1024*t];
    __syncthreads();

    int warp = tid >> 5, lane = tid & 31;
    int* myidx = idxbf + warp*100;
    const uint2* rowbase = (const uint2*)tile + lane;   // lane's 4 channels (8B)
#pragma unroll
    for (int nl = 0; nl < 4; nl++) {
        int nodeLocal = part*128 + warp*4 + nl;
        int node = bg*512 + nodeLocal;
        const int* nb = nbr + (size_t)node*KG;
        myidx[lane]      = nb[lane]      & 511;
        myidx[lane + 32] = nb[lane + 32] & 511;
        myidx[lane + 64] = nb[lane + 64] & 511;
        if (lane < 4) myidx[lane + 96] = nb[lane + 96] & 511;
        __syncwarp();
        float4 acc = {0.f, 0.f, 0.f, 0.f};
#pragma unroll 4
        for (int k = 0; k < KG; k++) {
            int j = myidx[k];
            uint2 u = rowbase[j*32];
            float2 f0 = __half22float2(*reinterpret_cast<__half2*>(&u.x));
            float2 f1 = __half22float2(*reinterpret_cast<__half2*>(&u.y));
            acc.x += f0.x; acc.y += f0.y; acc.z += f1.x; acc.w += f1.y;
        }
        __syncwarp();
        acc.x *= scale; acc.y *= scale; acc.z *= scale; acc.w *= scale;
        *(float4*)(dst + (size_t)node*ldd + lane*4) = acc;
        if (wantHalf) {
            __half2* o = (__half2*)(dst2 + (size_t)node*128 + lane*4);
            o[0] = __floats2half2_rn(acc.x, acc.y);
            o[1] = __floats2half2_rn(acc.z, acc.w);
        }
    }
}

// ---------------- fused GEMM: C = act(A[M,K] @ W[K,128] + bias) ----------------
__global__ void gemm_bias_lrelu(const float* __restrict__ A, int lda,
                                const float* __restrict__ W,
                                const float* __restrict__ bias,
                                float* __restrict__ C, int ldc,
                                int K, int act, __half* __restrict__ C16) {
    __shared__ float As[16][136];
    __shared__ float Ws[16][128];
    int m0 = blockIdx.x * 128;
    int tid = threadIdx.x;
    int tr = tid >> 4, tc = tid & 15;
    float acc[8][8] = {};

    for (int k0 = 0; k0 < K; k0 += 16) {
#pragma unroll
        for (int i = 0; i < 8; i++) {
            int idx = tid + 256*i;
            int r = idx >> 4, c = idx & 15;
            float v = 0.f;
            if (k0 + c < K) v = A[(size_t)(m0 + r)*lda + k0 + c];
            As[c][r] = v;
        }
#pragma unroll
        for (int i = 0; i < 8; i++) {
            int idx = tid + 256*i;
            int kk = idx >> 7, n = idx & 127;
            float v = 0.f;
            if (k0 + kk < K) v = W[(size_t)(k0+kk)*128 + n];
            Ws[kk][n] = v;
        }
        __syncthreads();
#pragma unroll
        for (int k = 0; k < 16; k++) {
            float a[8], bv[8];
            *(float4*)&a[0]  = *(const float4*)&As[k][tr*8];
            *(float4*)&a[4]  = *(const float4*)&As[k][tr*8+4];
            *(float4*)&bv[0] = *(const float4*)&Ws[k][tc*8];
            *(float4*)&bv[4] = *(const float4*)&Ws[k][tc*8+4];
#pragma unroll
            for (int u = 0; u < 8; u++)
#pragma unroll
                for (int v = 0; v < 8; v++)
                    acc[u][v] = fmaf(a[u], bv[v], acc[u][v]);
        }
        __syncthreads();
    }
#pragma unroll
    for (int u = 0; u < 8; u++) {
        int r = m0 + tr*8 + u;
#pragma unroll
        for (int v = 0; v < 8; v++) {
            int c = tc*8 + v;
            float val = acc[u][v];
            if (bias) val += bias[c];
            if (act) val = val > 0.f ? val : 0.01f*val;
            C[(size_t)r*ldc + c] = val;
            if (C16) C16[(size_t)r*128 + c] = __float2half_rn(val);
        }
    }
}

// ---------------- per-graph Gram: 128x64 tiles, 8x4 per thread ----------------
__global__ void gram_kernel(const float* __restrict__ Y, int ld,
                            float* __restrict__ G, float* __restrict__ nrm) {
    __shared__ float As[16][136];
    __shared__ float Bs[16][72];
    int b  = blockIdx.z;
    int i0 = blockIdx.y * 128, j0 = blockIdx.x * 64;
    const float* Yb = Y + (size_t)b * 512 * ld;
    int tid = threadIdx.x;
    int tr = tid >> 4, tc = tid & 15;
    float acc[8][4] = {};

    for (int k0 = 0; k0 < 128; k0 += 16) {
#pragma unroll
        for (int t = 0; t < 8; t++) {
            int idx = tid + 256*t;
            int r = idx >> 4, c = idx & 15;
            As[c][r] = Yb[(size_t)(i0 + r)*ld + k0 + c];
        }
#pragma unroll
        for (int t = 0; t < 4; t++) {
            int idx = tid + 256*t;
            int r = idx >> 4, c = idx & 15;
            Bs[c][r] = Yb[(size_t)(j0 + r)*ld + k0 + c];
        }
        __syncthreads();
#pragma unroll
        for (int k = 0; k < 16; k++) {
            float a[8], bv[4];
            *(float4*)&a[0]  = *(const float4*)&As[k][tr*8];
            *(float4*)&a[4]  = *(const float4*)&As[k][tr*8+4];
            *(float4*)&bv[0] = *(const float4*)&Bs[k][tc*4];
#pragma unroll
            for (int u = 0; u < 8; u++)
#pragma unroll
                for (int v = 0; v < 4; v++)
                    acc[u][v] = fmaf(a[u], bv[v], acc[u][v]);
        }
        __syncthreads();
    }
    float* Gb = G + (size_t)b*512*512;
#pragma unroll
    for (int u = 0; u < 8; u++) {
        int r = i0 + tr*8 + u;
        *(float4*)(Gb + (size_t)r*512 + j0 + tc*4) =
            make_float4(acc[u][0], acc[u][1], acc[u][2], acc[u][3]);
    }
#pragma unroll
    for (int u = 0; u < 8; u++) {
        int r = i0 + tr*8 + u;
        int dc = r - (j0 + tc*4);
        if (dc >= 0 && dc < 4)
            nrm[b*512 + r] = acc[u][dc];
    }
}

// ---------------- EdgeConv1: U/V from x (K=6 each) ----------------
__global__ void uv6_kernel(const float* __restrict__ x, const float* __restrict__ W12,
                           float* __restrict__ U, float* __restrict__ V) {
    __shared__ float Ws[12][128];
    int tid = threadIdx.x;   // 256
    for (int t = tid; t < 12*128; t += 256) Ws[t >> 7][t & 127] = W12[t];
    __syncthreads();
    int node = blockIdx.x*2 + (tid >> 7);
    int c = tid & 127;
    const float* xr = x + (size_t)node*6;
    float au = 0.f, av = 0.f;
#pragma unroll
    for (int d = 0; d < 6; d++) {
        float xv = xr[d];
        au = fmaf(xv, Ws[d][c], au);
        av = fmaf(xv, Ws[6+d][c], av);
    }
    U[(size_t)node*128 + c] = au;
    V[(size_t)node*128 + c] = av;
}

// h_e = lrelu(U[i] + V[j] - V[i] + b), 3 edges per node
__global__ void edge_hidden(const float* __restrict__ U, const float* __restrict__ V,
                            const int* __restrict__ nbr, int nstride,
                            const float* __restrict__ b, float* __restrict__ H) {
    int n = blockIdx.x; int c = threadIdx.x;   // 128
    float base = U[(size_t)n*128 + c] - V[(size_t)n*128 + c] + b[c];
#pragma unroll
    for (int k = 0; k < 3; k++) {
        int j = nbr[(size_t)n*nstride + k];
        float h = base + V[(size_t)j*128 + c];
        H[(size_t)(n*3 + k)*128 + c] = h > 0.f ? h : 0.01f*h;
    }
}

// Y_out[n] = max_k lrelu(U[n] + V[j_k] - V[n] + b)
__global__ void edge_fused_max(const float* __restrict__ U, const float* __restrict__ V,
                               const int* __restrict__ nbr, int nstride,
                               const float* __restrict__ b, float* __restrict__ Yout) {
    int n = blockIdx.x; int c = threadIdx.x;   // 128
    float base = U[(size_t)n*128 + c] - V[(size_t)n*128 + c] + b[c];
    float m = -1e30f;
#pragma unroll
    for (int k = 0; k < 3; k++) {
        int j = nbr[(size_t)n*nstride + k];
        float h = base + V[(size_t)j*128 + c];
        h = h > 0.f ? h : 0.01f*h;
        m = fmaxf(m, h);
    }
    Yout[(size_t)n*384 + c] = m;
}

__global__ void maxpool3(const float* __restrict__ M, float* __restrict__ Yc) {
    int n = blockIdx.x; int c = threadIdx.x;   // 128
    float v0 = M[(size_t)(n*3+0)*128 + c];
    float v1 = M[(size_t)(n*3+1)*128 + c];
    float v2 = M[(size_t)(n*3+2)*128 + c];
    Yc[(size_t)n*384 + c] = fmaxf(v0, fmaxf(v1, v2));
}

// ---------------- graph pooling: 4 independent accumulators ----------------
__global__ void pool_mean_max(const float* __restrict__ src, int ld,
                              float* __restrict__ z, int offm, int offx) {
    __shared__ float ss[8][32];
    __shared__ float sx[8][32];
    int b = blockIdx.x;
    int lane = threadIdx.x & 31;
    int s = threadIdx.x >> 5;
    int c = blockIdx.y*32 + lane;
    const float* p = src + (size_t)b*512*ld + c + (size_t)(s*64)*ld;
    float s0 = 0.f, s1 = 0.f, s2 = 0.f, s3 = 0.f;
    float x0 = -1e30f, x1 = -1e30f, x2 = -1e30f, x3 = -1e30f;
#pragma unroll
    for (int n = 0; n < 64; n += 4) {
        float v0 = p[(size_t)(n+0)*ld];
        float v1 = p[(size_t)(n+1)*ld];
        float v2 = p[(size_t)(n+2)*ld];
        float v3 = p[(size_t)(n+3)*ld];
        s0 += v0; s1 += v1; s2 += v2; s3 += v3;
        x0 = fmaxf(x0, v0); x1 = fmaxf(x1, v1);
        x2 = fmaxf(x2, v2); x3 = fmaxf(x3, v3);
    }
    float sum = (s0 + s1) + (s2 + s3);
    float mx = fmaxf(fmaxf(x0, x1), fmaxf(x2, x3));
    ss[s][lane] = sum; sx[s][lane] = mx;
    __syncthreads();
    if (s == 0) {
#pragma unroll
        for (int t = 1; t < 8; t++) {
            sum += ss[t][lane];
            mx = fmaxf(mx, sx[t][lane]);
        }
        z[b*DIM2 + offm + c] = sum * (1.f/512.f);
        z[b*DIM2 + offx + c] = mx;
    }
}

// fused point-branch pool: all 384 Y channels, grid (32, 12)
__global__ void pool_y(const float* __restrict__ Y, float* __restrict__ z) {
    __shared__ float ss[8][32];
    __shared__ float sx[8][32];
    int b = blockIdx.x;
    int lane = threadIdx.x & 31;
    int s = threadIdx.x >> 5;
    int c = blockIdx.y*32 + lane;                // 0..383
    const float* p = Y + (size_t)b*512*384 + c + (size_t)(s*64)*384;
    float s0 = 0.f, s1 = 0.f, s2 = 0.f, s3 = 0.f;
    float x0 = -1e30f, x1 = -1e30f, x2 = -1e30f, x3 = -1e30f;
#pragma unroll
    for (int n = 0; n < 64; n += 4) {
        float v0 = p[(size_t)(n+0)*384];
        float v1 = p[(size_t)(n+1)*384];
        float v2 = p[(size_t)(n+2)*384];
        float v3 = p[(size_t)(n+3)*384];
        s0 += v0; s1 += v1; s2 += v2; s3 += v3;
        x0 = fmaxf(x0, v0); x1 = fmaxf(x1, v1);
        x2 = fmaxf(x2, v2); x3 = fmaxf(x3, v3);
    }
    float sum = (s0 + s1) + (s2 + s3);
    float mx = fmaxf(fmaxf(x0, x1), fmaxf(x2, x3));
    ss[s][lane] = sum; sx[s][lane] = mx;
    __syncthreads();
    if (s == 0) {
#pragma unroll
        for (int t = 1; t < 8; t++) {
            sum += ss[t][lane];
            mx = fmaxf(mx, sx[t][lane]);
        }
        z[b*DIM2 + 768 + c]  = sum * (1.f/512.f);
        z[b*DIM2 + 1152 + c] = mx;
    }
}

// ---------------- head: lin layer with optional fused BatchNorm ----------------
__global__ void lin_layer(const float* __restrict__ A, const float* __restrict__ W,
                          const float* __restrict__ bias, float* __restrict__ C,
                          const float* __restrict__ gamma, const float* __restrict__ beta,
                          int doBN) {
    extern __shared__ float As[];               // 32 x 1537
    int tid = threadIdx.x;                       // 512
    for (int idx = tid; idx < 32*1536; idx += 512) {
        int r = idx / 1536; int k = idx - r*1536;
        As[r*1537 + k] = A[idx];
    }
    __syncthreads();
    if (doBN) {
        for (int ch = tid; ch < 1536; ch += 512) {
            float sm = 0.f;
#pragma unroll 8
            for (int r = 0; r < 32; r++) sm += As[r*1537 + ch];
            float mu = sm * (1.f/32.f);
            float vr = 0.f;
#pragma unroll 8
            for (int r = 0; r < 32; r++) { float d = As[r*1537 + ch] - mu; vr += d*d; }
            float inv = rsqrtf(vr*(1.f/32.f) + 1e-5f) * gamma[ch];
            float be = beta[ch];
#pragma unroll 8
            for (int r = 0; r < 32; r++)
                As[r*1537 + ch] = (As[r*1537 + ch] - mu)*inv + be;
        }
        __syncthreads();
    }
    int c = blockIdx.x*16 + (tid & 15);
    int r = tid >> 4;
    const float* As_r = As + r*1537;
    float a0 = 0.f, a1 = 0.f, a2 = 0.f, a3 = 0.f;
#pragma unroll 8
    for (int k = 0; k < 1536; k += 4) {
        a0 = fmaf(As_r[k+0], W[(size_t)(k+0)*1536 + c], a0);
        a1 = fmaf(As_r[k+1], W[(size_t)(k+1)*1536 + c], a1);
        a2 = fmaf(As_r[k+2], W[(size_t)(k+2)*1536 + c], a2);
        a3 = fmaf(As_r[k+3], W[(size_t)(k+3)*1536 + c], a3);
    }
    float v = (a0 + a1) + (a2 + a3) + bias[c];
    v = v > 0.f ? v : 0.01f*v;
    C[r*DIM2 + c] = v;
}

__global__ void out_kernel(const float* __restrict__ z, const float* __restrict__ W,
                           const float* __restrict__ b, float* __restrict__ out) {
    __shared__ float red[256];
    int row = blockIdx.x; int tid = threadIdx.x;
    float s = 0.f;
    for (int k = tid; k < DIM2; k += 256) s += z[row*DIM2 + k] * W[k];
    red[tid] = s; __syncthreads();
    for (int o = 128; o > 0; o >>= 1) { if (tid < o) red[tid] += red[tid+o]; __syncthreads(); }
    if (tid == 0) out[row] = red[0] + b[0];
}

// ---------------- host orchestration ----------------
extern "C" void kernel_launch(void* const* d_in, const int* in_sizes, int n_in,
                              void* d_out, int out_size) {
    const float* x       = (const float*)d_in[0];
    const float* tag1_W  = (const float*)d_in[2];
    const float* tag1_b  = (const float*)d_in[3];
    const float* tag_W   = (const float*)d_in[4];
    const float* tag_b   = (const float*)d_in[5];
    const float* p1_W1   = (const float*)d_in[6];
    const float* p1_b1   = (const float*)d_in[7];
    const float* p1_W2   = (const float*)d_in[8];
    const float* p1_b2   = (const float*)d_in[9];
    const float* pf_W    = (const float*)d_in[10];
    const float* pf_b    = (const float*)d_in[11];
    const float* bn_g    = (const float*)d_in[12];
    const float* bn_b    = (const float*)d_in[13];
    const float* lin_W   = (const float*)d_in[14];
    const float* lin_b   = (const float*)d_in[15];
    const float* out_W   = (const float*)d_in[16];
    const float* out_b   = (const float*)d_in[17];
    float* out = (float*)d_out;

    int *nbr100, *nbr3;
    float *t1, *hmA, *hmB, *Y, *Z, *M, *gram, *nrm, *z1, *z2;
    __half *h16a, *h16b;
    cudaGetSymbolAddress((void**)&nbr100, g_nbr100);
    cudaGetSymbolAddress((void**)&nbr3,   g_nbr3);
    cudaGetSymbolAddress((void**)&t1,     g_t1);
    cudaGetSymbolAddress((void**)&hmA,    g_hmA);
    cudaGetSymbolAddress((void**)&hmB,    g_hmB);
    cudaGetSymbolAddress((void**)&Y,      g_Y);
    cudaGetSymbolAddress((void**)&Z,      g_Z);
    cudaGetSymbolAddress((void**)&M,      g_M);
    cudaGetSymbolAddress((void**)&gram,   g_gram);
    cudaGetSymbolAddress((void**)&nrm,    g_nrm);
    cudaGetSymbolAddress((void**)&h16a,   g_h16a);
    cudaGetSymbolAddress((void**)&h16b,   g_h16b);
    cudaGetSymbolAddress((void**)&z1,     g_z1);
    cudaGetSymbolAddress((void**)&z2,     g_z2);

    cudaFuncSetAttribute(aggr_smem, cudaFuncAttributeMaxDynamicSharedMemorySize, SMEM_AGG);
    size_t shmem_lin = 32*1537*sizeof(float);
    cudaFuncSetAttribute(lin_layer, cudaFuncAttributeMaxDynamicSharedMemorySize, (int)shmem_lin);

    const float invKG = 1.f/(float)KG;
    dim3 gAgg(4, 32);
    dim3 gPool(32, 4);
    dim3 gPoolY(32, 12);
    dim3 gGram(8, 4, 32);

    // ===== graph kNN =====
    knn_kernel<<<NNODE, 256>>>(x, KG, nbr100);                                   // #1

    // ===== EdgeConv 1 first (slot #4 = big edge GEMM) =====
    {
        float* U = M;
        float* V = M + (size_t)NNODE*128;
        uv6_kernel<<<NNODE/2, 256>>>(x, p1_W1, U, V);                            // #2
        edge_hidden<<<NNODE, 128>>>(U, V, nbr100, KG, p1_b1, Z);                 // #3
    }
    gemm_bias_lrelu<<<NEDGE/128, 256>>>(Z, 128, p1_W2, p1_b2, M, 128, 128, 1, nullptr); // #4 (profiled)
    maxpool3<<<NNODE, 128>>>(M, Y);                                              // #5

    // ===== TAG layer 1 (F=6 -> 128) =====
    tag1_aggr<<<32, 512>>>(x, nbr100, t1);
    gemm_bias_lrelu<<<NNODE/128, 256>>>(t1, 18, tag1_W, tag1_b, hmA, 384, 18, 1, h16a);

    // ===== TAG layer 2 =====
    aggr_smem<<<gAgg, 1024, SMEM_AGG>>>(h16a, nbr100, hmA + 128, 384, h16b, 1, invKG);
    aggr_smem<<<gAgg, 1024, SMEM_AGG>>>(h16b, nbr100, hmA + 256, 384, nullptr, 0, invKG);
    pool_mean_max<<<gPool, 256>>>(hmA, 384, z1, 0, 128);
    gemm_bias_lrelu<<<NNODE/128, 256>>>(hmA, 384, tag_W, tag_b, hmB, 384, 384, 1, h16a);
    pool_mean_max<<<gPool, 256>>>(hmB, 384, z1, 256, 384);

    // ===== TAG layer 3 =====
    aggr_smem<<<gAgg, 1024, SMEM_AGG>>>(h16a, nbr100, hmB + 128, 384, h16b, 1, invKG);
    aggr_smem<<<gAgg, 1024, SMEM_AGG>>>(h16b, nbr100, hmB + 256, 384, nullptr, 0, invKG);
    gemm_bias_lrelu<<<NNODE/128, 256>>>(hmB, 384, tag_W + 3*128*128, tag_b + 128, hmA, 384, 384, 1, nullptr);
    pool_mean_max<<<gPool, 256>>>(hmA, 384, z1, 512, 640);

    // ===== EdgeConv 2 (kNN on y1, linearized) =====
    gram_kernel<<<gGram, 256>>>(Y, 384, gram, nrm);
    top3_kernel<<<NNODE, 256>>>(gram, nrm, nbr3);
    {
        float* U = Z;
        float* V = Z + (size_t)NNODE*128;
        gemm_bias_lrelu<<<NNODE/128, 256>>>(Y, 384, pf_W,            nullptr, U, 128, 128, 0, nullptr);
        gemm_bias_lrelu<<<NNODE/128, 256>>>(Y, 384, pf_W + 128*128,  nullptr, V, 128, 128, 0, nullptr);
        edge_fused_max<<<NNODE, 128>>>(U, V, nbr3, KP, pf_b, Y + 128);
    }

    // ===== EdgeConv 3 (kNN on y2, linearized) =====
    gram_kernel<<<gGram, 256>>>(Y + 128, 384, gram, nrm);
    top3_kernel<<<NNODE, 256>>>(gram, nrm, nbr3);
    {
        float* U = Z;
        float* V = Z + (size_t)NNODE*128;
        gemm_bias_lrelu<<<NNODE/128, 256>>>(Y + 128, 384, pf_W + 256*128,           nullptr, U, 128, 128, 0, nullptr);
        gemm_bias_lrelu<<<NNODE/128, 256>>>(Y + 128, 384, pf_W + 256*128 + 128*128, nullptr, V, 128, 128, 0, nullptr);
        edge_fused_max<<<NNODE, 128>>>(U, V, nbr3, KP, pf_b + 128, Y + 256);
    }

    // ===== point-branch pooling (fused) =====
    pool_y<<<gPoolY, 256>>>(Y, z1);

    // ===== head: BN fused into first lin layer =====
    const float* src = z1; float* dst = z2;
    for (int g = 0; g < 5; g++) {
        lin_layer<<<96, 512, shmem_lin>>>(src, lin_W + (size_t)g*1536*1536, lin_b + g*1536,
                                          dst, bn_g, bn_b, g == 0 ? 1 : 0);
        const float* tmp = dst; dst = (float*)src; src = tmp;
    }
    out_kernel<<<32, 256>>>(z2, out_W, out_b, out);
}

// round 9
// speedup vs baseline: 1.9540x; 1.1305x over previous
#include <cuda_runtime.h>
#include <cuda_fp16.h>
#include <math.h>

#define BB 32
#define NN 512
#define NNODE (BB*NN)      // 16384
#define FF 6
#define WW 128
#define KG 100
#define KP 3
#define NEDGE (NNODE*KP)   // 49152
#define DIM2 1536

typedef unsigned long long ull;

// ---------------- scratch (device globals; no allocation) ----------------
__device__ int    g_nbr100[NNODE*KG];
__device__ int    g_nbr3[NNODE*KP];
__device__ float  g_t1[NNODE*18];
__device__ float  g_hmA[NNODE*384];
__device__ float  g_hmB[NNODE*384];
__device__ float  g_Y[NNODE*384];
__device__ float  g_Z[(size_t)NEDGE*256];
__device__ float  g_M[(size_t)NEDGE*128];
__device__ float  g_gram[(size_t)BB*NN*NN];
__device__ float  g_nrm[NNODE];
__device__ __half g_h16a[NNODE*128];
__device__ __half g_h16b[NNODE*128];
__device__ float  g_z1[BB*DIM2];
__device__ float  g_z2[BB*DIM2];

// ---------------- tf32 mma helpers ----------------
__device__ __forceinline__ unsigned cvt_tf32(float f) {
    unsigned u;
    asm("cvt.rna.tf32.f32 %0, %1;" : "=r"(u) : "f"(f));
    return u;
}
// split: v = hi + lo, both tf32-representable; hi+lo error ~2^-24 of v
__device__ __forceinline__ void split_tf32(float v, unsigned& hi, unsigned& lo) {
    hi = cvt_tf32(v);
    lo = cvt_tf32(v - __uint_as_float(hi));
}
__device__ __forceinline__ void mma_tf32(float* c, const unsigned* a, const unsigned* b) {
    asm("mma.sync.aligned.m16n8k8.row.col.f32.tf32.tf32.f32 "
        "{%0,%1,%2,%3}, {%4,%5,%6,%7}, {%8,%9}, {%0,%1,%2,%3};"
        : "+f"(c[0]), "+f"(c[1]), "+f"(c[2]), "+f"(c[3])
        : "r"(a[0]), "r"(a[1]), "r"(a[2]), "r"(a[3]), "r"(b[0]), "r"(b[1]));
}

// ---------------- tensor-core GEMM (split-TF32, fp32-accurate) ----------------
// C = act(A[M,K] @ W[K,128] + bias). BM=128, BN=128, BK=32, 256 thr (8 warps 2x4).
// K % 32 == 0, M % 128 == 0. Error ~2^-22 (TF32x3: hi*hi + hi*lo + lo*hi).
#define TCPAD 133
__global__ void gemm_tc(const float* __restrict__ A, int lda,
                        const float* __restrict__ W,
                        const float* __restrict__ bias,
                        float* __restrict__ C, int ldc,
                        int K, int act, __half* __restrict__ C16) {
    __shared__ float As[32][TCPAD];   // [k][m]
    __shared__ float Ws[32][TCPAD];   // [k][n]
    int m0 = blockIdx.x * 128;
    int tid = threadIdx.x;
    int warp = tid >> 5, lane = tid & 31;
    int wr = warp >> 2, wc = warp & 3;      // warp tile: 64 rows x 32 cols
    int g = lane >> 2, tg = lane & 3;
    float acc[4][4][4] = {};

    for (int k0 = 0; k0 < K; k0 += 32) {
#pragma unroll
        for (int t = 0; t < 16; t++) {
            int idx = tid + 256*t;
            int m = idx >> 5, k = idx & 31;
            As[k][m] = A[(size_t)(m0 + m)*lda + k0 + k];
        }
#pragma unroll
        for (int t = 0; t < 16; t++) {
            int idx = tid + 256*t;
            int k = idx >> 7, n = idx & 127;
            Ws[k][n] = W[(size_t)(k0 + k)*128 + n];
        }
        __syncthreads();
#pragma unroll
        for (int kk = 0; kk < 32; kk += 8) {
            unsigned ah[4][4], al[4][4], bh[4][2], bl[4][2];
#pragma unroll
            for (int tm = 0; tm < 4; tm++) {
                int mr = wr*64 + tm*16;
                split_tf32(As[kk + tg][mr + g],         ah[tm][0], al[tm][0]);
                split_tf32(As[kk + tg][mr + g + 8],     ah[tm][1], al[tm][1]);
                split_tf32(As[kk + tg + 4][mr + g],     ah[tm][2], al[tm][2]);
                split_tf32(As[kk + tg + 4][mr + g + 8], ah[tm][3], al[tm][3]);
            }
#pragma unroll
            for (int tn = 0; tn < 4; tn++) {
                int nc = wc*32 + tn*8;
                split_tf32(Ws[kk + tg][nc + g],     bh[tn][0], bl[tn][0]);
                split_tf32(Ws[kk + tg + 4][nc + g], bh[tn][1], bl[tn][1]);
            }
#pragma unroll
            for (int tm = 0; tm < 4; tm++)
#pragma unroll
                for (int tn = 0; tn < 4; tn++) {
                    mma_tf32(acc[tm][tn], ah[tm], bl[tn]);  // hi*lo
                    mma_tf32(acc[tm][tn], al[tm], bh[tn]);  // lo*hi
                    mma_tf32(acc[tm][tn], ah[tm], bh[tn]);  // hi*hi (last: largest term)
                }
        }
        __syncthreads();
    }
    // epilogue: c0(r,c) c1(r,c+1) c2(r+8,c) c3(r+8,c+1)
#pragma unroll
    for (int tm = 0; tm < 4; tm++) {
        int r = m0 + wr*64 + tm*16 + g;
#pragma unroll
        for (int tn = 0; tn < 4; tn++) {
            int c = wc*32 + tn*8 + 2*tg;
            float v0 = acc[tm][tn][0], v1 = acc[tm][tn][1];
            float v2 = acc[tm][tn][2], v3 = acc[tm][tn][3];
            if (bias) {
                float b0 = bias[c], b1 = bias[c+1];
                v0 += b0; v1 += b1; v2 += b0; v3 += b1;
            }
            if (act) {
                v0 = v0 > 0.f ? v0 : 0.01f*v0;
                v1 = v1 > 0.f ? v1 : 0.01f*v1;
                v2 = v2 > 0.f ? v2 : 0.01f*v2;
                v3 = v3 > 0.f ? v3 : 0.01f*v3;
            }
            *(float2*)&C[(size_t)r*ldc + c]     = make_float2(v0, v1);
            *(float2*)&C[(size_t)(r+8)*ldc + c] = make_float2(v2, v3);
            if (C16) {
                *(__half2*)&C16[(size_t)r*128 + c]     = __floats2half2_rn(v0, v1);
                *(__half2*)&C16[(size_t)(r+8)*128 + c] = __floats2half2_rn(v2, v3);
            }
        }
    }
}

// ---------------- kNN (k=100): packed 64-bit-key bitonic sort of 512 ----------------
__global__ void knn_kernel(const float* __restrict__ x, int K, int* __restrict__ out) {
    __shared__ ull key[512];
    int node = blockIdx.x;
    int b = node >> 9;
    int i = node & 511;
    int tid = threadIdx.x;  // 256

    float xi[FF];
    const float* xr = x + (size_t)node * FF;
    float sqi = 0.f;
#pragma unroll
    for (int d = 0; d < FF; d++) { xi[d] = xr[d]; sqi += xi[d]*xi[d]; }
    for (int j = tid; j < 512; j += 256) {
        const float* xj = x + (size_t)(b*512 + j) * FF;
        float dot = 0.f, sqj = 0.f;
#pragma unroll
        for (int d = 0; d < FF; d++) { float v = xj[d]; dot += xi[d]*v; sqj += v*v; }
        float dd = sqi + sqj - 2.f*dot;
        if (j == i) dd = 1e10f;
        unsigned int bits = __float_as_uint(dd);
        bits = (bits & 0x80000000u) ? ~bits : (bits | 0x80000000u);
        key[j] = ((ull)bits << 32) | (unsigned)j;
    }
    __syncthreads();

    for (int size = 2; size < 512; size <<= 1) {
        int up = ((tid & (size >> 1)) == 0);
        for (int stride = size >> 1; stride > 0; stride >>= 1) {
            int pos = 2*tid - (tid & (stride - 1));
            ull a = key[pos], c = key[pos + stride];
            ull lo = a < c ? a : c;
            ull hi = a < c ? c : a;
            key[pos]          = up ? lo : hi;
            key[pos + stride] = up ? hi : lo;
            __syncthreads();
        }
    }
    for (int stride = 256; stride > 0; stride >>= 1) {
        int pos = 2*tid - (tid & (stride - 1));
        ull a = key[pos], c = key[pos + stride];
        key[pos]          = a < c ? a : c;
        key[pos + stride] = a < c ? c : a;
        __syncthreads();
    }
    for (int t = tid; t < K; t += 256)
        out[(size_t)node*K + t] = b*512 + (int)(key[t] & 0xffffffffu);
}

// ---------------- top-3 from gram: shfl-based 3-round argmin ----------------
__global__ void top3_kernel(const float* __restrict__ gram, const float* __restrict__ nrm,
                            int* __restrict__ out3) {
    __shared__ ull keys[512];
    __shared__ ull wmin[8];
    int node = blockIdx.x;
    int b = node >> 9, i = node & 511;
    int tid = threadIdx.x;  // 256
    int warp = tid >> 5, lane = tid & 31;
    const float* g = gram + (size_t)b*512*512 + (size_t)i*512;
    const float* nb = nrm + b*512;
    float ni = nb[i];
#pragma unroll
    for (int t = 0; t < 2; t++) {
        int j = tid + 256*t;
        float d = ni + nb[j] - 2.f*g[j];
        if (j == i) d = 1e10f;
        unsigned int bits = __float_as_uint(d);
        bits = (bits & 0x80000000u) ? ~bits : (bits | 0x80000000u);
        keys[j] = ((ull)bits << 32) | (unsigned)j;
    }
    __syncthreads();
#pragma unroll
    for (int r = 0; r < 3; r++) {
        ull m = min(keys[tid], keys[tid+256]);
#pragma unroll
        for (int o = 16; o > 0; o >>= 1)
            m = min(m, __shfl_down_sync(0xffffffffu, m, o));
        if (lane == 0) wmin[warp] = m;
        __syncthreads();
        if (tid == 0) {
            ull best = wmin[0];
#pragma unroll
            for (int w = 1; w < 8; w++) best = min(best, wmin[w]);
            int j = (int)(best & 0xffffffffu);
            out3[node*3 + r] = b*512 + j;
            keys[j] = 0xFFFFFFFFFFFFFFFFull;
        }
        __syncthreads();
    }
}

// ---------------- TAG1: fused per-graph 2-hop mean (dim 6), warp-per-node ----------------
__global__ void tag1_aggr(const float* __restrict__ x, const int* __restrict__ nbr,
                          float* __restrict__ t1) {
    __shared__ float xs[6][512];
    __shared__ float m1[6][512];
    __shared__ float m2[6][512];
    int b = blockIdx.x;
    int tid = threadIdx.x;  // 512
    int warp = tid >> 5, lane = tid & 31;
    const float* xr = x + (size_t)(b*512 + tid)*6;
#pragma unroll
    for (int d = 0; d < 6; d++) xs[d][tid] = xr[d];
    __syncthreads();

    for (int nl = 0; nl < 32; nl++) {
        int node = warp*32 + nl;
        const int* nbp = nbr + (size_t)(b*512 + node)*KG;
        float a0=0,a1=0,a2=0,a3=0,a4=0,a5=0;
        for (int k = lane; k < KG; k += 32) {
            int j = nbp[k] & 511;
            a0 += xs[0][j]; a1 += xs[1][j]; a2 += xs[2][j];
            a3 += xs[3][j]; a4 += xs[4][j]; a5 += xs[5][j];
        }
#pragma unroll
        for (int o = 16; o > 0; o >>= 1) {
            a0 += __shfl_down_sync(0xffffffffu, a0, o);
            a1 += __shfl_down_sync(0xffffffffu, a1, o);
            a2 += __shfl_down_sync(0xffffffffu, a2, o);
            a3 += __shfl_down_sync(0xffffffffu, a3, o);
            a4 += __shfl_down_sync(0xffffffffu, a4, o);
            a5 += __shfl_down_sync(0xffffffffu, a5, o);
        }
        if (lane == 0) {
            m1[0][node] = a0*0.01f; m1[1][node] = a1*0.01f; m1[2][node] = a2*0.01f;
            m1[3][node] = a3*0.01f; m1[4][node] = a4*0.01f; m1[5][node] = a5*0.01f;
        }
    }
    __syncthreads();
    for (int nl = 0; nl < 32; nl++) {
        int node = warp*32 + nl;
        const int* nbp = nbr + (size_t)(b*512 + node)*KG;
        float a0=0,a1=0,a2=0,a3=0,a4=0,a5=0;
        for (int k = lane; k < KG; k += 32) {
            int j = nbp[k] & 511;
            a0 += m1[0][j]; a1 += m1[1][j]; a2 += m1[2][j];
            a3 += m1[3][j]; a4 += m1[4][j]; a5 += m1[5][j];
        }
#pragma unroll
        for (int o = 16; o > 0; o >>= 1) {
            a0 += __shfl_down_sync(0xffffffffu, a0, o);
            a1 += __shfl_down_sync(0xffffffffu, a1, o);
            a2 += __shfl_down_sync(0xffffffffu, a2, o);
            a3 += __shfl_down_sync(0xffffffffu, a3, o);
            a4 += __shfl_down_sync(0xffffffffu, a4, o);
            a5 += __shfl_down_sync(0xffffffffu, a5, o);
        }
        if (lane == 0) {
            m2[0][node] = a0*0.01f; m2[1][node] = a1*0.01f; m2[2][node] = a2*0.01f;
            m2[3][node] = a3*0.01f; m2[4][node] = a4*0.01f; m2[5][node] = a5*0.01f;
        }
    }
    __syncthreads();
    float* tr = t1 + (size_t)(b*512 + tid)*18;
#pragma unroll
    for (int d = 0; d < 6; d++) {
        tr[d]      = xs[d][tid];
        tr[6 + d]  = m1[d][tid];
        tr[12 + d] = m2[d][tid];
    }
}

// ---------------- smem-staged fp16 aggregation (dim 128) ----------------
#define SMEM_AGG (512*128*2 + 32*100*4)
__global__ void aggr_smem(const __half* __restrict__ src16,
                          const int* __restrict__ nbr,
                          float* __restrict__ dst, int ldd,
                          __half* __restrict__ dst2, int wantHalf,
                          float scale) {
    extern __shared__ char sm[];
    __half* tile  = (__half*)sm;
    int*    idxbf = (int*)(sm + 512*128*2);
    int bg = blockIdx.y, part = blockIdx.x;
    int tid = threadIdx.x;                        // 1024
    const uint4* gsrc = (const uint4*)(src16 + (size_t)bg*512*128);
    uint4* stile = (uint4*)tile;
#pragma unroll
    for (int t = 0; t < 8; t++) stile[tid + 1024*t] = gsrc[tid + 1024*t];
    __syncthreads();

    int warp = tid >> 5, lane = tid & 31;
    int* myidx = idxbf + warp*100;
    const uint2* rowbase = (const uint2*)tile + lane;
#pragma unroll
    for (int nl = 0; nl < 4; nl++) {
        int nodeLocal = part*128 + warp*4 + nl;
        int node = bg*512 + nodeLocal;
        const int* nb = nbr + (size_t)node*KG;
        myidx[lane]      = nb[lane]      & 511;
        myidx[lane + 32] = nb[lane + 32] & 511;
        myidx[lane + 64] = nb[lane + 64] & 511;
        if (lane < 4) myidx[lane + 96] = nb[lane + 96] & 511;
        __syncwarp();
        float4 acc = {0.f, 0.f, 0.f, 0.f};
#pragma unroll 4
        for (int k = 0; k < KG; k++) {
            int j = myidx[k];
            uint2 u = rowbase[j*32];
            float2 f0 = __half22float2(*reinterpret_cast<__half2*>(&u.x));
            float2 f1 = __half22float2(*reinterpret_cast<__half2*>(&u.y));
            acc.x += f0.x; acc.y += f0.y; acc.z += f1.x; acc.w += f1.y;
        }
        __syncwarp();
        acc.x *= scale; acc.y *= scale; acc.z *= scale; acc.w *= scale;
        *(float4*)(dst + (size_t)node*ldd + lane*4) = acc;
        if (wantHalf) {
            __half2* o = (__half2*)(dst2 + (size_t)node*128 + lane*4);
            o[0] = __floats2half2_rn(acc.x, acc.y);
            o[1] = __floats2half2_rn(acc.z, acc.w);
        }
    }
}

// ---------------- SIMT GEMM (only for K=18 t1 layer) ----------------
__global__ void gemm_bias_lrelu(const float* __restrict__ A, int lda,
                                const float* __restrict__ W,
                                const float* __restrict__ bias,
                                float* __restrict__ C, int ldc,
                                int K, int act, __half* __restrict__ C16) {
    __shared__ float As[16][136];
    __shared__ float Ws[16][128];
    int m0 = blockIdx.x * 128;
    int tid = threadIdx.x;
    int tr = tid >> 4, tc = tid & 15;
    float acc[8][8] = {};

    for (int k0 = 0; k0 < K; k0 += 16) {
#pragma unroll
        for (int i = 0; i < 8; i++) {
            int idx = tid + 256*i;
            int r = idx >> 4, c = idx & 15;
            float v = 0.f;
            if (k0 + c < K) v = A[(size_t)(m0 + r)*lda + k0 + c];
            As[c][r] = v;
        }
#pragma unroll
        for (int i = 0; i < 8; i++) {
            int idx = tid + 256*i;
            int kk = idx >> 7, n = idx & 127;
            float v = 0.f;
            if (k0 + kk < K) v = W[(size_t)(k0+kk)*128 + n];
            Ws[kk][n] = v;
        }
        __syncthreads();
#pragma unroll
        for (int k = 0; k < 16; k++) {
            float a[8], bv[8];
            *(float4*)&a[0]  = *(const float4*)&As[k][tr*8];
            *(float4*)&a[4]  = *(const float4*)&As[k][tr*8+4];
            *(float4*)&bv[0] = *(const float4*)&Ws[k][tc*8];
            *(float4*)&bv[4] = *(const float4*)&Ws[k][tc*8+4];
#pragma unroll
            for (int u = 0; u < 8; u++)
#pragma unroll
                for (int v = 0; v < 8; v++)
                    acc[u][v] = fmaf(a[u], bv[v], acc[u][v]);
        }
        __syncthreads();
    }
#pragma unroll
    for (int u = 0; u < 8; u++) {
        int r = m0 + tr*8 + u;
#pragma unroll
        for (int v = 0; v < 8; v++) {
            int c = tc*8 + v;
            float val = acc[u][v];
            if (bias) val += bias[c];
            if (act) val = val > 0.f ? val : 0.01f*val;
            C[(size_t)r*ldc + c] = val;
            if (C16) C16[(size_t)r*128 + c] = __float2half_rn(val);
        }
    }
}

// ---------------- per-graph Gram: 128x64 tiles, 8x4 per thread (fp32, selection-stable) ----------------
__global__ void gram_kernel(const float* __restrict__ Y, int ld,
                            float* __restrict__ G, float* __restrict__ nrm) {
    __shared__ float As[16][136];
    __shared__ float Bs[16][72];
    int b  = blockIdx.z;
    int i0 = blockIdx.y * 128, j0 = blockIdx.x * 64;
    const float* Yb = Y + (size_t)b * 512 * ld;
    int tid = threadIdx.x;
    int tr = tid >> 4, tc = tid & 15;
    float acc[8][4] = {};

    for (int k0 = 0; k0 < 128; k0 += 16) {
#pragma unroll
        for (int t = 0; t < 8; t++) {
            int idx = tid + 256*t;
            int r = idx >> 4, c = idx & 15;
            As[c][r] = Yb[(size_t)(i0 + r)*ld + k0 + c];
        }
#pragma unroll
        for (int t = 0; t < 4; t++) {
            int idx = tid + 256*t;
            int r = idx >> 4, c = idx & 15;
            Bs[c][r] = Yb[(size_t)(j0 + r)*ld + k0 + c];
        }
        __syncthreads();
#pragma unroll
        for (int k = 0; k < 16; k++) {
            float a[8], bv[4];
            *(float4*)&a[0]  = *(const float4*)&As[k][tr*8];
            *(float4*)&a[4]  = *(const float4*)&As[k][tr*8+4];
            *(float4*)&bv[0] = *(const float4*)&Bs[k][tc*4];
#pragma unroll
            for (int u = 0; u < 8; u++)
#pragma unroll
                for (int v = 0; v < 4; v++)
                    acc[u][v] = fmaf(a[u], bv[v], acc[u][v]);
        }
        __syncthreads();
    }
    float* Gb = G + (size_t)b*512*512;
#pragma unroll
    for (int u = 0; u < 8; u++) {
        int r = i0 + tr*8 + u;
        *(float4*)(Gb + (size_t)r*512 + j0 + tc*4) =
            make_float4(acc[u][0], acc[u][1], acc[u][2], acc[u][3]);
    }
#pragma unroll
    for (int u = 0; u < 8; u++) {
        int r = i0 + tr*8 + u;
        int dc = r - (j0 + tc*4);
        if (dc >= 0 && dc < 4)
            nrm[b*512 + r] = acc[u][dc];
    }
}

// ---------------- EdgeConv1: U/V from x (K=6 each) ----------------
__global__ void uv6_kernel(const float* __restrict__ x, const float* __restrict__ W12,
                           float* __restrict__ U, float* __restrict__ V) {
    __shared__ float Ws[12][128];
    int tid = threadIdx.x;   // 256
    for (int t = tid; t < 12*128; t += 256) Ws[t >> 7][t & 127] = W12[t];
    __syncthreads();
    int node = blockIdx.x*2 + (tid >> 7);
    int c = tid & 127;
    const float* xr = x + (size_t)node*6;
    float au = 0.f, av = 0.f;
#pragma unroll
    for (int d = 0; d < 6; d++) {
        float xv = xr[d];
        au = fmaf(xv, Ws[d][c], au);
        av = fmaf(xv, Ws[6+d][c], av);
    }
    U[(size_t)node*128 + c] = au;
    V[(size_t)node*128 + c] = av;
}

// h_e = lrelu(U[i] + V[j] - V[i] + b), 3 edges per node
__global__ void edge_hidden(const float* __restrict__ U, const float* __restrict__ V,
                            const int* __restrict__ nbr, int nstride,
                            const float* __restrict__ b, float* __restrict__ H) {
    int n = blockIdx.x; int c = threadIdx.x;   // 128
    float base = U[(size_t)n*128 + c] - V[(size_t)n*128 + c] + b[c];
#pragma unroll
    for (int k = 0; k < 3; k++) {
        int j = nbr[(size_t)n*nstride + k];
        float h = base + V[(size_t)j*128 + c];
        H[(size_t)(n*3 + k)*128 + c] = h > 0.f ? h : 0.01f*h;
    }
}

// Y_out[n] = max_k lrelu(U[n] + V[j_k] - V[n] + b)
__global__ void edge_fused_max(const float* __restrict__ U, const float* __restrict__ V,
                               const int* __restrict__ nbr, int nstride,
                               const float* __restrict__ b, float* __restrict__ Yout) {
    int n = blockIdx.x; int c = threadIdx.x;   // 128
    float base = U[(size_t)n*128 + c] - V[(size_t)n*128 + c] + b[c];
    float m = -1e30f;
#pragma unroll
    for (int k = 0; k < 3; k++) {
        int j = nbr[(size_t)n*nstride + k];
        float h = base + V[(size_t)j*128 + c];
        h = h > 0.f ? h : 0.01f*h;
        m = fmaxf(m, h);
    }
    Yout[(size_t)n*384 + c] = m;
}

__global__ void maxpool3(const float* __restrict__ M, float* __restrict__ Yc) {
    int n = blockIdx.x; int c = threadIdx.x;   // 128
    float v0 = M[(size_t)(n*3+0)*128 + c];
    float v1 = M[(size_t)(n*3+1)*128 + c];
    float v2 = M[(size_t)(n*3+2)*128 + c];
    Yc[(size_t)n*384 + c] = fmaxf(v0, fmaxf(v1, v2));
}

// ---------------- graph pooling ----------------
__global__ void pool_mean_max(const float* __restrict__ src, int ld,
                              float* __restrict__ z, int offm, int offx) {
    __shared__ float ss[8][32];
    __shared__ float sx[8][32];
    int b = blockIdx.x;
    int lane = threadIdx.x & 31;
    int s = threadIdx.x >> 5;
    int c = blockIdx.y*32 + lane;
    const float* p = src + (size_t)b*512*ld + c + (size_t)(s*64)*ld;
    float s0 = 0.f, s1 = 0.f, s2 = 0.f, s3 = 0.f;
    float x0 = -1e30f, x1 = -1e30f, x2 = -1e30f, x3 = -1e30f;
#pragma unroll
    for (int n = 0; n < 64; n += 4) {
        float v0 = p[(size_t)(n+0)*ld];
        float v1 = p[(size_t)(n+1)*ld];
        float v2 = p[(size_t)(n+2)*ld];
        float v3 = p[(size_t)(n+3)*ld];
        s0 += v0; s1 += v1; s2 += v2; s3 += v3;
        x0 = fmaxf(x0, v0); x1 = fmaxf(x1, v1);
        x2 = fmaxf(x2, v2); x3 = fmaxf(x3, v3);
    }
    float sum = (s0 + s1) + (s2 + s3);
    float mx = fmaxf(fmaxf(x0, x1), fmaxf(x2, x3));
    ss[s][lane] = sum; sx[s][lane] = mx;
    __syncthreads();
    if (s == 0) {
#pragma unroll
        for (int t = 1; t < 8; t++) {
            sum += ss[t][lane];
            mx = fmaxf(mx, sx[t][lane]);
        }
        z[b*DIM2 + offm + c] = sum * (1.f/512.f);
        z[b*DIM2 + offx + c] = mx;
    }
}

__global__ void pool_y(const float* __restrict__ Y, float* __restrict__ z) {
    __shared__ float ss[8][32];
    __shared__ float sx[8][32];
    int b = blockIdx.x;
    int lane = threadIdx.x & 31;
    int s = threadIdx.x >> 5;
    int c = blockIdx.y*32 + lane;
    const float* p = Y + (size_t)b*512*384 + c + (size_t)(s*64)*384;
    float s0 = 0.f, s1 = 0.f, s2 = 0.f, s3 = 0.f;
    float x0 = -1e30f, x1 = -1e30f, x2 = -1e30f, x3 = -1e30f;
#pragma unroll
    for (int n = 0; n < 64; n += 4) {
        float v0 = p[(size_t)(n+0)*384];
        float v1 = p[(size_t)(n+1)*384];
        float v2 = p[(size_t)(n+2)*384];
        float v3 = p[(size_t)(n+3)*384];
        s0 += v0; s1 += v1; s2 += v2; s3 += v3;
        x0 = fmaxf(x0, v0); x1 = fmaxf(x1, v1);
        x2 = fmaxf(x2, v2); x3 = fmaxf(x3, v3);
    }
    float sum = (s0 + s1) + (s2 + s3);
    float mx = fmaxf(fmaxf(x0, x1), fmaxf(x2, x3));
    ss[s][lane] = sum; sx[s][lane] = mx;
    __syncthreads();
    if (s == 0) {
#pragma unroll
        for (int t = 1; t < 8; t++) {
            sum += ss[t][lane];
            mx = fmaxf(mx, sx[t][lane]);
        }
        z[b*DIM2 + 768 + c]  = sum * (1.f/512.f);
        z[b*DIM2 + 1152 + c] = mx;
    }
}

// ---------------- head: lin layer with optional fused BatchNorm ----------------
__global__ void lin_layer(const float* __restrict__ A, const float* __restrict__ W,
                          const float* __restrict__ bias, float* __restrict__ C,
                          const float* __restrict__ gamma, const float* __restrict__ beta,
                          int doBN) {
    extern __shared__ float As[];               // 32 x 1537
    int tid = threadIdx.x;                       // 512
    for (int idx = tid; idx < 32*1536; idx += 512) {
        int r = idx / 1536; int k = idx - r*1536;
        As[r*1537 + k] = A[idx];
    }
    __syncthreads();
    if (doBN) {
        for (int ch = tid; ch < 1536; ch += 512) {
            float sm = 0.f;
#pragma unroll 8
            for (int r = 0; r < 32; r++) sm += As[r*1537 + ch];
            float mu = sm * (1.f/32.f);
            float vr = 0.f;
#pragma unroll 8
            for (int r = 0; r < 32; r++) { float d = As[r*1537 + ch] - mu; vr += d*d; }
            float inv = rsqrtf(vr*(1.f/32.f) + 1e-5f) * gamma[ch];
            float be = beta[ch];
#pragma unroll 8
            for (int r = 0; r < 32; r++)
                As[r*1537 + ch] = (As[r*1537 + ch] - mu)*inv + be;
        }
        __syncthreads();
    }
    int c = blockIdx.x*16 + (tid & 15);
    int r = tid >> 4;
    const float* As_r = As + r*1537;
    float a0 = 0.f, a1 = 0.f, a2 = 0.f, a3 = 0.f;
#pragma unroll 8
    for (int k = 0; k < 1536; k += 4) {
        a0 = fmaf(As_r[k+0], W[(size_t)(k+0)*1536 + c], a0);
        a1 = fmaf(As_r[k+1], W[(size_t)(k+1)*1536 + c], a1);
        a2 = fmaf(As_r[k+2], W[(size_t)(k+2)*1536 + c], a2);
        a3 = fmaf(As_r[k+3], W[(size_t)(k+3)*1536 + c], a3);
    }
    float v = (a0 + a1) + (a2 + a3) + bias[c];
    v = v > 0.f ? v : 0.01f*v;
    C[r*DIM2 + c] = v;
}

__global__ void out_kernel(const float* __restrict__ z, const float* __restrict__ W,
                           const float* __restrict__ b, float* __restrict__ out) {
    __shared__ float red[256];
    int row = blockIdx.x; int tid = threadIdx.x;
    float s = 0.f;
    for (int k = tid; k < DIM2; k += 256) s += z[row*DIM2 + k] * W[k];
    red[tid] = s; __syncthreads();
    for (int o = 128; o > 0; o >>= 1) { if (tid < o) red[tid] += red[tid+o]; __syncthreads(); }
    if (tid == 0) out[row] = red[0] + b[0];
}

// ---------------- host orchestration ----------------
extern "C" void kernel_launch(void* const* d_in, const int* in_sizes, int n_in,
                              void* d_out, int out_size) {
    const float* x       = (const float*)d_in[0];
    const float* tag1_W  = (const float*)d_in[2];
    const float* tag1_b  = (const float*)d_in[3];
    const float* tag_W   = (const float*)d_in[4];
    const float* tag_b   = (const float*)d_in[5];
    const float* p1_W1   = (const float*)d_in[6];
    const float* p1_b1   = (const float*)d_in[7];
    const float* p1_W2   = (const float*)d_in[8];
    const float* p1_b2   = (const float*)d_in[9];
    const float* pf_W    = (const float*)d_in[10];
    const float* pf_b    = (const float*)d_in[11];
    const float* bn_g    = (const float*)d_in[12];
    const float* bn_b    = (const float*)d_in[13];
    const float* lin_W   = (const float*)d_in[14];
    const float* lin_b   = (const float*)d_in[15];
    const float* out_W   = (const float*)d_in[16];
    const float* out_b   = (const float*)d_in[17];
    float* out = (float*)d_out;

    int *nbr100, *nbr3;
    float *t1, *hmA, *hmB, *Y, *Z, *M, *gram, *nrm, *z1, *z2;
    __half *h16a, *h16b;
    cudaGetSymbolAddress((void**)&nbr100, g_nbr100);
    cudaGetSymbolAddress((void**)&nbr3,   g_nbr3);
    cudaGetSymbolAddress((void**)&t1,     g_t1);
    cudaGetSymbolAddress((void**)&hmA,    g_hmA);
    cudaGetSymbolAddress((void**)&hmB,    g_hmB);
    cudaGetSymbolAddress((void**)&Y,      g_Y);
    cudaGetSymbolAddress((void**)&Z,      g_Z);
    cudaGetSymbolAddress((void**)&M,      g_M);
    cudaGetSymbolAddress((void**)&gram,   g_gram);
    cudaGetSymbolAddress((void**)&nrm,    g_nrm);
    cudaGetSymbolAddress((void**)&h16a,   g_h16a);
    cudaGetSymbolAddress((void**)&h16b,   g_h16b);
    cudaGetSymbolAddress((void**)&z1,     g_z1);
    cudaGetSymbolAddress((void**)&z2,     g_z2);

    cudaFuncSetAttribute(aggr_smem, cudaFuncAttributeMaxDynamicSharedMemorySize, SMEM_AGG);
    size_t shmem_lin = 32*1537*sizeof(float);
    cudaFuncSetAttribute(lin_layer, cudaFuncAttributeMaxDynamicSharedMemorySize, (int)shmem_lin);

    const float invKG = 1.f/(float)KG;
    dim3 gAgg(4, 32);
    dim3 gPool(32, 4);
    dim3 gPoolY(32, 12);
    dim3 gGram(8, 4, 32);

    // ===== graph kNN =====
    knn_kernel<<<NNODE, 256>>>(x, KG, nbr100);                                   // #1

    // ===== EdgeConv 1 first (slot #4 = edge GEMM, split-TF32 tensor-core) =====
    {
        float* U = M;
        float* V = M + (size_t)NNODE*128;
        uv6_kernel<<<NNODE/2, 256>>>(x, p1_W1, U, V);                            // #2
        edge_hidden<<<NNODE, 128>>>(U, V, nbr100, KG, p1_b1, Z);                 // #3
    }
    gemm_tc<<<NEDGE/128, 256>>>(Z, 128, p1_W2, p1_b2, M, 128, 128, 1, nullptr);  // #4 (profiled)
    maxpool3<<<NNODE, 128>>>(M, Y);                                              // #5

    // ===== TAG layer 1 (F=6 -> 128), K=18 stays SIMT =====
    tag1_aggr<<<32, 512>>>(x, nbr100, t1);
    gemm_bias_lrelu<<<NNODE/128, 256>>>(t1, 18, tag1_W, tag1_b, hmA, 384, 18, 1, h16a);

    // ===== TAG layer 2 =====
    aggr_smem<<<gAgg, 1024, SMEM_AGG>>>(h16a, nbr100, hmA + 128, 384, h16b, 1, invKG);
    aggr_smem<<<gAgg, 1024, SMEM_AGG>>>(h16b, nbr100, hmA + 256, 384, nullptr, 0, invKG);
    pool_mean_max<<<gPool, 256>>>(hmA, 384, z1, 0, 128);
    gemm_tc<<<NNODE/128, 256>>>(hmA, 384, tag_W, tag_b, hmB, 384, 384, 1, h16a);
    pool_mean_max<<<gPool, 256>>>(hmB, 384, z1, 256, 384);

    // ===== TAG layer 3 =====
    aggr_smem<<<gAgg, 1024, SMEM_AGG>>>(h16a, nbr100, hmB + 128, 384, h16b, 1, invKG);
    aggr_smem<<<gAgg, 1024, SMEM_AGG>>>(h16b, nbr100, hmB + 256, 384, nullptr, 0, invKG);
    gemm_tc<<<NNODE/128, 256>>>(hmB, 384, tag_W + 3*128*128, tag_b + 128, hmA, 384, 384, 1, nullptr);
    pool_mean_max<<<gPool, 256>>>(hmA, 384, z1, 512, 640);

    // ===== EdgeConv 2 (kNN on y1, linearized) =====
    gram_kernel<<<gGram, 256>>>(Y, 384, gram, nrm);
    top3_kernel<<<NNODE, 256>>>(gram, nrm, nbr3);
    {
        float* U = Z;
        float* V = Z + (size_t)NNODE*128;
        gemm_tc<<<NNODE/128, 256>>>(Y, 384, pf_W,           nullptr, U, 128, 128, 0, nullptr);
        gemm_tc<<<NNODE/128, 256>>>(Y, 384, pf_W + 128*128, nullptr, V, 128, 128, 0, nullptr);
        edge_fused_max<<<NNODE, 128>>>(U, V, nbr3, KP, pf_b, Y + 128);
    }

    // ===== EdgeConv 3 (kNN on y2, linearized) =====
    gram_kernel<<<gGram, 256>>>(Y + 128, 384, gram, nrm);
    top3_kernel<<<NNODE, 256>>>(gram, nrm, nbr3);
    {
        float* U = Z;
        float* V = Z + (size_t)NNODE*128;
        gemm_tc<<<NNODE/128, 256>>>(Y + 128, 384, pf_W + 256*128,           nullptr, U, 128, 128, 0, nullptr);
        gemm_tc<<<NNODE/128, 256>>>(Y + 128, 384, pf_W + 256*128 + 128*128, nullptr, V, 128, 128, 0, nullptr);
        edge_fused_max<<<NNODE, 128>>>(U, V, nbr3, KP, pf_b + 128, Y + 256);
    }

    // ===== point-branch pooling (fused) =====
    pool_y<<<gPoolY, 256>>>(Y, z1);

    // ===== head: BN fused into first lin layer =====
    const float* src = z1; float* dst = z2;
    for (int g = 0; g < 5; g++) {
        lin_layer<<<96, 512, shmem_lin>>>(src, lin_W + (size_t)g*1536*1536, lin_b + g*1536,
                                          dst, bn_g, bn_b, g == 0 ? 1 : 0);
        const float* tmp = dst; dst = (float*)src; src = tmp;
    }
    out_kernel<<<32, 256>>>(z2, out_W, out_b, out);
}

// round 10
// speedup vs baseline: 2.0001x; 1.0236x over previous
#include <cuda_runtime.h>
#include <cuda_fp16.h>
#include <math.h>

#define BB 32
#define NN 512
#define NNODE (BB*NN)      // 16384
#define FF 6
#define WW 128
#define KG 100
#define KP 3
#define NEDGE (NNODE*KP)   // 49152
#define DIM2 1536

typedef unsigned long long ull;

// ---------------- scratch (device globals; no allocation) ----------------
__device__ int    g_nbr100[NNODE*KG];
__device__ int    g_nbr3[NNODE*KP];
__device__ float  g_t1[NNODE*18];
__device__ float  g_hmA[NNODE*384];
__device__ float  g_hmB[NNODE*384];
__device__ float  g_Y[NNODE*384];
__device__ float  g_Z[(size_t)NEDGE*256];
__device__ float  g_M[(size_t)NEDGE*128];
__device__ float  g_gram[(size_t)BB*NN*NN];
__device__ float  g_nrm[NNODE];
__device__ __half g_h16a[NNODE*128];
__device__ __half g_h16b[NNODE*128];
__device__ float  g_z1[BB*DIM2];
__device__ float  g_z2[BB*DIM2];

// ---------------- tf32 mma helpers ----------------
__device__ __forceinline__ unsigned cvt_tf32(float f) {
    unsigned u;
    asm("cvt.rna.tf32.f32 %0, %1;" : "=r"(u) : "f"(f));
    return u;
}
__device__ __forceinline__ void mma_tf32(float* c, const unsigned* a, const unsigned* b) {
    asm("mma.sync.aligned.m16n8k8.row.col.f32.tf32.tf32.f32 "
        "{%0,%1,%2,%3}, {%4,%5,%6,%7}, {%8,%9}, {%0,%1,%2,%3};"
        : "+f"(c[0]), "+f"(c[1]), "+f"(c[2]), "+f"(c[3])
        : "r"(a[0]), "r"(a[1]), "r"(a[2]), "r"(a[3]), "r"(b[0]), "r"(b[1]));
}

#define TCS 133
#define TCSMEM (4*32*TCS*sizeof(float))   // 68096 B dynamic smem

// ---------------- tensor-core GEMM (split-TF32, pre-split smem) ----------------
// C = act(A[M,K] @ W[K,128] + bias). BM=128, BN=128, BK=32, 256 thr (8 warps 2x4).
// hi = cvt_tf32(v), lo = v - hi stored in smem; MMA truncates lo's extra bits (err ~2^-23).
__global__ void gemm_tc(const float* __restrict__ A, int lda,
                        const float* __restrict__ W,
                        const float* __restrict__ bias,
                        float* __restrict__ C, int ldc,
                        int K, int act, __half* __restrict__ C16) {
    extern __shared__ float dsm[];
    float* Ah = dsm;
    float* Al = dsm + 32*TCS;
    float* Bh = dsm + 2*32*TCS;
    float* Bl = dsm + 3*32*TCS;
    int m0 = blockIdx.x * 128;
    int tid = threadIdx.x;
    int warp = tid >> 5, lane = tid & 31;
    int wr = warp >> 2, wc = warp & 3;      // warp tile: 64 rows x 32 cols
    int g = lane >> 2, tg = lane & 3;
    float acc[4][4][4] = {};

    for (int k0 = 0; k0 < K; k0 += 32) {
#pragma unroll
        for (int t = 0; t < 16; t++) {
            int idx = tid + 256*t;
            int m = idx >> 5, k = idx & 31;
            float v = A[(size_t)(m0 + m)*lda + k0 + k];
            float h = __uint_as_float(cvt_tf32(v));
            Ah[k*TCS + m] = h;
            Al[k*TCS + m] = v - h;
        }
#pragma unroll
        for (int t = 0; t < 16; t++) {
            int idx = tid + 256*t;
            int k = idx >> 7, n = idx & 127;
            float v = W[(size_t)(k0 + k)*128 + n];
            float h = __uint_as_float(cvt_tf32(v));
            Bh[k*TCS + n] = h;
            Bl[k*TCS + n] = v - h;
        }
        __syncthreads();
#pragma unroll
        for (int kk = 0; kk < 32; kk += 8) {
            unsigned ah[4][4], al[4][4], bh[4][2], bl[4][2];
#pragma unroll
            for (int tm = 0; tm < 4; tm++) {
                int mr = wr*64 + tm*16;
                int r0 = (kk + tg)*TCS, r1 = (kk + tg + 4)*TCS;
                ah[tm][0] = __float_as_uint(Ah[r0 + mr + g]);
                ah[tm][1] = __float_as_uint(Ah[r0 + mr + g + 8]);
                ah[tm][2] = __float_as_uint(Ah[r1 + mr + g]);
                ah[tm][3] = __float_as_uint(Ah[r1 + mr + g + 8]);
                al[tm][0] = __float_as_uint(Al[r0 + mr + g]);
                al[tm][1] = __float_as_uint(Al[r0 + mr + g + 8]);
                al[tm][2] = __float_as_uint(Al[r1 + mr + g]);
                al[tm][3] = __float_as_uint(Al[r1 + mr + g + 8]);
            }
#pragma unroll
            for (int tn = 0; tn < 4; tn++) {
                int nc = wc*32 + tn*8;
                int r0 = (kk + tg)*TCS, r1 = (kk + tg + 4)*TCS;
                bh[tn][0] = __float_as_uint(Bh[r0 + nc + g]);
                bh[tn][1] = __float_as_uint(Bh[r1 + nc + g]);
                bl[tn][0] = __float_as_uint(Bl[r0 + nc + g]);
                bl[tn][1] = __float_as_uint(Bl[r1 + nc + g]);
            }
#pragma unroll
            for (int tm = 0; tm < 4; tm++)
#pragma unroll
                for (int tn = 0; tn < 4; tn++) {
                    mma_tf32(acc[tm][tn], ah[tm], bl[tn]);  // hi*lo
                    mma_tf32(acc[tm][tn], al[tm], bh[tn]);  // lo*hi
                    mma_tf32(acc[tm][tn], ah[tm], bh[tn]);  // hi*hi
                }
        }
        __syncthreads();
    }
#pragma unroll
    for (int tm = 0; tm < 4; tm++) {
        int r = m0 + wr*64 + tm*16 + g;
#pragma unroll
        for (int tn = 0; tn < 4; tn++) {
            int c = wc*32 + tn*8 + 2*tg;
            float v0 = acc[tm][tn][0], v1 = acc[tm][tn][1];
            float v2 = acc[tm][tn][2], v3 = acc[tm][tn][3];
            if (bias) {
                float b0 = bias[c], b1 = bias[c+1];
                v0 += b0; v1 += b1; v2 += b0; v3 += b1;
            }
            if (act) {
                v0 = v0 > 0.f ? v0 : 0.01f*v0;
                v1 = v1 > 0.f ? v1 : 0.01f*v1;
                v2 = v2 > 0.f ? v2 : 0.01f*v2;
                v3 = v3 > 0.f ? v3 : 0.01f*v3;
            }
            *(float2*)&C[(size_t)r*ldc + c]     = make_float2(v0, v1);
            *(float2*)&C[(size_t)(r+8)*ldc + c] = make_float2(v2, v3);
            if (C16) {
                *(__half2*)&C16[(size_t)r*128 + c]     = __floats2half2_rn(v0, v1);
                *(__half2*)&C16[(size_t)(r+8)*128 + c] = __floats2half2_rn(v2, v3);
            }
        }
    }
}

// ---------------- tensor-core Gram (split-TF32): G = Y Y^T per graph ----------------
// 128x128 tile per block, grid (4, 4, 32), K=128. Emits nrm from diagonal.
__global__ void gram_tc(const float* __restrict__ Y, int ld,
                        float* __restrict__ G, float* __restrict__ nrm) {
    extern __shared__ float dsm[];
    float* Ah = dsm;
    float* Al = dsm + 32*TCS;
    float* Bh = dsm + 2*32*TCS;
    float* Bl = dsm + 3*32*TCS;
    int b  = blockIdx.z;
    int i0 = blockIdx.y * 128, j0 = blockIdx.x * 128;
    const float* Yb = Y + (size_t)b * 512 * ld;
    int tid = threadIdx.x;
    int warp = tid >> 5, lane = tid & 31;
    int wr = warp >> 2, wc = warp & 3;
    int g = lane >> 2, tg = lane & 3;
    float acc[4][4][4] = {};

    for (int k0 = 0; k0 < 128; k0 += 32) {
#pragma unroll
        for (int t = 0; t < 16; t++) {
            int idx = tid + 256*t;
            int m = idx >> 5, k = idx & 31;
            float v = Yb[(size_t)(i0 + m)*ld + k0 + k];
            float h = __uint_as_float(cvt_tf32(v));
            Ah[k*TCS + m] = h;
            Al[k*TCS + m] = v - h;
        }
#pragma unroll
        for (int t = 0; t < 16; t++) {
            int idx = tid + 256*t;
            int n = idx >> 5, k = idx & 31;
            float v = Yb[(size_t)(j0 + n)*ld + k0 + k];
            float h = __uint_as_float(cvt_tf32(v));
            Bh[k*TCS + n] = h;
            Bl[k*TCS + n] = v - h;
        }
        __syncthreads();
#pragma unroll
        for (int kk = 0; kk < 32; kk += 8) {
            unsigned ah[4][4], al[4][4], bh[4][2], bl[4][2];
#pragma unroll
            for (int tm = 0; tm < 4; tm++) {
                int mr = wr*64 + tm*16;
                int r0 = (kk + tg)*TCS, r1 = (kk + tg + 4)*TCS;
                ah[tm][0] = __float_as_uint(Ah[r0 + mr + g]);
                ah[tm][1] = __float_as_uint(Ah[r0 + mr + g + 8]);
                ah[tm][2] = __float_as_uint(Ah[r1 + mr + g]);
                ah[tm][3] = __float_as_uint(Ah[r1 + mr + g + 8]);
                al[tm][0] = __float_as_uint(Al[r0 + mr + g]);
                al[tm][1] = __float_as_uint(Al[r0 + mr + g + 8]);
                al[tm][2] = __float_as_uint(Al[r1 + mr + g]);
                al[tm][3] = __float_as_uint(Al[r1 + mr + g + 8]);
            }
#pragma unroll
            for (int tn = 0; tn < 4; tn++) {
                int nc = wc*32 + tn*8;
                int r0 = (kk + tg)*TCS, r1 = (kk + tg + 4)*TCS;
                bh[tn][0] = __float_as_uint(Bh[r0 + nc + g]);
                bh[tn][1] = __float_as_uint(Bh[r1 + nc + g]);
                bl[tn][0] = __float_as_uint(Bl[r0 + nc + g]);
                bl[tn][1] = __float_as_uint(Bl[r1 + nc + g]);
            }
#pragma unroll
            for (int tm = 0; tm < 4; tm++)
#pragma unroll
                for (int tn = 0; tn < 4; tn++) {
                    mma_tf32(acc[tm][tn], ah[tm], bl[tn]);
                    mma_tf32(acc[tm][tn], al[tm], bh[tn]);
                    mma_tf32(acc[tm][tn], ah[tm], bh[tn]);
                }
        }
        __syncthreads();
    }
    float* Gb = G + (size_t)b*512*512;
#pragma unroll
    for (int tm = 0; tm < 4; tm++) {
        int r = i0 + wr*64 + tm*16 + g;
#pragma unroll
        for (int tn = 0; tn < 4; tn++) {
            int c = j0 + wc*32 + tn*8 + 2*tg;
            float v0 = acc[tm][tn][0], v1 = acc[tm][tn][1];
            float v2 = acc[tm][tn][2], v3 = acc[tm][tn][3];
            *(float2*)&Gb[(size_t)r*512 + c]     = make_float2(v0, v1);
            *(float2*)&Gb[(size_t)(r+8)*512 + c] = make_float2(v2, v3);
            int br = b*512;
            if (r == c)         nrm[br + r]     = v0;
            if (r == c + 1)     nrm[br + r]     = v1;
            if (r + 8 == c)     nrm[br + r + 8] = v2;
            if (r + 8 == c + 1) nrm[br + r + 8] = v3;
        }
    }
}

// ---------------- kNN (k=100): packed 64-bit-key bitonic sort of 512 ----------------
__global__ void knn_kernel(const float* __restrict__ x, int K, int* __restrict__ out) {
    __shared__ ull key[512];
    int node = blockIdx.x;
    int b = node >> 9;
    int i = node & 511;
    int tid = threadIdx.x;  // 256

    float xi[FF];
    const float* xr = x + (size_t)node * FF;
    float sqi = 0.f;
#pragma unroll
    for (int d = 0; d < FF; d++) { xi[d] = xr[d]; sqi += xi[d]*xi[d]; }
    for (int j = tid; j < 512; j += 256) {
        const float* xj = x + (size_t)(b*512 + j) * FF;
        float dot = 0.f, sqj = 0.f;
#pragma unroll
        for (int d = 0; d < FF; d++) { float v = xj[d]; dot += xi[d]*v; sqj += v*v; }
        float dd = sqi + sqj - 2.f*dot;
        if (j == i) dd = 1e10f;
        unsigned int bits = __float_as_uint(dd);
        bits = (bits & 0x80000000u) ? ~bits : (bits | 0x80000000u);
        key[j] = ((ull)bits << 32) | (unsigned)j;
    }
    __syncthreads();

    for (int size = 2; size < 512; size <<= 1) {
        int up = ((tid & (size >> 1)) == 0);
        for (int stride = size >> 1; stride > 0; stride >>= 1) {
            int pos = 2*tid - (tid & (stride - 1));
            ull a = key[pos], c = key[pos + stride];
            ull lo = a < c ? a : c;
            ull hi = a < c ? c : a;
            key[pos]          = up ? lo : hi;
            key[pos + stride] = up ? hi : lo;
            __syncthreads();
        }
    }
    for (int stride = 256; stride > 0; stride >>= 1) {
        int pos = 2*tid - (tid & (stride - 1));
        ull a = key[pos], c = key[pos + stride];
        key[pos]          = a < c ? a : c;
        key[pos + stride] = a < c ? c : a;
        __syncthreads();
    }
    for (int t = tid; t < K; t += 256)
        out[(size_t)node*K + t] = b*512 + (int)(key[t] & 0xffffffffu);
}

// ---------------- top-3 from gram: shfl-based 3-round argmin ----------------
__global__ void top3_kernel(const float* __restrict__ gram, const float* __restrict__ nrm,
                            int* __restrict__ out3) {
    __shared__ ull keys[512];
    __shared__ ull wmin[8];
    int node = blockIdx.x;
    int b = node >> 9, i = node & 511;
    int tid = threadIdx.x;  // 256
    int warp = tid >> 5, lane = tid & 31;
    const float* g = gram + (size_t)b*512*512 + (size_t)i*512;
    const float* nb = nrm + b*512;
    float ni = nb[i];
#pragma unroll
    for (int t = 0; t < 2; t++) {
        int j = tid + 256*t;
        float d = ni + nb[j] - 2.f*g[j];
        if (j == i) d = 1e10f;
        unsigned int bits = __float_as_uint(d);
        bits = (bits & 0x80000000u) ? ~bits : (bits | 0x80000000u);
        keys[j] = ((ull)bits << 32) | (unsigned)j;
    }
    __syncthreads();
#pragma unroll
    for (int r = 0; r < 3; r++) {
        ull m = min(keys[tid], keys[tid+256]);
#pragma unroll
        for (int o = 16; o > 0; o >>= 1)
            m = min(m, __shfl_down_sync(0xffffffffu, m, o));
        if (lane == 0) wmin[warp] = m;
        __syncthreads();
        if (tid == 0) {
            ull best = wmin[0];
#pragma unroll
            for (int w = 1; w < 8; w++) best = min(best, wmin[w]);
            int j = (int)(best & 0xffffffffu);
            out3[node*3 + r] = b*512 + j;
            keys[j] = 0xFFFFFFFFFFFFFFFFull;
        }
        __syncthreads();
    }
}

// ---------------- TAG1: fused per-graph 2-hop mean (dim 6), warp-per-node ----------------
__global__ void tag1_aggr(const float* __restrict__ x, const int* __restrict__ nbr,
                          float* __restrict__ t1) {
    __shared__ float xs[6][512];
    __shared__ float m1[6][512];
    __shared__ float m2[6][512];
    int b = blockIdx.x;
    int tid = threadIdx.x;  // 512
    int warp = tid >> 5, lane = tid & 31;
    const float* xr = x + (size_t)(b*512 + tid)*6;
#pragma unroll
    for (int d = 0; d < 6; d++) xs[d][tid] = xr[d];
    __syncthreads();

    for (int nl = 0; nl < 32; nl++) {
        int node = warp*32 + nl;
        const int* nbp = nbr + (size_t)(b*512 + node)*KG;
        float a0=0,a1=0,a2=0,a3=0,a4=0,a5=0;
        for (int k = lane; k < KG; k += 32) {
            int j = nbp[k] & 511;
            a0 += xs[0][j]; a1 += xs[1][j]; a2 += xs[2][j];
            a3 += xs[3][j]; a4 += xs[4][j]; a5 += xs[5][j];
        }
#pragma unroll
        for (int o = 16; o > 0; o >>= 1) {
            a0 += __shfl_down_sync(0xffffffffu, a0, o);
            a1 += __shfl_down_sync(0xffffffffu, a1, o);
            a2 += __shfl_down_sync(0xffffffffu, a2, o);
            a3 += __shfl_down_sync(0xffffffffu, a3, o);
            a4 += __shfl_down_sync(0xffffffffu, a4, o);
            a5 += __shfl_down_sync(0xffffffffu, a5, o);
        }
        if (lane == 0) {
            m1[0][node] = a0*0.01f; m1[1][node] = a1*0.01f; m1[2][node] = a2*0.01f;
            m1[3][node] = a3*0.01f; m1[4][node] = a4*0.01f; m1[5][node] = a5*0.01f;
        }
    }
    __syncthreads();
    for (int nl = 0; nl < 32; nl++) {
        int node = warp*32 + nl;
        const int* nbp = nbr + (size_t)(b*512 + node)*KG;
        float a0=0,a1=0,a2=0,a3=0,a4=0,a5=0;
        for (int k = lane; k < KG; k += 32) {
            int j = nbp[k] & 511;
            a0 += m1[0][j]; a1 += m1[1][j]; a2 += m1[2][j];
            a3 += m1[3][j]; a4 += m1[4][j]; a5 += m1[5][j];
        }
#pragma unroll
        for (int o = 16; o > 0; o >>= 1) {
            a0 += __shfl_down_sync(0xffffffffu, a0, o);
            a1 += __shfl_down_sync(0xffffffffu, a1, o);
            a2 += __shfl_down_sync(0xffffffffu, a2, o);
            a3 += __shfl_down_sync(0xffffffffu, a3, o);
            a4 += __shfl_down_sync(0xffffffffu, a4, o);
            a5 += __shfl_down_sync(0xffffffffu, a5, o);
        }
        if (lane == 0) {
            m2[0][node] = a0*0.01f; m2[1][node] = a1*0.01f; m2[2][node] = a2*0.01f;
            m2[3][node] = a3*0.01f; m2[4][node] = a4*0.01f; m2[5][node] = a5*0.01f;
        }
    }
    __syncthreads();
    float* tr = t1 + (size_t)(b*512 + tid)*18;
#pragma unroll
    for (int d = 0; d < 6; d++) {
        tr[d]      = xs[d][tid];
        tr[6 + d]  = m1[d][tid];
        tr[12 + d] = m2[d][tid];
    }
}

// ---------------- smem-staged fp16 aggregation (dim 128) ----------------
#define SMEM_AGG (512*128*2 + 32*100*4)
__global__ void aggr_smem(const __half* __restrict__ src16,
                          const int* __restrict__ nbr,
                          float* __restrict__ dst, int ldd,
                          __half* __restrict__ dst2, int wantHalf,
                          float scale) {
    extern __shared__ char sm[];
    __half* tile  = (__half*)sm;
    int*    idxbf = (int*)(sm + 512*128*2);
    int bg = blockIdx.y, part = blockIdx.x;
    int tid = threadIdx.x;                        // 1024
    const uint4* gsrc = (const uint4*)(src16 + (size_t)bg*512*128);
    uint4* stile = (uint4*)tile;
#pragma unroll
    for (int t = 0; t < 8; t++) stile[tid + 1024*t] = gsrc[tid + 1024*t];
    __syncthreads();

    int warp = tid >> 5, lane = tid & 31;
    int* myidx = idxbf + warp*100;
    const uint2* rowbase = (const uint2*)tile + lane;
#pragma unroll
    for (int nl = 0; nl < 4; nl++) {
        int nodeLocal = part*128 + warp*4 + nl;
        int node = bg*512 + nodeLocal;
        const int* nb = nbr + (size_t)node*KG;
        myidx[lane]      = nb[lane]      & 511;
        myidx[lane + 32] = nb[lane + 32] & 511;
        myidx[lane + 64] = nb[lane + 64] & 511;
        if (lane < 4) myidx[lane + 96] = nb[lane + 96] & 511;
        __syncwarp();
        float4 acc = {0.f, 0.f, 0.f, 0.f};
#pragma unroll 4
        for (int k = 0; k < KG; k++) {
            int j = myidx[k];
            uint2 u = rowbase[j*32];
            float2 f0 = __half22float2(*reinterpret_cast<__half2*>(&u.x));
            float2 f1 = __half22float2(*reinterpret_cast<__half2*>(&u.y));
            acc.x += f0.x; acc.y += f0.y; acc.z += f1.x; acc.w += f1.y;
        }
        __syncwarp();
        acc.x *= scale; acc.y *= scale; acc.z *= scale; acc.w *= scale;
        *(float4*)(dst + (size_t)node*ldd + lane*4) = acc;
        if (wantHalf) {
            __half2* o = (__half2*)(dst2 + (size_t)node*128 + lane*4);
            o[0] = __floats2half2_rn(acc.x, acc.y);
            o[1] = __floats2half2_rn(acc.z, acc.w);
        }
    }
}

// ---------------- SIMT GEMM (only for K=18 t1 layer) ----------------
__global__ void gemm_bias_lrelu(const float* __restrict__ A, int lda,
                                const float* __restrict__ W,
                                const float* __restrict__ bias,
                                float* __restrict__ C, int ldc,
                                int K, int act, __half* __restrict__ C16) {
    __shared__ float As[16][136];
    __shared__ float Ws[16][128];
    int m0 = blockIdx.x * 128;
    int tid = threadIdx.x;
    int tr = tid >> 4, tc = tid & 15;
    float acc[8][8] = {};

    for (int k0 = 0; k0 < K; k0 += 16) {
#pragma unroll
        for (int i = 0; i < 8; i++) {
            int idx = tid + 256*i;
            int r = idx >> 4, c = idx & 15;
            float v = 0.f;
            if (k0 + c < K) v = A[(size_t)(m0 + r)*lda + k0 + c];
            As[c][r] = v;
        }
#pragma unroll
        for (int i = 0; i < 8; i++) {
            int idx = tid + 256*i;
            int kk = idx >> 7, n = idx & 127;
            float v = 0.f;
            if (k0 + kk < K) v = W[(size_t)(k0+kk)*128 + n];
            Ws[kk][n] = v;
        }
        __syncthreads();
#pragma unroll
        for (int k = 0; k < 16; k++) {
            float a[8], bv[8];
            *(float4*)&a[0]  = *(const float4*)&As[k][tr*8];
            *(float4*)&a[4]  = *(const float4*)&As[k][tr*8+4];
            *(float4*)&bv[0] = *(const float4*)&Ws[k][tc*8];
            *(float4*)&bv[4] = *(const float4*)&Ws[k][tc*8+4];
#pragma unroll
            for (int u = 0; u < 8; u++)
#pragma unroll
                for (int v = 0; v < 8; v++)
                    acc[u][v] = fmaf(a[u], bv[v], acc[u][v]);
        }
        __syncthreads();
    }
#pragma unroll
    for (int u = 0; u < 8; u++) {
        int r = m0 + tr*8 + u;
#pragma unroll
        for (int v = 0; v < 8; v++) {
            int c = tc*8 + v;
            float val = acc[u][v];
            if (bias) val += bias[c];
            if (act) val = val > 0.f ? val : 0.01f*val;
            C[(size_t)r*ldc + c] = val;
            if (C16) C16[(size_t)r*128 + c] = __float2half_rn(val);
        }
    }
}

// ---------------- EdgeConv1: U/V from x (K=6 each) ----------------
__global__ void uv6_kernel(const float* __restrict__ x, const float* __restrict__ W12,
                           float* __restrict__ U, float* __restrict__ V) {
    __shared__ float Ws[12][128];
    int tid = threadIdx.x;   // 256
    for (int t = tid; t < 12*128; t += 256) Ws[t >> 7][t & 127] = W12[t];
    __syncthreads();
    int node = blockIdx.x*2 + (tid >> 7);
    int c = tid & 127;
    const float* xr = x + (size_t)node*6;
    float au = 0.f, av = 0.f;
#pragma unroll
    for (int d = 0; d < 6; d++) {
        float xv = xr[d];
        au = fmaf(xv, Ws[d][c], au);
        av = fmaf(xv, Ws[6+d][c], av);
    }
    U[(size_t)node*128 + c] = au;
    V[(size_t)node*128 + c] = av;
}

// h_e = lrelu(U[i] + V[j] - V[i] + b), 3 edges per node
__global__ void edge_hidden(const float* __restrict__ U, const float* __restrict__ V,
                            const int* __restrict__ nbr, int nstride,
                            const float* __restrict__ b, float* __restrict__ H) {
    int n = blockIdx.x; int c = threadIdx.x;   // 128
    float base = U[(size_t)n*128 + c] - V[(size_t)n*128 + c] + b[c];
#pragma unroll
    for (int k = 0; k < 3; k++) {
        int j = nbr[(size_t)n*nstride + k];
        float h = base + V[(size_t)j*128 + c];
        H[(size_t)(n*3 + k)*128 + c] = h > 0.f ? h : 0.01f*h;
    }
}

// Y_out[n] = max_k lrelu(U[n] + V[j_k] - V[n] + b)
__global__ void edge_fused_max(const float* __restrict__ U, const float* __restrict__ V,
                               const int* __restrict__ nbr, int nstride,
                               const float* __restrict__ b, float* __restrict__ Yout) {
    int n = blockIdx.x; int c = threadIdx.x;   // 128
    float base = U[(size_t)n*128 + c] - V[(size_t)n*128 + c] + b[c];
    float m = -1e30f;
#pragma unroll
    for (int k = 0; k < 3; k++) {
        int j = nbr[(size_t)n*nstride + k];
        float h = base + V[(size_t)j*128 + c];
        h = h > 0.f ? h : 0.01f*h;
        m = fmaxf(m, h);
    }
    Yout[(size_t)n*384 + c] = m;
}

__global__ void maxpool3(const float* __restrict__ M, float* __restrict__ Yc) {
    int n = blockIdx.x; int c = threadIdx.x;   // 128
    float v0 = M[(size_t)(n*3+0)*128 + c];
    float v1 = M[(size_t)(n*3+1)*128 + c];
    float v2 = M[(size_t)(n*3+2)*128 + c];
    Yc[(size_t)n*384 + c] = fmaxf(v0, fmaxf(v1, v2));
}

// ---------------- graph pooling ----------------
__global__ void pool_mean_max(const float* __restrict__ src, int ld,
                              float* __restrict__ z, int offm, int offx) {
    __shared__ float ss[8][32];
    __shared__ float sx[8][32];
    int b = blockIdx.x;
    int lane = threadIdx.x & 31;
    int s = threadIdx.x >> 5;
    int c = blockIdx.y*32 + lane;
    const float* p = src + (size_t)b*512*ld + c + (size_t)(s*64)*ld;
    float s0 = 0.f, s1 = 0.f, s2 = 0.f, s3 = 0.f;
    float x0 = -1e30f, x1 = -1e30f, x2 = -1e30f, x3 = -1e30f;
#pragma unroll
    for (int n = 0; n < 64; n += 4) {
        float v0 = p[(size_t)(n+0)*ld];
        float v1 = p[(size_t)(n+1)*ld];
        float v2 = p[(size_t)(n+2)*ld];
        float v3 = p[(size_t)(n+3)*ld];
        s0 += v0; s1 += v1; s2 += v2; s3 += v3;
        x0 = fmaxf(x0, v0); x1 = fmaxf(x1, v1);
        x2 = fmaxf(x2, v2); x3 = fmaxf(x3, v3);
    }
    float sum = (s0 + s1) + (s2 + s3);
    float mx = fmaxf(fmaxf(x0, x1), fmaxf(x2, x3));
    ss[s][lane] = sum; sx[s][lane] = mx;
    __syncthreads();
    if (s == 0) {
#pragma unroll
        for (int t = 1; t < 8; t++) {
            sum += ss[t][lane];
            mx = fmaxf(mx, sx[t][lane]);
        }
        z[b*DIM2 + offm + c] = sum * (1.f/512.f);
        z[b*DIM2 + offx + c] = mx;
    }
}

__global__ void pool_y(const float* __restrict__ Y, float* __restrict__ z) {
    __shared__ float ss[8][32];
    __shared__ float sx[8][32];
    int b = blockIdx.x;
    int lane = threadIdx.x & 31;
    int s = threadIdx.x >> 5;
    int c = blockIdx.y*32 + lane;
    const float* p = Y + (size_t)b*512*384 + c + (size_t)(s*64)*384;
    float s0 = 0.f, s1 = 0.f, s2 = 0.f, s3 = 0.f;
    float x0 = -1e30f, x1 = -1e30f, x2 = -1e30f, x3 = -1e30f;
#pragma unroll
    for (int n = 0; n < 64; n += 4) {
        float v0 = p[(size_t)(n+0)*384];
        float v1 = p[(size_t)(n+1)*384];
        float v2 = p[(size_t)(n+2)*384];
        float v3 = p[(size_t)(n+3)*384];
        s0 += v0; s1 += v1; s2 += v2; s3 += v3;
        x0 = fmaxf(x0, v0); x1 = fmaxf(x1, v1);
        x2 = fmaxf(x2, v2); x3 = fmaxf(x3, v3);
    }
    float sum = (s0 + s1) + (s2 + s3);
    float mx = fmaxf(fmaxf(x0, x1), fmaxf(x2, x3));
    ss[s][lane] = sum; sx[s][lane] = mx;
    __syncthreads();
    if (s == 0) {
#pragma unroll
        for (int t = 1; t < 8; t++) {
            sum += ss[t][lane];
            mx = fmaxf(mx, sx[t][lane]);
        }
        z[b*DIM2 + 768 + c]  = sum * (1.f/512.f);
        z[b*DIM2 + 1152 + c] = mx;
    }
}

// ---------------- head: lin layer with optional fused BatchNorm ----------------
__global__ void lin_layer(const float* __restrict__ A, const float* __restrict__ W,
                          const float* __restrict__ bias, float* __restrict__ C,
                          const float* __restrict__ gamma, const float* __restrict__ beta,
                          int doBN) {
    extern __shared__ float As[];               // 32 x 1537
    int tid = threadIdx.x;                       // 512
    for (int idx = tid; idx < 32*1536; idx += 512) {
        int r = idx / 1536; int k = idx - r*1536;
        As[r*1537 + k] = A[idx];
    }
    __syncthreads();
    if (doBN) {
        for (int ch = tid; ch < 1536; ch += 512) {
            float sm = 0.f;
#pragma unroll 8
            for (int r = 0; r < 32; r++) sm += As[r*1537 + ch];
            float mu = sm * (1.f/32.f);
            float vr = 0.f;
#pragma unroll 8
            for (int r = 0; r < 32; r++) { float d = As[r*1537 + ch] - mu; vr += d*d; }
            float inv = rsqrtf(vr*(1.f/32.f) + 1e-5f) * gamma[ch];
            float be = beta[ch];
#pragma unroll 8
            for (int r = 0; r < 32; r++)
                As[r*1537 + ch] = (As[r*1537 + ch] - mu)*inv + be;
        }
        __syncthreads();
    }
    int c = blockIdx.x*16 + (tid & 15);
    int r = tid >> 4;
    const float* As_r = As + r*1537;
    float a0 = 0.f, a1 = 0.f, a2 = 0.f, a3 = 0.f;
#pragma unroll 8
    for (int k = 0; k < 1536; k += 4) {
        a0 = fmaf(As_r[k+0], W[(size_t)(k+0)*1536 + c], a0);
        a1 = fmaf(As_r[k+1], W[(size_t)(k+1)*1536 + c], a1);
        a2 = fmaf(As_r[k+2], W[(size_t)(k+2)*1536 + c], a2);
        a3 = fmaf(As_r[k+3], W[(size_t)(k+3)*1536 + c], a3);
    }
    float v = (a0 + a1) + (a2 + a3) + bias[c];
    v = v > 0.f ? v : 0.01f*v;
    C[r*DIM2 + c] = v;
}

__global__ void out_kernel(const float* __restrict__ z, const float* __restrict__ W,
                           const float* __restrict__ b, float* __restrict__ out) {
    __shared__ float red[256];
    int row = blockIdx.x; int tid = threadIdx.x;
    float s = 0.f;
    for (int k = tid; k < DIM2; k += 256) s += z[row*DIM2 + k] * W[k];
    red[tid] = s; __syncthreads();
    for (int o = 128; o > 0; o >>= 1) { if (tid < o) red[tid] += red[tid+o]; __syncthreads(); }
    if (tid == 0) out[row] = red[0] + b[0];
}

// ---------------- host orchestration ----------------
extern "C" void kernel_launch(void* const* d_in, const int* in_sizes, int n_in,
                              void* d_out, int out_size) {
    const float* x       = (const float*)d_in[0];
    const float* tag1_W  = (const float*)d_in[2];
    const float* tag1_b  = (const float*)d_in[3];
    const float* tag_W   = (const float*)d_in[4];
    const float* tag_b   = (const float*)d_in[5];
    const float* p1_W1   = (const float*)d_in[6];
    const float* p1_b1   = (const float*)d_in[7];
    const float* p1_W2   = (const float*)d_in[8];
    const float* p1_b2   = (const float*)d_in[9];
    const float* pf_W    = (const float*)d_in[10];
    const float* pf_b    = (const float*)d_in[11];
    const float* bn_g    = (const float*)d_in[12];
    const float* bn_b    = (const float*)d_in[13];
    const float* lin_W   = (const float*)d_in[14];
    const float* lin_b   = (const float*)d_in[15];
    const float* out_W   = (const float*)d_in[16];
    const float* out_b   = (const float*)d_in[17];
    float* out = (float*)d_out;

    int *nbr100, *nbr3;
    float *t1, *hmA, *hmB, *Y, *Z, *M, *gram, *nrm, *z1, *z2;
    __half *h16a, *h16b;
    cudaGetSymbolAddress((void**)&nbr100, g_nbr100);
    cudaGetSymbolAddress((void**)&nbr3,   g_nbr3);
    cudaGetSymbolAddress((void**)&t1,     g_t1);
    cudaGetSymbolAddress((void**)&hmA,    g_hmA);
    cudaGetSymbolAddress((void**)&hmB,    g_hmB);
    cudaGetSymbolAddress((void**)&Y,      g_Y);
    cudaGetSymbolAddress((void**)&Z,      g_Z);
    cudaGetSymbolAddress((void**)&M,      g_M);
    cudaGetSymbolAddress((void**)&gram,   g_gram);
    cudaGetSymbolAddress((void**)&nrm,    g_nrm);
    cudaGetSymbolAddress((void**)&h16a,   g_h16a);
    cudaGetSymbolAddress((void**)&h16b,   g_h16b);
    cudaGetSymbolAddress((void**)&z1,     g_z1);
    cudaGetSymbolAddress((void**)&z2,     g_z2);

    cudaFuncSetAttribute(aggr_smem, cudaFuncAttributeMaxDynamicSharedMemorySize, SMEM_AGG);
    cudaFuncSetAttribute(gemm_tc, cudaFuncAttributeMaxDynamicSharedMemorySize, (int)TCSMEM);
    cudaFuncSetAttribute(gram_tc, cudaFuncAttributeMaxDynamicSharedMemorySize, (int)TCSMEM);
    size_t shmem_lin = 32*1537*sizeof(float);
    cudaFuncSetAttribute(lin_layer, cudaFuncAttributeMaxDynamicSharedMemorySize, (int)shmem_lin);

    const float invKG = 1.f/(float)KG;
    dim3 gAgg(4, 32);
    dim3 gPool(32, 4);
    dim3 gPoolY(32, 12);
    dim3 gGram(4, 4, 32);

    // ===== graph kNN =====
    knn_kernel<<<NNODE, 256>>>(x, KG, nbr100);                                   // #1

    // ===== EdgeConv 1 first (slot #4 = edge GEMM, pre-split TF32x3) =====
    {
        float* U = M;
        float* V = M + (size_t)NNODE*128;
        uv6_kernel<<<NNODE/2, 256>>>(x, p1_W1, U, V);                            // #2
        edge_hidden<<<NNODE, 128>>>(U, V, nbr100, KG, p1_b1, Z);                 // #3
    }
    gemm_tc<<<NEDGE/128, 256, TCSMEM>>>(Z, 128, p1_W2, p1_b2, M, 128, 128, 1, nullptr); // #4 (profiled)
    maxpool3<<<NNODE, 128>>>(M, Y);                                              // #5

    // ===== TAG layer 1 (F=6 -> 128), K=18 stays SIMT =====
    tag1_aggr<<<32, 512>>>(x, nbr100, t1);
    gemm_bias_lrelu<<<NNODE/128, 256>>>(t1, 18, tag1_W, tag1_b, hmA, 384, 18, 1, h16a);

    // ===== TAG layer 2 =====
    aggr_smem<<<gAgg, 1024, SMEM_AGG>>>(h16a, nbr100, hmA + 128, 384, h16b, 1, invKG);
    aggr_smem<<<gAgg, 1024, SMEM_AGG>>>(h16b, nbr100, hmA + 256, 384, nullptr, 0, invKG);
    pool_mean_max<<<gPool, 256>>>(hmA, 384, z1, 0, 128);
    gemm_tc<<<NNODE/128, 256, TCSMEM>>>(hmA, 384, tag_W, tag_b, hmB, 384, 384, 1, h16a);
    pool_mean_max<<<gPool, 256>>>(hmB, 384, z1, 256, 384);

    // ===== TAG layer 3 =====
    aggr_smem<<<gAgg, 1024, SMEM_AGG>>>(h16a, nbr100, hmB + 128, 384, h16b, 1, invKG);
    aggr_smem<<<gAgg, 1024, SMEM_AGG>>>(h16b, nbr100, hmB + 256, 384, nullptr, 0, invKG);
    gemm_tc<<<NNODE/128, 256, TCSMEM>>>(hmB, 384, tag_W + 3*128*128, tag_b + 128, hmA, 384, 384, 1, nullptr);
    pool_mean_max<<<gPool, 256>>>(hmA, 384, z1, 512, 640);

    // ===== EdgeConv 2 (kNN on y1, linearized) =====
    gram_tc<<<gGram, 256, TCSMEM>>>(Y, 384, gram, nrm);
    top3_kernel<<<NNODE, 256>>>(gram, nrm, nbr3);
    {
        float* U = Z;
        float* V = Z + (size_t)NNODE*128;
        gemm_tc<<<NNODE/128, 256, TCSMEM>>>(Y, 384, pf_W,           nullptr, U, 128, 128, 0, nullptr);
        gemm_tc<<<NNODE/128, 256, TCSMEM>>>(Y, 384, pf_W + 128*128, nullptr, V, 128, 128, 0, nullptr);
        edge_fused_max<<<NNODE, 128>>>(U, V, nbr3, KP, pf_b, Y + 128);
    }

    // ===== EdgeConv 3 (kNN on y2, linearized) =====
    gram_tc<<<gGram, 256, TCSMEM>>>(Y + 128, 384, gram, nrm);
    top3_kernel<<<NNODE, 256>>>(gram, nrm, nbr3);
    {
        float* U = Z;
        float* V = Z + (size_t)NNODE*128;
        gemm_tc<<<NNODE/128, 256, TCSMEM>>>(Y + 128, 384, pf_W + 256*128,           nullptr, U, 128, 128, 0, nullptr);
        gemm_tc<<<NNODE/128, 256, TCSMEM>>>(Y + 128, 384, pf_W + 256*128 + 128*128, nullptr, V, 128, 128, 0, nullptr);
        edge_fused_max<<<NNODE, 128>>>(U, V, nbr3, KP, pf_b + 128, Y + 256);
    }

    // ===== point-branch pooling (fused) =====
    pool_y<<<gPoolY, 256>>>(Y, z1);

    // ===== head: BN fused into first lin layer =====
    const float* src = z1; float* dst = z2;
    for (int g = 0; g < 5; g++) {
        lin_layer<<<96, 512, shmem_lin>>>(src, lin_W + (size_t)g*1536*1536, lin_b + g*1536,
                                          dst, bn_g, bn_b, g == 0 ? 1 : 0);
        const float* tmp = dst; dst = (float*)src; src = tmp;
    }
    out_kernel<<<32, 256>>>(z2, out_W, out_b, out);
}